// round 8
// baseline (speedup 1.0000x reference)
#include <cuda_runtime.h>
#include <math.h>
#include <stdint.h>

typedef unsigned long long ull;

#define NB   64
#define TT   1024
#define INW  64
#define H1   512
#define H2   256

#define SW1  580   // lstm1 weight row stride (floats)
#define SA1  588   // lstm1 act row stride  (floats)  -> conflict-free act LDS
#define SW2  772   // lstm2 weight row stride
#define SA2  772   // lstm2 act row stride

// ---------------- scratch (static device globals; no allocation) ----------------
__device__ float g_out1[(size_t)NB * TT * H1];   // h1 sequence
__device__ float g_out2[(size_t)NB * TT * H2];   // h2 sequence
__device__ float g_ctx [(size_t)NB * TT * H2];   // attention contexts
__device__ float g_fc1T[512 * 128];
__device__ float g_fc2T[128 * 51];
__device__ unsigned g_bar1;
__device__ unsigned g_bar2;

__global__ void reset_kernel() { g_bar1 = 0u; g_bar2 = 0u; }

__global__ void prep_kernel(const float* __restrict__ fc1w, const float* __restrict__ fc2w) {
    int i = blockIdx.x * blockDim.x + threadIdx.x;
    if (i < 128 * 512) { int j = i / 512, k = i % 512; g_fc1T[k * 128 + j] = fc1w[i]; }
    if (i < 51 * 128)  { int j = i / 128, k = i % 128; g_fc2T[k * 51 + j] = fc2w[i]; }
}

// ---------------- helpers ----------------
__device__ __forceinline__ float sigf(float x) { return 1.f / (1.f + __expf(-x)); }

__device__ __forceinline__ uint32_t s2u(const void* p) {
    uint32_t a;
    asm("{ .reg .u64 t; cvta.to.shared.u64 t, %1; cvt.u32.u64 %0, t; }" : "=r"(a) : "l"(p));
    return a;
}
__device__ __forceinline__ void cp16(uint32_t dst, const void* src) {
    asm volatile("cp.async.cg.shared.global [%0], [%1], 16;" :: "r"(dst), "l"(src));
}
__device__ __forceinline__ void cpcommit() {
    asm volatile("cp.async.commit_group;" ::: "memory");
}
__device__ __forceinline__ void cpwait(int n) {
    switch (n) {
        case 0:  asm volatile("cp.async.wait_group 0;"  ::: "memory"); break;
        case 1:  asm volatile("cp.async.wait_group 1;"  ::: "memory"); break;
        case 2:  asm volatile("cp.async.wait_group 2;"  ::: "memory"); break;
        case 3:  asm volatile("cp.async.wait_group 3;"  ::: "memory"); break;
        case 4:  asm volatile("cp.async.wait_group 4;"  ::: "memory"); break;
        case 5:  asm volatile("cp.async.wait_group 5;"  ::: "memory"); break;
        case 6:  asm volatile("cp.async.wait_group 6;"  ::: "memory"); break;
        case 7:  asm volatile("cp.async.wait_group 7;"  ::: "memory"); break;
        case 8:  asm volatile("cp.async.wait_group 8;"  ::: "memory"); break;
        case 9:  asm volatile("cp.async.wait_group 9;"  ::: "memory"); break;
        case 10: asm volatile("cp.async.wait_group 10;" ::: "memory"); break;
        default: asm volatile("cp.async.wait_group 11;" ::: "memory"); break;
    }
}
__device__ __forceinline__ ull fma2(ull a, ull b, ull c) {
    ull d;
    asm("fma.rn.f32x2 %0, %1, %2, %3;" : "=l"(d) : "l"(a), "l"(b), "l"(c));
    return d;
}
__device__ __forceinline__ float psum(ull a) {
    return __int_as_float((int)(a & 0xffffffffULL)) + __int_as_float((int)(a >> 32));
}

// ============================ LSTM layer 1 ============================
// 128 CTAs x 256 thr, 1/SM. CTA owns 4 hidden cols (16 gate rows), K=576.
// thread tile: 2 gate rows (gI=tid&7) x 2 batch rows (rp=tid>>3).
__device__ __forceinline__ void load1(int c, int t, const float* __restrict__ x, uint32_t aB) {
    const int tid = threadIdx.x;
#pragma unroll
    for (int j = 0; j < 4; ++j) {
        int o = j * 256 + tid;
        int row = o >> 4, f4 = o & 15;
        const float* src = (c == 0)
            ? x + ((size_t)row * TT + t) * INW + f4 * 4
            : g_out1 + ((size_t)row * TT + (t - 1)) * H1 + (c - 1) * 64 + f4 * 4;
        cp16(aB + (uint32_t)((row * SA1 + c * 64 + f4 * 4) * 4), src);
    }
}

__device__ __forceinline__ void chunk1(const float* sW, const float* sA, int gI, int rp, int c,
                                       ull& a00, ull& a01, ull& a10, ull& a11) {
    const ulonglong2* w0 = (const ulonglong2*)(sW + (2 * gI) * SW1 + c * 64);
    const ulonglong2* w1 = (const ulonglong2*)(sW + (2 * gI + 1) * SW1 + c * 64);
    const ulonglong2* p0 = (const ulonglong2*)(sA + (2 * rp) * SA1 + c * 64);
    const ulonglong2* p1 = (const ulonglong2*)(sA + (2 * rp + 1) * SA1 + c * 64);
#pragma unroll
    for (int i = 0; i < 16; ++i) {
        ulonglong2 W0 = w0[i], W1 = w1[i], A0 = p0[i], A1 = p1[i];
        a00 = fma2(W0.x, A0.x, a00); a01 = fma2(W0.x, A1.x, a01);
        a10 = fma2(W1.x, A0.x, a10); a11 = fma2(W1.x, A1.x, a11);
        a00 = fma2(W0.y, A0.y, a00); a01 = fma2(W0.y, A1.y, a01);
        a10 = fma2(W1.y, A0.y, a10); a11 = fma2(W1.y, A1.y, a11);
    }
}

__global__ void __launch_bounds__(256, 1)
lstm1_kernel(const float* __restrict__ x,
             const float* __restrict__ Wih, const float* __restrict__ Whh,
             const float* __restrict__ bih, const float* __restrict__ bhh,
             float* __restrict__ dout)
{
    extern __shared__ float sm[];
    float* sW = sm;                      // 16*580
    float* sA = sW + 16 * SW1;           // 64*588
    float* sG = sA + 64 * SA1;           // 16*65
    float* sB = sG + 16 * 65;            // 16
    float* sC = sB + 16;                 // 256
    const int tid = threadIdx.x;
    const int bx  = blockIdx.x;

    // stage weights once: row r = gate*4+hcl, cols [x 64 | h 512]
    for (int i = tid; i < 16 * 576; i += 256) {
        int r = i / 576, k = i - r * 576;
        int gr = (r >> 2) * H1 + bx * 4 + (r & 3);
        sW[r * SW1 + k] = (k < INW) ? Wih[gr * INW + k] : Whh[gr * H1 + (k - INW)];
    }
    if (tid < 16) {
        int gr = (tid >> 2) * H1 + bx * 4 + (tid & 3);
        sB[tid] = bih[gr] + bhh[gr];
    }
    sC[tid] = 0.f;
    __syncthreads();

    const int gI = tid & 7;
    const int rp = tid >> 3;
    const uint32_t aB = s2u(sA);

    for (int t = 0; t < TT; ++t) {
        if (t == 0) { load1(0, 0, x, aB); cpcommit(); }
        else {
#pragma unroll
            for (int c = 0; c < 9; ++c) { load1(c, t, x, aB); cpcommit(); }
        }

        ull a00 = 0, a01 = 0, a10 = 0, a11 = 0;
        if (t == 0) {
            cpwait(0); __syncthreads();
            chunk1(sW, sA, gI, rp, 0, a00, a01, a10, a11);
        } else {
#pragma unroll
            for (int c = 0; c < 9; ++c) {
                cpwait(8 - c); __syncthreads();
                chunk1(sW, sA, gI, rp, c, a00, a01, a10, a11);
            }
        }

        // gate exchange
        sG[(2 * gI) * 65 + 2 * rp]         = psum(a00);
        sG[(2 * gI) * 65 + 2 * rp + 1]     = psum(a01);
        sG[(2 * gI + 1) * 65 + 2 * rp]     = psum(a10);
        sG[(2 * gI + 1) * 65 + 2 * rp + 1] = psum(a11);
        __syncthreads();

        // cell update: thread = (n, hcl)
        {
            int n = tid >> 2, hcl = tid & 3;
            float xi = sG[hcl * 65 + n]        + sB[hcl];
            float xf = sG[(4 + hcl) * 65 + n]  + sB[4 + hcl];
            float xg = sG[(8 + hcl) * 65 + n]  + sB[8 + hcl];
            float xo = sG[(12 + hcl) * 65 + n] + sB[12 + hcl];
            float cp = sC[tid];
            float cn = sigf(xf) * cp + sigf(xi) * tanhf(xg);
            sC[tid] = cn;
            float h = sigf(xo) * tanhf(cn);
            int hc = bx * 4 + hcl;
            g_out1[((size_t)n * TT + t) * H1 + hc] = h;
            if (t == TT - 1) {
                dout[65536 + n * H1 + hc] = h;
                dout[98304 + n * H1 + hc] = cn;
            }
        }

        if (t < TT - 1) {
            __threadfence();
            __syncthreads();
            if (tid == 0) {
                atomicAdd(&g_bar1, 1u);
                unsigned tgt = 128u * (unsigned)(t + 1);
                while (*(volatile unsigned*)&g_bar1 < tgt) {}
            }
            __syncthreads();
        }
    }
}

// ============================ LSTM layer 2 ============================
// 128 CTAs x 256 thr. CTA owns 2 hidden cols (8 gate rows), K=768.
// thread: ks=tid>>7 (k-half within chunk), gI=(tid&127)&3, rp=(tid&127)>>2.
__device__ __forceinline__ void load2(int c, int t, uint32_t aB) {
    const int tid = threadIdx.x;
#pragma unroll
    for (int j = 0; j < 4; ++j) {
        int o = j * 256 + tid;
        int row = o >> 4, f4 = o & 15;
        int col = c * 64 + f4 * 4;
        const float* src = (col < 512)
            ? g_out1 + ((size_t)row * TT + t) * H1 + col
            : g_out2 + ((size_t)row * TT + (t - 1)) * H2 + (col - 512);
        cp16(aB + (uint32_t)((row * SA2 + col) * 4), src);
    }
}

__device__ __forceinline__ void chunk2(const float* sW, const float* sA, int gI, int rp, int ks, int c,
                                       ull& a00, ull& a01, ull& a10, ull& a11) {
    const int kb = c * 64 + ks * 32;
    const ulonglong2* w0 = (const ulonglong2*)(sW + (2 * gI) * SW2 + kb);
    const ulonglong2* w1 = (const ulonglong2*)(sW + (2 * gI + 1) * SW2 + kb);
    const ulonglong2* p0 = (const ulonglong2*)(sA + (2 * rp) * SA2 + kb);
    const ulonglong2* p1 = (const ulonglong2*)(sA + (2 * rp + 1) * SA2 + kb);
#pragma unroll
    for (int i = 0; i < 8; ++i) {
        ulonglong2 W0 = w0[i], W1 = w1[i], A0 = p0[i], A1 = p1[i];
        a00 = fma2(W0.x, A0.x, a00); a01 = fma2(W0.x, A1.x, a01);
        a10 = fma2(W1.x, A0.x, a10); a11 = fma2(W1.x, A1.x, a11);
        a00 = fma2(W0.y, A0.y, a00); a01 = fma2(W0.y, A1.y, a01);
        a10 = fma2(W1.y, A0.y, a10); a11 = fma2(W1.y, A1.y, a11);
    }
}

__global__ void __launch_bounds__(256, 1)
lstm2_kernel(const float* __restrict__ Wih, const float* __restrict__ Whh,
             const float* __restrict__ bih, const float* __restrict__ bhh,
             float* __restrict__ dout)
{
    extern __shared__ float sm[];
    float* sW = sm;                      // 8*772
    float* sA = sW + 8 * SW2;            // 64*772
    float* sG = sA + 64 * SA2;           // 16*65 (2 k-halves x 8 rows)
    float* sB = sG + 16 * 65;            // 8
    float* sC = sB + 8;                  // 128
    const int tid = threadIdx.x;
    const int bx  = blockIdx.x;

    for (int i = tid; i < 8 * 768; i += 256) {
        int r = i / 768, k = i - r * 768;
        int gr = (r >> 1) * H2 + bx * 2 + (r & 1);
        sW[r * SW2 + k] = (k < H1) ? Wih[gr * H1 + k] : Whh[gr * H2 + (k - H1)];
    }
    if (tid < 8) {
        int gr = (tid >> 1) * H2 + bx * 2 + (tid & 1);
        sB[tid] = bih[gr] + bhh[gr];
    }
    if (tid < 128) sC[tid] = 0.f;
    __syncthreads();

    const int ks  = tid >> 7;
    const int rem = tid & 127;
    const int gI  = rem & 3;
    const int rp  = rem >> 2;
    const uint32_t aB = s2u(sA);

    for (int t = 0; t < TT; ++t) {
        if (t == 0) {
#pragma unroll
            for (int c = 0; c < 8; ++c) { load2(c, 0, aB); cpcommit(); }
        } else {
#pragma unroll
            for (int c = 0; c < 12; ++c) { load2(c, t, aB); cpcommit(); }
        }

        ull a00 = 0, a01 = 0, a10 = 0, a11 = 0;
        if (t == 0) {
#pragma unroll
            for (int c = 0; c < 8; ++c) {
                cpwait(7 - c); __syncthreads();
                chunk2(sW, sA, gI, rp, ks, c, a00, a01, a10, a11);
            }
        } else {
#pragma unroll
            for (int c = 0; c < 12; ++c) {
                cpwait(11 - c); __syncthreads();
                chunk2(sW, sA, gI, rp, ks, c, a00, a01, a10, a11);
            }
        }

        int base = (ks * 8 + 2 * gI) * 65;
        sG[base + 2 * rp]          = psum(a00);
        sG[base + 2 * rp + 1]      = psum(a01);
        sG[base + 65 + 2 * rp]     = psum(a10);
        sG[base + 65 + 2 * rp + 1] = psum(a11);
        __syncthreads();

        if (tid < 128) {
            int n = tid >> 1, hcl = tid & 1;
            float xi = sG[(0 + hcl) * 65 + n] + sG[(8 + hcl) * 65 + n]  + sB[0 + hcl];
            float xf = sG[(2 + hcl) * 65 + n] + sG[(10 + hcl) * 65 + n] + sB[2 + hcl];
            float xg = sG[(4 + hcl) * 65 + n] + sG[(12 + hcl) * 65 + n] + sB[4 + hcl];
            float xo = sG[(6 + hcl) * 65 + n] + sG[(14 + hcl) * 65 + n] + sB[6 + hcl];
            float cp = sC[tid];
            float cn = sigf(xf) * cp + sigf(xi) * tanhf(xg);
            sC[tid] = cn;
            float h = sigf(xo) * tanhf(cn);
            int hc = bx * 2 + hcl;
            g_out2[((size_t)n * TT + t) * H2 + hc] = h;
            if (t == TT - 1) {
                dout[131072 + n * H2 + hc] = h;
                dout[147456 + n * H2 + hc] = cn;
            }
        }

        if (t < TT - 1) {
            __threadfence();
            __syncthreads();
            if (tid == 0) {
                atomicAdd(&g_bar2, 1u);
                unsigned tgt = 128u * (unsigned)(t + 1);
                while (*(volatile unsigned*)&g_bar2 < tgt) {}
            }
            __syncthreads();
        }
    }
}

// ============================ causal attention ============================
__global__ void __launch_bounds__(256)
attn_kernel()
{
    const int lane = threadIdx.x & 31;
    const int gw = blockIdx.x * (blockDim.x >> 5) + (threadIdx.x >> 5);
    const int nw = gridDim.x * (blockDim.x >> 5);

    for (int row = gw; row < NB * TT; row += nw) {
        const int n = row >> 10;
        const int t = row & 1023;
        const float* bp = g_out2 + (size_t)n * TT * H2;
        const float4* qp = (const float4*)(bp + (size_t)t * H2);
        const float4 qa = qp[lane];
        const float4 qb = qp[lane + 32];

        float m = -1e30f, l = 0.f;
        float4 accA = make_float4(0.f, 0.f, 0.f, 0.f);
        float4 accB = make_float4(0.f, 0.f, 0.f, 0.f);

        for (int s = 0; s <= t; ++s) {
            const float4* kp = (const float4*)(bp + (size_t)s * H2);
            float4 ka = kp[lane];
            float4 kb = kp[lane + 32];
            float p = qa.x*ka.x + qa.y*ka.y + qa.z*ka.z + qa.w*ka.w
                    + qb.x*kb.x + qb.y*kb.y + qb.z*kb.z + qb.w*kb.w;
            p += __shfl_xor_sync(0xffffffffu, p, 16);
            p += __shfl_xor_sync(0xffffffffu, p, 8);
            p += __shfl_xor_sync(0xffffffffu, p, 4);
            p += __shfl_xor_sync(0xffffffffu, p, 2);
            p += __shfl_xor_sync(0xffffffffu, p, 1);
            float nm = fmaxf(m, p);
            float e  = __expf(p - nm);
            float sc = __expf(m - nm);
            l = l * sc + e;
            accA.x = accA.x*sc + e*ka.x; accA.y = accA.y*sc + e*ka.y;
            accA.z = accA.z*sc + e*ka.z; accA.w = accA.w*sc + e*ka.w;
            accB.x = accB.x*sc + e*kb.x; accB.y = accB.y*sc + e*kb.y;
            accB.z = accB.z*sc + e*kb.z; accB.w = accB.w*sc + e*kb.w;
            m = nm;
        }
        float inv = 1.f / l;
        float4* op = (float4*)(g_ctx + (size_t)row * H2);
        op[lane]      = make_float4(accA.x*inv, accA.y*inv, accA.z*inv, accA.w*inv);
        op[lane + 32] = make_float4(accB.x*inv, accB.y*inv, accB.z*inv, accB.w*inv);
    }
}

// ============================ MLP head ============================
__global__ void __launch_bounds__(128)
mlp_kernel(const float* __restrict__ fc1b,
           const float* __restrict__ fc2b,
           const float* __restrict__ fc3w, const float* __restrict__ fc3b,
           float* __restrict__ dout)
{
    __shared__ float sIn[16][512];
    __shared__ float sH1b[16][128];
    __shared__ float sH2b[16][52];
    const int tid = threadIdx.x;

    for (int tile = blockIdx.x; tile < (NB * TT) / 16; tile += gridDim.x) {
        const int row0 = tile * 16;
        for (int i = tid; i < 16 * 512; i += 128) {
            int r = i >> 9, c = i & 511;
            size_t row = (size_t)(row0 + r);
            sIn[r][c] = (c < 256) ? g_ctx[row * 256 + c] : g_out2[row * 256 + (c - 256)];
        }
        __syncthreads();

        {
            float acc[16];
            float b = fc1b[tid];
#pragma unroll
            for (int r = 0; r < 16; ++r) acc[r] = b;
            for (int k = 0; k < 512; ++k) {
                float w = g_fc1T[k * 128 + tid];
#pragma unroll
                for (int r = 0; r < 16; ++r) acc[r] = fmaf(w, sIn[r][k], acc[r]);
            }
#pragma unroll
            for (int r = 0; r < 16; ++r) sH1b[r][tid] = fmaxf(acc[r], 0.f);
        }
        __syncthreads();

        if (tid < 51) {
            float acc[16];
            float b = fc2b[tid];
#pragma unroll
            for (int r = 0; r < 16; ++r) acc[r] = b;
            for (int k = 0; k < 128; ++k) {
                float w = g_fc2T[k * 51 + tid];
#pragma unroll
                for (int r = 0; r < 16; ++r) acc[r] = fmaf(w, sH1b[r][k], acc[r]);
            }
#pragma unroll
            for (int r = 0; r < 16; ++r) sH2b[r][tid] = fmaxf(acc[r], 0.f);
        }
        __syncthreads();

        if (tid < 16) {
            float s = fc3b[0];
            for (int k = 0; k < 51; ++k) s = fmaf(fc3w[k], sH2b[tid][k], s);
            dout[row0 + tid] = s;
        }
        __syncthreads();
    }
}

// ============================ launch ============================
extern "C" void kernel_launch(void* const* d_in, const int* in_sizes, int n_in,
                              void* d_out, int out_size)
{
    const float* x     = (const float*)d_in[0];
    const float* Wih1  = (const float*)d_in[1];
    const float* Whh1  = (const float*)d_in[2];
    const float* bih1  = (const float*)d_in[3];
    const float* bhh1  = (const float*)d_in[4];
    const float* Wih2  = (const float*)d_in[5];
    const float* Whh2  = (const float*)d_in[6];
    const float* bih2  = (const float*)d_in[7];
    const float* bhh2  = (const float*)d_in[8];
    const float* fc1w  = (const float*)d_in[9];
    const float* fc1b  = (const float*)d_in[10];
    const float* fc2w  = (const float*)d_in[11];
    const float* fc2b  = (const float*)d_in[12];
    const float* fc3w  = (const float*)d_in[13];
    const float* fc3b  = (const float*)d_in[14];
    float* out = (float*)d_out;

    const int SM1 = (16 * SW1 + 64 * SA1 + 16 * 65 + 16 + 256) * 4;   // 192,896 B
    const int SM2 = (8 * SW2 + 64 * SA2 + 16 * 65 + 8 + 128) * 4;     // 227,040 B
    cudaFuncSetAttribute(lstm1_kernel, cudaFuncAttributeMaxDynamicSharedMemorySize, SM1);
    cudaFuncSetAttribute(lstm2_kernel, cudaFuncAttributeMaxDynamicSharedMemorySize, SM2);

    reset_kernel<<<1, 1>>>();
    prep_kernel<<<(128 * 512 + 255) / 256, 256>>>(fc1w, fc2w);
    lstm1_kernel<<<128, 256, SM1>>>(x, Wih1, Whh1, bih1, bhh1, out);
    lstm2_kernel<<<128, 256, SM2>>>(Wih2, Whh2, bih2, bhh2, out);
    attn_kernel<<<592, 256>>>();
    mlp_kernel<<<1024, 128>>>(fc1b, fc2b, fc3w, fc3b, out);
}

// round 10
// speedup vs baseline: 1.6968x; 1.6968x over previous
#include <cuda_runtime.h>
#include <math.h>
#include <stdint.h>

typedef unsigned long long ull;

#define NB   64
#define TT   1024
#define INW  64
#define H1   512
#define H2   256

// ---------------- scratch (static device globals; no allocation) ----------------
__device__ float g_out1[(size_t)NB * TT * H1];
__device__ float g_out2[(size_t)NB * TT * H2];
__device__ float g_ctx [(size_t)NB * TT * H2];
__device__ float g_fc1T[512 * 128];
__device__ float g_fc2T[128 * 51];
__device__ unsigned g_bars[64];

__global__ void reset_kernel() {
    if (threadIdx.x < 64) g_bars[threadIdx.x] = 0u;
}

__global__ void prep_kernel(const float* __restrict__ fc1w, const float* __restrict__ fc2w) {
    int i = blockIdx.x * blockDim.x + threadIdx.x;
    if (i < 128 * 512) { int j = i / 512, k = i % 512; g_fc1T[k * 128 + j] = fc1w[i]; }
    if (i < 51 * 128)  { int j = i / 128, k = i % 128; g_fc2T[k * 51 + j] = fc2w[i]; }
}

// ---------------- helpers ----------------
__device__ __forceinline__ float sigf(float x) { return 1.f / (1.f + __expf(-x)); }

__device__ __forceinline__ uint32_t s2u(const void* p) {
    uint32_t a;
    asm("{ .reg .u64 t; cvta.to.shared.u64 t, %1; cvt.u32.u64 %0, t; }" : "=r"(a) : "l"(p));
    return a;
}
__device__ __forceinline__ void cp16(uint32_t dst, const void* src) {
    asm volatile("cp.async.cg.shared.global [%0], [%1], 16;" :: "r"(dst), "l"(src));
}
__device__ __forceinline__ void cpcommit() {
    asm volatile("cp.async.commit_group;" ::: "memory");
}
template <int N>
__device__ __forceinline__ void cpwait() {
    asm volatile("cp.async.wait_group %0;" :: "n"(N) : "memory");
}
__device__ __forceinline__ ull fma2(ull a, ull b, ull c) {
    ull d;
    asm("fma.rn.f32x2 %0, %1, %2, %3;" : "=l"(d) : "l"(a), "l"(b), "l"(c));
    return d;
}
__device__ __forceinline__ ull add2(ull a, ull b) {
    ull d;
    asm("add.rn.f32x2 %0, %1, %2;" : "=l"(d) : "l"(a), "l"(b));
    return d;
}
__device__ __forceinline__ float psum(ull a) {
    return __int_as_float((int)(a & 0xffffffffULL)) + __int_as_float((int)(a >> 32));
}
__device__ __forceinline__ unsigned ldvol(const unsigned* p) {
    unsigned v;
    asm volatile("ld.volatile.global.u32 %0, [%1];" : "=r"(v) : "l"(p));
    return v;
}
__device__ __forceinline__ void gridbar(unsigned* ctr, unsigned tgt) {
    __threadfence();
    __syncthreads();
    if (threadIdx.x == 0) {
        atomicAdd(ctr, 1u);
        while (ldvol(ctr) < tgt) { __nanosleep(32); }
    }
    __syncthreads();
}

// ============================ LSTM layer 1 ============================
// 128 CTAs x 512 thr. CTA bx: hidden group hg=bx>>1 (8 cols), rowgrp=bx&1 (32 rows).
// Thread: hcl=tid&7, rq=(tid>>3)&7, ks=tid>>6. Tile: 4 gates x 4 rows, K-slice ks.
__global__ void __launch_bounds__(512, 1)
lstm1_kernel(const float* __restrict__ x,
             const float* __restrict__ Wih, const float* __restrict__ Whh,
             const float* __restrict__ bih, const float* __restrict__ bhh,
             float* __restrict__ dout)
{
    extern __shared__ float sm[];
    float* sW    = sm;
    float* sA    = sm + 18560;
    ull*   sP    = (ull*)(sm + 37120);
    float* sBias = sm + 54016;
    float* sC    = sm + 54048;

    const int tid = threadIdx.x;
    const int bx  = blockIdx.x;
    const int hg = bx >> 1, rowgrp = bx & 1, rows0 = rowgrp * 32;

    for (int i = tid; i < 32 * 576; i += 512) {
        int lr = i / 576, k = i - lr * 576;
        int g = lr >> 3, hc = lr & 7;
        int grow = g * H1 + hg * 8 + hc;
        sW[lr * 580 + k] = (k < INW) ? Wih[grow * INW + k] : Whh[grow * H1 + (k - INW)];
    }
    if (tid < 32) {
        int g = tid >> 3, hc = tid & 7;
        int grow = g * H1 + hg * 8 + hc;
        sBias[tid] = bih[grow] + bhh[grow];
    }
    if (tid < 256) sC[tid] = 0.f;
    for (int i = tid; i < 32 * 512; i += 512) {
        int row = i >> 9, c = i & 511;
        sA[row * 580 + 64 + c] = 0.f;
    }
    __syncthreads();

    const int hcl = tid & 7;
    const int rq  = (tid >> 3) & 7;
    const int ks  = tid >> 6;
    const int lr_ = tid >> 4;
    const int lc  = tid & 15;
    const int lp  = (lr_ >> 2) + (lr_ & 3) * 8;
    const uint32_t aB = s2u(sA);
    unsigned* ctr = &g_bars[rowgrp * 16];        // 0 or 16 (lstm1-private)

    for (int t = 0; t < TT; ++t) {
#pragma unroll
        for (int ch = 0; ch < 3; ++ch) {
#pragma unroll
            for (int jj = 0; jj < 3; ++jj) {
                int j = ch * 3 + jj;
                if (t > 0 || j == 0) {
                    int k4 = lc + 16 * j;
                    const float* src = (j == 0)
                        ? x + ((size_t)(rows0 + lr_) * TT + t) * INW + k4 * 4
                        : g_out1 + ((size_t)(rows0 + lr_) * TT + (t - 1)) * H1 + (k4 * 4 - 64);
                    cp16(aB + (uint32_t)((lp * 580 + k4 * 4) * 4), src);
                }
            }
            cpcommit();
        }

        ull acc[16];
#pragma unroll
        for (int i = 0; i < 16; ++i) acc[i] = 0;

#pragma unroll
        for (int ch = 0; ch < 3; ++ch) {
            if (ch == 0) cpwait<2>();
            else if (ch == 1) cpwait<1>();
            else cpwait<0>();
            __syncthreads();
#pragma unroll
            for (int m = 0; m < 3; ++m) {
                int grp = ks + 8 * (ch * 3 + m);
                int kb = grp * 8;
#pragma unroll
                for (int u = 0; u < 2; ++u) {
                    int ko = kb + u * 4;
                    ulonglong2 W0 = *(const ulonglong2*)(sW + (hcl)      * 580 + ko);
                    ulonglong2 W1 = *(const ulonglong2*)(sW + (8 + hcl)  * 580 + ko);
                    ulonglong2 W2 = *(const ulonglong2*)(sW + (16 + hcl) * 580 + ko);
                    ulonglong2 W3 = *(const ulonglong2*)(sW + (24 + hcl) * 580 + ko);
                    ulonglong2 A0 = *(const ulonglong2*)(sA + (rq)      * 580 + ko);
                    ulonglong2 A1 = *(const ulonglong2*)(sA + (rq + 8)  * 580 + ko);
                    ulonglong2 A2 = *(const ulonglong2*)(sA + (rq + 16) * 580 + ko);
                    ulonglong2 A3 = *(const ulonglong2*)(sA + (rq + 24) * 580 + ko);
                    acc[0]  = fma2(W0.x, A0.x, acc[0]);  acc[0]  = fma2(W0.y, A0.y, acc[0]);
                    acc[1]  = fma2(W0.x, A1.x, acc[1]);  acc[1]  = fma2(W0.y, A1.y, acc[1]);
                    acc[2]  = fma2(W0.x, A2.x, acc[2]);  acc[2]  = fma2(W0.y, A2.y, acc[2]);
                    acc[3]  = fma2(W0.x, A3.x, acc[3]);  acc[3]  = fma2(W0.y, A3.y, acc[3]);
                    acc[4]  = fma2(W1.x, A0.x, acc[4]);  acc[4]  = fma2(W1.y, A0.y, acc[4]);
                    acc[5]  = fma2(W1.x, A1.x, acc[5]);  acc[5]  = fma2(W1.y, A1.y, acc[5]);
                    acc[6]  = fma2(W1.x, A2.x, acc[6]);  acc[6]  = fma2(W1.y, A2.y, acc[6]);
                    acc[7]  = fma2(W1.x, A3.x, acc[7]);  acc[7]  = fma2(W1.y, A3.y, acc[7]);
                    acc[8]  = fma2(W2.x, A0.x, acc[8]);  acc[8]  = fma2(W2.y, A0.y, acc[8]);
                    acc[9]  = fma2(W2.x, A1.x, acc[9]);  acc[9]  = fma2(W2.y, A1.y, acc[9]);
                    acc[10] = fma2(W2.x, A2.x, acc[10]); acc[10] = fma2(W2.y, A2.y, acc[10]);
                    acc[11] = fma2(W2.x, A3.x, acc[11]); acc[11] = fma2(W2.y, A3.y, acc[11]);
                    acc[12] = fma2(W3.x, A0.x, acc[12]); acc[12] = fma2(W3.y, A0.y, acc[12]);
                    acc[13] = fma2(W3.x, A1.x, acc[13]); acc[13] = fma2(W3.y, A1.y, acc[13]);
                    acc[14] = fma2(W3.x, A2.x, acc[14]); acc[14] = fma2(W3.y, A2.y, acc[14]);
                    acc[15] = fma2(W3.x, A3.x, acc[15]); acc[15] = fma2(W3.y, A3.y, acc[15]);
                }
            }
        }

#pragma unroll
        for (int g = 0; g < 4; ++g) {
#pragma unroll
            for (int r = 0; r < 4; ++r) {
                int cell = (rq * 4 + r) * 8 + hcl;
                int col = g * 8 + ((ks + rq) & 7);
                sP[cell * 33 + col] = acc[g * 4 + r];
            }
        }
        __syncthreads();

        if (tid < 256) {
            int n = tid >> 3, hc = tid & 7;
            const ull* pp = sP + tid * 33;
            float gate[4];
#pragma unroll
            for (int g = 0; g < 4; ++g) {
                ull s0 = add2(pp[g * 8 + 0], pp[g * 8 + 1]);
                ull s1 = add2(pp[g * 8 + 2], pp[g * 8 + 3]);
                ull s2 = add2(pp[g * 8 + 4], pp[g * 8 + 5]);
                ull s3 = add2(pp[g * 8 + 6], pp[g * 8 + 7]);
                ull s = add2(add2(s0, s1), add2(s2, s3));
                gate[g] = psum(s) + sBias[g * 8 + hc];
            }
            float cp = sC[tid];
            float cn = sigf(gate[1]) * cp + sigf(gate[0]) * tanhf(gate[2]);
            sC[tid] = cn;
            float h = sigf(gate[3]) * tanhf(cn);
            int ng = rows0 + n;
            int hcg = hg * 8 + hc;
            g_out1[((size_t)ng * TT + t) * H1 + hcg] = h;
            if (t == TT - 1) {
                dout[65536 + ng * H1 + hcg] = h;
                dout[98304 + ng * H1 + hcg] = cn;
            }
        }

        if (t < TT - 1) gridbar(ctr, 64u * (unsigned)(t + 1));
    }
}

// ============================ LSTM layer 2 ============================
__global__ void __launch_bounds__(512, 1)
lstm2_kernel(const float* __restrict__ Wih, const float* __restrict__ Whh,
             const float* __restrict__ bih, const float* __restrict__ bhh,
             float* __restrict__ dout)
{
    extern __shared__ float sm[];
    float* sW    = sm;
    float* sA    = sm + 12352;
    ull*   sP    = (ull*)(sm + 37056);
    float* sBias = sm + 53696;
    float* sC    = sm + 53712;

    const int tid = threadIdx.x;
    const int bx  = blockIdx.x;
    const int hg = bx >> 1, rowgrp = bx & 1, rows0 = rowgrp * 32;

    for (int i = tid; i < 16 * 768; i += 512) {
        int lr = i / 768, k = i - lr * 768;
        int g = lr >> 2, hc = lr & 3;
        int grow = g * H2 + hg * 4 + hc;
        sW[lr * 772 + k] = (k < H1) ? Wih[grow * H1 + k] : Whh[grow * H2 + (k - H1)];
    }
    if (tid < 16) {
        int g = tid >> 2, hc = tid & 3;
        int grow = g * H2 + hg * 4 + hc;
        sBias[tid] = bih[grow] + bhh[grow];
    }
    if (tid < 128) sC[tid] = 0.f;
    for (int i = tid; i < 32 * 256; i += 512) {
        int row = i >> 8, c = i & 255;
        sA[row * 772 + 512 + c] = 0.f;
    }
    __syncthreads();

    const int hcl = tid & 3;
    const int rq  = (tid >> 2) & 7;
    const int ks  = tid >> 5;
    const int lr_ = tid >> 4;
    const int lc  = tid & 15;
    const int lp  = (lr_ >> 2) + (lr_ & 3) * 8;
    const uint32_t aB = s2u(sA);
    unsigned* ctr = &g_bars[32 + rowgrp * 16];   // 32 or 48 (lstm2-private)

    for (int t = 0; t < TT; ++t) {
#pragma unroll
        for (int ch = 0; ch < 3; ++ch) {
#pragma unroll
            for (int jj = 0; jj < 4; ++jj) {
                int j = ch * 4 + jj;
                if (t > 0 || j < 8) {
                    int k4 = lc + 16 * j;
                    const float* src = (j < 8)
                        ? g_out1 + ((size_t)(rows0 + lr_) * TT + t) * H1 + k4 * 4
                        : g_out2 + ((size_t)(rows0 + lr_) * TT + (t - 1)) * H2 + (k4 * 4 - 512);
                    cp16(aB + (uint32_t)((lp * 772 + k4 * 4) * 4), src);
                }
            }
            cpcommit();
        }

        ull acc[16];
#pragma unroll
        for (int i = 0; i < 16; ++i) acc[i] = 0;

#pragma unroll
        for (int ch = 0; ch < 3; ++ch) {
            if (ch == 0) cpwait<2>();
            else if (ch == 1) cpwait<1>();
            else cpwait<0>();
            __syncthreads();
#pragma unroll
            for (int m = 0; m < 2; ++m) {
                int grp = ks + 16 * (ch * 2 + m);
                int kb = grp * 8;
#pragma unroll
                for (int u = 0; u < 2; ++u) {
                    int ko = kb + u * 4;
                    ulonglong2 W0 = *(const ulonglong2*)(sW + (hcl)      * 772 + ko);
                    ulonglong2 W1 = *(const ulonglong2*)(sW + (4 + hcl)  * 772 + ko);
                    ulonglong2 W2 = *(const ulonglong2*)(sW + (8 + hcl)  * 772 + ko);
                    ulonglong2 W3 = *(const ulonglong2*)(sW + (12 + hcl) * 772 + ko);
                    ulonglong2 A0 = *(const ulonglong2*)(sA + (rq)      * 772 + ko);
                    ulonglong2 A1 = *(const ulonglong2*)(sA + (rq + 8)  * 772 + ko);
                    ulonglong2 A2 = *(const ulonglong2*)(sA + (rq + 16) * 772 + ko);
                    ulonglong2 A3 = *(const ulonglong2*)(sA + (rq + 24) * 772 + ko);
                    acc[0]  = fma2(W0.x, A0.x, acc[0]);  acc[0]  = fma2(W0.y, A0.y, acc[0]);
                    acc[1]  = fma2(W0.x, A1.x, acc[1]);  acc[1]  = fma2(W0.y, A1.y, acc[1]);
                    acc[2]  = fma2(W0.x, A2.x, acc[2]);  acc[2]  = fma2(W0.y, A2.y, acc[2]);
                    acc[3]  = fma2(W0.x, A3.x, acc[3]);  acc[3]  = fma2(W0.y, A3.y, acc[3]);
                    acc[4]  = fma2(W1.x, A0.x, acc[4]);  acc[4]  = fma2(W1.y, A0.y, acc[4]);
                    acc[5]  = fma2(W1.x, A1.x, acc[5]);  acc[5]  = fma2(W1.y, A1.y, acc[5]);
                    acc[6]  = fma2(W1.x, A2.x, acc[6]);  acc[6]  = fma2(W1.y, A2.y, acc[6]);
                    acc[7]  = fma2(W1.x, A3.x, acc[7]);  acc[7]  = fma2(W1.y, A3.y, acc[7]);
                    acc[8]  = fma2(W2.x, A0.x, acc[8]);  acc[8]  = fma2(W2.y, A0.y, acc[8]);
                    acc[9]  = fma2(W2.x, A1.x, acc[9]);  acc[9]  = fma2(W2.y, A1.y, acc[9]);
                    acc[10] = fma2(W2.x, A2.x, acc[10]); acc[10] = fma2(W2.y, A2.y, acc[10]);
                    acc[11] = fma2(W2.x, A3.x, acc[11]); acc[11] = fma2(W2.y, A3.y, acc[11]);
                    acc[12] = fma2(W3.x, A0.x, acc[12]); acc[12] = fma2(W3.y, A0.y, acc[12]);
                    acc[13] = fma2(W3.x, A1.x, acc[13]); acc[13] = fma2(W3.y, A1.y, acc[13]);
                    acc[14] = fma2(W3.x, A2.x, acc[14]); acc[14] = fma2(W3.y, A2.y, acc[14]);
                    acc[15] = fma2(W3.x, A3.x, acc[15]); acc[15] = fma2(W3.y, A3.y, acc[15]);
                }
            }
        }

#pragma unroll
        for (int g = 0; g < 4; ++g) {
#pragma unroll
            for (int r = 0; r < 4; ++r) {
                int cell = (rq * 4 + r) * 4 + hcl;
                int col = g * 16 + ((ks + rq) & 15);
                sP[cell * 65 + col] = acc[g * 4 + r];
            }
        }
        __syncthreads();

        if (tid < 128) {
            int n = tid >> 2, hc = tid & 3;
            const ull* pp = sP + tid * 65;
            float gate[4];
#pragma unroll
            for (int g = 0; g < 4; ++g) {
                ull s = pp[g * 16];
#pragma unroll
                for (int j = 1; j < 16; ++j) s = add2(s, pp[g * 16 + j]);
                gate[g] = psum(s) + sBias[g * 4 + hc];
            }
            float cp = sC[tid];
            float cn = sigf(gate[1]) * cp + sigf(gate[0]) * tanhf(gate[2]);
            sC[tid] = cn;
            float h = sigf(gate[3]) * tanhf(cn);
            int ng = rows0 + n;
            int hcg = hg * 4 + hc;
            g_out2[((size_t)ng * TT + t) * H2 + hcg] = h;
            if (t == TT - 1) {
                dout[131072 + ng * H2 + hcg] = h;
                dout[147456 + ng * H2 + hcg] = cn;
            }
        }

        if (t < TT - 1) gridbar(ctr, 64u * (unsigned)(t + 1));
    }
}

// ============================ causal attention (tiled) ============================
__global__ void __launch_bounds__(256)
attn_kernel()
{
    __shared__ float sK[32 * 256];
    const int tid = threadIdx.x;
    const int lane = tid & 31, warp = tid >> 5;
    const int qb = blockIdx.x, n = blockIdx.y;
    const int q0 = qb * 16 + warp * 2, q1 = q0 + 1;
    const float* bp = g_out2 + (size_t)n * TT * H2;

    const float4* qp0 = (const float4*)(bp + (size_t)q0 * H2) + lane * 2;
    const float4* qp1 = (const float4*)(bp + (size_t)q1 * H2) + lane * 2;
    float4 q0a = qp0[0], q0b = qp0[1];
    float4 q1a = qp1[0], q1b = qp1[1];

    float m0 = -1e30f, l0 = 0.f, m1 = -1e30f, l1 = 0.f;
    float4 a0a = {0,0,0,0}, a0b = {0,0,0,0}, a1a = {0,0,0,0}, a1b = {0,0,0,0};

    const int ntiles = (qb * 16 + 16 + 31) >> 5;
    const uint32_t kB = s2u(sK);

    for (int tile = 0; tile < ntiles; ++tile) {
        const int s0 = tile * 32;
        __syncthreads();
#pragma unroll
        for (int jj = 0; jj < 8; ++jj) {
            int flat = jj * 256 + tid;
            int key = flat >> 6, off = flat & 63;
            cp16(kB + (uint32_t)flat * 16, bp + (size_t)(s0 + key) * H2 + off * 4);
        }
        cpcommit();
        cpwait<0>();
        __syncthreads();

        int kmax = q1 - s0 + 1;
        if (kmax > 32) kmax = 32;
        for (int kk = 0; kk < kmax; ++kk) {
            const float4* kp = (const float4*)(sK + kk * 256) + lane * 2;
            float4 ka = kp[0], kb4 = kp[1];
            float p0 = q0a.x*ka.x + q0a.y*ka.y + q0a.z*ka.z + q0a.w*ka.w
                     + q0b.x*kb4.x + q0b.y*kb4.y + q0b.z*kb4.z + q0b.w*kb4.w;
            float p1 = q1a.x*ka.x + q1a.y*ka.y + q1a.z*ka.z + q1a.w*ka.w
                     + q1b.x*kb4.x + q1b.y*kb4.y + q1b.z*kb4.z + q1b.w*kb4.w;
            p0 += __shfl_xor_sync(0xffffffffu, p0, 16);
            p1 += __shfl_xor_sync(0xffffffffu, p1, 16);
            p0 += __shfl_xor_sync(0xffffffffu, p0, 8);
            p1 += __shfl_xor_sync(0xffffffffu, p1, 8);
            p0 += __shfl_xor_sync(0xffffffffu, p0, 4);
            p1 += __shfl_xor_sync(0xffffffffu, p1, 4);
            p0 += __shfl_xor_sync(0xffffffffu, p0, 2);
            p1 += __shfl_xor_sync(0xffffffffu, p1, 2);
            p0 += __shfl_xor_sync(0xffffffffu, p0, 1);
            p1 += __shfl_xor_sync(0xffffffffu, p1, 1);
            int keyg = s0 + kk;
            {
                float nm = fmaxf(m1, p1);
                float e  = __expf(p1 - nm);
                float sc = __expf(m1 - nm);
                l1 = l1 * sc + e; m1 = nm;
                a1a.x = a1a.x*sc + e*ka.x;  a1a.y = a1a.y*sc + e*ka.y;
                a1a.z = a1a.z*sc + e*ka.z;  a1a.w = a1a.w*sc + e*ka.w;
                a1b.x = a1b.x*sc + e*kb4.x; a1b.y = a1b.y*sc + e*kb4.y;
                a1b.z = a1b.z*sc + e*kb4.z; a1b.w = a1b.w*sc + e*kb4.w;
            }
            if (keyg <= q0) {
                float nm = fmaxf(m0, p0);
                float e  = __expf(p0 - nm);
                float sc = __expf(m0 - nm);
                l0 = l0 * sc + e; m0 = nm;
                a0a.x = a0a.x*sc + e*ka.x;  a0a.y = a0a.y*sc + e*ka.y;
                a0a.z = a0a.z*sc + e*ka.z;  a0a.w = a0a.w*sc + e*ka.w;
                a0b.x = a0b.x*sc + e*kb4.x; a0b.y = a0b.y*sc + e*kb4.y;
                a0b.z = a0b.z*sc + e*kb4.z; a0b.w = a0b.w*sc + e*kb4.w;
            }
        }
    }

    float i0 = 1.f / l0, i1 = 1.f / l1;
    float4* o0 = (float4*)(g_ctx + ((size_t)n * TT + q0) * H2) + lane * 2;
    float4* o1 = (float4*)(g_ctx + ((size_t)n * TT + q1) * H2) + lane * 2;
    o0[0] = make_float4(a0a.x*i0, a0a.y*i0, a0a.z*i0, a0a.w*i0);
    o0[1] = make_float4(a0b.x*i0, a0b.y*i0, a0b.z*i0, a0b.w*i0);
    o1[0] = make_float4(a1a.x*i1, a1a.y*i1, a1a.z*i1, a1a.w*i1);
    o1[1] = make_float4(a1b.x*i1, a1b.y*i1, a1b.z*i1, a1b.w*i1);
}

// ============================ MLP head ============================
__global__ void __launch_bounds__(128)
mlp_kernel(const float* __restrict__ fc1b,
           const float* __restrict__ fc2b,
           const float* __restrict__ fc3w, const float* __restrict__ fc3b,
           float* __restrict__ dout)
{
    __shared__ float sIn[16][512];
    __shared__ float sH1b[16][128];
    __shared__ float sH2b[16][52];
    const int tid = threadIdx.x;

    for (int tile = blockIdx.x; tile < (NB * TT) / 16; tile += gridDim.x) {
        const int row0 = tile * 16;
        for (int i = tid; i < 16 * 512; i += 128) {
            int r = i >> 9, c = i & 511;
            size_t row = (size_t)(row0 + r);
            sIn[r][c] = (c < 256) ? g_ctx[row * 256 + c] : g_out2[row * 256 + (c - 256)];
        }
        __syncthreads();

        {
            float acc[16];
            float b = fc1b[tid];
#pragma unroll
            for (int r = 0; r < 16; ++r) acc[r] = b;
            for (int k = 0; k < 512; ++k) {
                float w = g_fc1T[k * 128 + tid];
#pragma unroll
                for (int r = 0; r < 16; ++r) acc[r] = fmaf(w, sIn[r][k], acc[r]);
            }
#pragma unroll
            for (int r = 0; r < 16; ++r) sH1b[r][tid] = fmaxf(acc[r], 0.f);
        }
        __syncthreads();

        if (tid < 51) {
            float acc[16];
            float b = fc2b[tid];
#pragma unroll
            for (int r = 0; r < 16; ++r) acc[r] = b;
            for (int k = 0; k < 128; ++k) {
                float w = g_fc2T[k * 51 + tid];
#pragma unroll
                for (int r = 0; r < 16; ++r) acc[r] = fmaf(w, sH1b[r][k], acc[r]);
            }
#pragma unroll
            for (int r = 0; r < 16; ++r) sH2b[r][tid] = fmaxf(acc[r], 0.f);
        }
        __syncthreads();

        if (tid < 16) {
            float s = fc3b[0];
            for (int k = 0; k < 51; ++k) s = fmaf(fc3w[k], sH2b[tid][k], s);
            dout[row0 + tid] = s;
        }
        __syncthreads();
    }
}

// ============================ launch ============================
extern "C" void kernel_launch(void* const* d_in, const int* in_sizes, int n_in,
                              void* d_out, int out_size)
{
    const float* x     = (const float*)d_in[0];
    const float* Wih1  = (const float*)d_in[1];
    const float* Whh1  = (const float*)d_in[2];
    const float* bih1  = (const float*)d_in[3];
    const float* bhh1  = (const float*)d_in[4];
    const float* Wih2  = (const float*)d_in[5];
    const float* Whh2  = (const float*)d_in[6];
    const float* bih2  = (const float*)d_in[7];
    const float* bhh2  = (const float*)d_in[8];
    const float* fc1w  = (const float*)d_in[9];
    const float* fc1b  = (const float*)d_in[10];
    const float* fc2w  = (const float*)d_in[11];
    const float* fc2b  = (const float*)d_in[12];
    const float* fc3w  = (const float*)d_in[13];
    const float* fc3b  = (const float*)d_in[14];
    float* out = (float*)d_out;

    const int SM1 = 54304 * 4;
    const int SM2 = 53840 * 4;
    cudaFuncSetAttribute(lstm1_kernel, cudaFuncAttributeMaxDynamicSharedMemorySize, SM1);
    cudaFuncSetAttribute(lstm2_kernel, cudaFuncAttributeMaxDynamicSharedMemorySize, SM2);

    reset_kernel<<<1, 64>>>();
    prep_kernel<<<(128 * 512 + 255) / 256, 256>>>(fc1w, fc2w);
    lstm1_kernel<<<128, 512, SM1>>>(x, Wih1, Whh1, bih1, bhh1, out);
    lstm2_kernel<<<128, 512, SM2>>>(Wih2, Whh2, bih2, bhh2, out);
    {
        dim3 grid(64, 64);
        attn_kernel<<<grid, 256>>>();
    }
    mlp_kernel<<<1024, 128>>>(fc1b, fc2b, fc3w, fc3b, out);
}

// round 11
// speedup vs baseline: 1.7450x; 1.0284x over previous
#include <cuda_runtime.h>
#include <math.h>
#include <stdint.h>

typedef unsigned long long ull;

#define NB   64
#define TT   1024
#define INW  64
#define H1   512
#define H2   256

// ---------------- scratch (static device globals; no allocation) ----------------
__device__ float g_out1[(size_t)NB * TT * H1];
__device__ float g_out2[(size_t)NB * TT * H2];
__device__ float g_ctx [(size_t)NB * TT * H2];
__device__ float g_fc1T[512 * 128];
__device__ float g_fc2T[128 * 51];
__device__ unsigned g_bars[64];

__global__ void reset_kernel() {
    if (threadIdx.x < 64) g_bars[threadIdx.x] = 0u;
}

__global__ void prep_kernel(const float* __restrict__ fc1w, const float* __restrict__ fc2w) {
    int i = blockIdx.x * blockDim.x + threadIdx.x;
    if (i < 128 * 512) { int j = i / 512, k = i % 512; g_fc1T[k * 128 + j] = fc1w[i]; }
    if (i < 51 * 128)  { int j = i / 128, k = i % 128; g_fc2T[k * 51 + j] = fc2w[i]; }
}

// ---------------- helpers ----------------
__device__ __forceinline__ float sigf(float x) { return 1.f / (1.f + __expf(-x)); }

__device__ __forceinline__ uint32_t s2u(const void* p) {
    uint32_t a;
    asm("{ .reg .u64 t; cvta.to.shared.u64 t, %1; cvt.u32.u64 %0, t; }" : "=r"(a) : "l"(p));
    return a;
}
__device__ __forceinline__ void cp16(uint32_t dst, const void* src) {
    asm volatile("cp.async.cg.shared.global [%0], [%1], 16;" :: "r"(dst), "l"(src));
}
__device__ __forceinline__ void cpcommit() {
    asm volatile("cp.async.commit_group;" ::: "memory");
}
template <int N>
__device__ __forceinline__ void cpwait() {
    asm volatile("cp.async.wait_group %0;" :: "n"(N) : "memory");
}
__device__ __forceinline__ ull fma2(ull a, ull b, ull c) {
    ull d;
    asm("fma.rn.f32x2 %0, %1, %2, %3;" : "=l"(d) : "l"(a), "l"(b), "l"(c));
    return d;
}
__device__ __forceinline__ ull add2(ull a, ull b) {
    ull d;
    asm("add.rn.f32x2 %0, %1, %2;" : "=l"(d) : "l"(a), "l"(b));
    return d;
}
__device__ __forceinline__ float psum(ull a) {
    return __int_as_float((int)(a & 0xffffffffULL)) + __int_as_float((int)(a >> 32));
}
__device__ __forceinline__ unsigned ldvol(const unsigned* p) {
    unsigned v;
    asm volatile("ld.volatile.global.u32 %0, [%1];" : "=r"(v) : "l"(p));
    return v;
}

// ============================ LSTM layer 1 ============================
// 128 CTAs x 512 thr. CTA bx: hg=bx>>1 (8 hidden cols), rowgrp=bx&1 (32 rows). K=576.
// Thread tile: hcl=tid&7, rq=(tid>>3)&7, ks=tid>>6; 4 gates x 4 rows, K-sliced by ks.
// m-group q (0..8) covers K cols [64q, 64q+64): q0 = x part, q1..8 = h part.
__device__ __forceinline__ void compute1_q(const float* sW, const float* sA,
                                           int hcl, int rq, int ks, int q, ull* acc) {
    const int kb = (ks + 8 * q) * 8;
#pragma unroll
    for (int u = 0; u < 2; ++u) {
        int ko = kb + u * 4;
        ulonglong2 W0 = *(const ulonglong2*)(sW + (hcl)      * 580 + ko);
        ulonglong2 W1 = *(const ulonglong2*)(sW + (8 + hcl)  * 580 + ko);
        ulonglong2 W2 = *(const ulonglong2*)(sW + (16 + hcl) * 580 + ko);
        ulonglong2 W3 = *(const ulonglong2*)(sW + (24 + hcl) * 580 + ko);
        ulonglong2 A0 = *(const ulonglong2*)(sA + (rq)      * 580 + ko);
        ulonglong2 A1 = *(const ulonglong2*)(sA + (rq + 8)  * 580 + ko);
        ulonglong2 A2 = *(const ulonglong2*)(sA + (rq + 16) * 580 + ko);
        ulonglong2 A3 = *(const ulonglong2*)(sA + (rq + 24) * 580 + ko);
        acc[0]  = fma2(W0.x, A0.x, acc[0]);  acc[0]  = fma2(W0.y, A0.y, acc[0]);
        acc[1]  = fma2(W0.x, A1.x, acc[1]);  acc[1]  = fma2(W0.y, A1.y, acc[1]);
        acc[2]  = fma2(W0.x, A2.x, acc[2]);  acc[2]  = fma2(W0.y, A2.y, acc[2]);
        acc[3]  = fma2(W0.x, A3.x, acc[3]);  acc[3]  = fma2(W0.y, A3.y, acc[3]);
        acc[4]  = fma2(W1.x, A0.x, acc[4]);  acc[4]  = fma2(W1.y, A0.y, acc[4]);
        acc[5]  = fma2(W1.x, A1.x, acc[5]);  acc[5]  = fma2(W1.y, A1.y, acc[5]);
        acc[6]  = fma2(W1.x, A2.x, acc[6]);  acc[6]  = fma2(W1.y, A2.y, acc[6]);
        acc[7]  = fma2(W1.x, A3.x, acc[7]);  acc[7]  = fma2(W1.y, A3.y, acc[7]);
        acc[8]  = fma2(W2.x, A0.x, acc[8]);  acc[8]  = fma2(W2.y, A0.y, acc[8]);
        acc[9]  = fma2(W2.x, A1.x, acc[9]);  acc[9]  = fma2(W2.y, A1.y, acc[9]);
        acc[10] = fma2(W2.x, A2.x, acc[10]); acc[10] = fma2(W2.y, A2.y, acc[10]);
        acc[11] = fma2(W2.x, A3.x, acc[11]); acc[11] = fma2(W2.y, A3.y, acc[11]);
        acc[12] = fma2(W3.x, A0.x, acc[12]); acc[12] = fma2(W3.y, A0.y, acc[12]);
        acc[13] = fma2(W3.x, A1.x, acc[13]); acc[13] = fma2(W3.y, A1.y, acc[13]);
        acc[14] = fma2(W3.x, A2.x, acc[14]); acc[14] = fma2(W3.y, A2.y, acc[14]);
        acc[15] = fma2(W3.x, A3.x, acc[15]); acc[15] = fma2(W3.y, A3.y, acc[15]);
    }
}

__global__ void __launch_bounds__(512, 1)
lstm1_kernel(const float* __restrict__ x,
             const float* __restrict__ Wih, const float* __restrict__ Whh,
             const float* __restrict__ bih, const float* __restrict__ bhh,
             float* __restrict__ dout)
{
    extern __shared__ float sm[];
    float* sW    = sm;
    float* sA    = sm + 18560;
    ull*   sP    = (ull*)(sm + 37120);
    float* sBias = sm + 54016;
    float* sC    = sm + 54048;

    const int tid = threadIdx.x;
    const int bx  = blockIdx.x;
    const int hg = bx >> 1, rowgrp = bx & 1, rows0 = rowgrp * 32;

    for (int i = tid; i < 32 * 576; i += 512) {
        int lr = i / 576, k = i - lr * 576;
        int g = lr >> 3, hc = lr & 7;
        int grow = g * H1 + hg * 8 + hc;
        sW[lr * 580 + k] = (k < INW) ? Wih[grow * INW + k] : Whh[grow * H1 + (k - INW)];
    }
    if (tid < 32) {
        int g = tid >> 3, hc = tid & 7;
        int grow = g * H1 + hg * 8 + hc;
        sBias[tid] = bih[grow] + bhh[grow];
    }
    if (tid < 256) sC[tid] = 0.f;
    __syncthreads();

    const int hcl = tid & 7;
    const int rq  = (tid >> 3) & 7;
    const int ks  = tid >> 6;
    const int lr_ = tid >> 4;
    const int lc  = tid & 15;
    const int lp  = (lr_ >> 2) + (lr_ & 3) * 8;
    const uint32_t aB = s2u(sA);
    unsigned* ctr = &g_bars[rowgrp * 16];

    // prime: x loads for t=0 (1 group; 1 cp16 per thread)
    cp16(aB + (uint32_t)((lp * 580 + lc * 4) * 4),
         x + ((size_t)(rows0 + lr_) * TT + 0) * INW + lc * 4);
    cpcommit();

    for (int t = 0; t < TT; ++t) {
        ull acc[16];
#pragma unroll
        for (int i = 0; i < 16; ++i) acc[i] = 0;

        // ---- non-recurrent part: x chunk (loads issued last iteration) ----
        cpwait<0>(); __syncthreads();
        compute1_q(sW, sA, hcl, rq, ks, 0, acc);

        // ---- recurrent part ----
        if (t > 0) {
            if (tid == 0) {
                unsigned tgt = 64u * (unsigned)t;
                while (ldvol(ctr) < tgt) { __nanosleep(32); }
            }
            __syncthreads();
            // issue h[t-1] loads: j=1..4, j=5..8 (2 groups)
#pragma unroll
            for (int j = 1; j <= 4; ++j) {
                int k4 = lc + 16 * j;
                cp16(aB + (uint32_t)((lp * 580 + k4 * 4) * 4),
                     g_out1 + ((size_t)(rows0 + lr_) * TT + (t - 1)) * H1 + (k4 * 4 - 64));
            }
            cpcommit();
#pragma unroll
            for (int j = 5; j <= 8; ++j) {
                int k4 = lc + 16 * j;
                cp16(aB + (uint32_t)((lp * 580 + k4 * 4) * 4),
                     g_out1 + ((size_t)(rows0 + lr_) * TT + (t - 1)) * H1 + (k4 * 4 - 64));
            }
            cpcommit();

            cpwait<1>(); __syncthreads();
#pragma unroll
            for (int q = 1; q <= 4; ++q) compute1_q(sW, sA, hcl, rq, ks, q, acc);
            cpwait<0>(); __syncthreads();
#pragma unroll
            for (int q = 5; q <= 8; ++q) compute1_q(sW, sA, hcl, rq, ks, q, acc);
        }

        // ---- partial store ----
#pragma unroll
        for (int g = 0; g < 4; ++g) {
#pragma unroll
            for (int r = 0; r < 4; ++r) {
                int cell = (rq * 4 + r) * 8 + hcl;
                int col = g * 8 + ((ks + rq) & 7);
                sP[cell * 33 + col] = acc[g * 4 + r];
            }
        }
        __syncthreads();

        // ---- issue next step's x loads (overlaps reduce) ----
        if (t + 1 < TT) {
            cp16(aB + (uint32_t)((lp * 580 + lc * 4) * 4),
                 x + ((size_t)(rows0 + lr_) * TT + (t + 1)) * INW + lc * 4);
            cpcommit();
        }

        // ---- reduce + nonlinearity ----
        if (tid < 256) {
            int n = tid >> 3, hc = tid & 7;
            const ull* pp = sP + tid * 33;
            float gate[4];
#pragma unroll
            for (int g = 0; g < 4; ++g) {
                ull s0 = add2(pp[g * 8 + 0], pp[g * 8 + 1]);
                ull s1 = add2(pp[g * 8 + 2], pp[g * 8 + 3]);
                ull s2 = add2(pp[g * 8 + 4], pp[g * 8 + 5]);
                ull s3 = add2(pp[g * 8 + 6], pp[g * 8 + 7]);
                ull s = add2(add2(s0, s1), add2(s2, s3));
                gate[g] = psum(s) + sBias[g * 8 + hc];
            }
            float cp = sC[tid];
            float cn = sigf(gate[1]) * cp + sigf(gate[0]) * tanhf(gate[2]);
            sC[tid] = cn;
            float h = sigf(gate[3]) * tanhf(cn);
            int ng = rows0 + n;
            int hcg = hg * 8 + hc;
            g_out1[((size_t)ng * TT + t) * H1 + hcg] = h;
            if (t == TT - 1) {
                dout[65536 + ng * H1 + hcg] = h;
                dout[98304 + ng * H1 + hcg] = cn;
            }
        }

        // ---- arrive (early, spin happens mid next step) ----
        if (t < TT - 1) {
            __threadfence();
            __syncthreads();
            if (tid == 0) atomicAdd(ctr, 1u);
        }
    }
}

// ============================ LSTM layer 2 ============================
// 128 CTAs x 512 thr. hg=bx>>1 (4 hidden cols), rowgrp (32 rows). K=768.
// Thread: hcl=tid&3, rq=(tid>>2)&7, ks=tid>>5 (0..15).
// m-group q (0..5) covers K cols [128q,128q+128): q0..3 = h1[t] (non-recurrent), q4,5 = h2[t-1].
__device__ __forceinline__ void compute2_q(const float* sW, const float* sA,
                                           int hcl, int rq, int ks, int q, ull* acc) {
    const int kb = (ks + 16 * q) * 8;
#pragma unroll
    for (int u = 0; u < 2; ++u) {
        int ko = kb + u * 4;
        ulonglong2 W0 = *(const ulonglong2*)(sW + (hcl)      * 772 + ko);
        ulonglong2 W1 = *(const ulonglong2*)(sW + (4 + hcl)  * 772 + ko);
        ulonglong2 W2 = *(const ulonglong2*)(sW + (8 + hcl)  * 772 + ko);
        ulonglong2 W3 = *(const ulonglong2*)(sW + (12 + hcl) * 772 + ko);
        ulonglong2 A0 = *(const ulonglong2*)(sA + (rq)      * 772 + ko);
        ulonglong2 A1 = *(const ulonglong2*)(sA + (rq + 8)  * 772 + ko);
        ulonglong2 A2 = *(const ulonglong2*)(sA + (rq + 16) * 772 + ko);
        ulonglong2 A3 = *(const ulonglong2*)(sA + (rq + 24) * 772 + ko);
        acc[0]  = fma2(W0.x, A0.x, acc[0]);  acc[0]  = fma2(W0.y, A0.y, acc[0]);
        acc[1]  = fma2(W0.x, A1.x, acc[1]);  acc[1]  = fma2(W0.y, A1.y, acc[1]);
        acc[2]  = fma2(W0.x, A2.x, acc[2]);  acc[2]  = fma2(W0.y, A2.y, acc[2]);
        acc[3]  = fma2(W0.x, A3.x, acc[3]);  acc[3]  = fma2(W0.y, A3.y, acc[3]);
        acc[4]  = fma2(W1.x, A0.x, acc[4]);  acc[4]  = fma2(W1.y, A0.y, acc[4]);
        acc[5]  = fma2(W1.x, A1.x, acc[5]);  acc[5]  = fma2(W1.y, A1.y, acc[5]);
        acc[6]  = fma2(W1.x, A2.x, acc[6]);  acc[6]  = fma2(W1.y, A2.y, acc[6]);
        acc[7]  = fma2(W1.x, A3.x, acc[7]);  acc[7]  = fma2(W1.y, A3.y, acc[7]);
        acc[8]  = fma2(W2.x, A0.x, acc[8]);  acc[8]  = fma2(W2.y, A0.y, acc[8]);
        acc[9]  = fma2(W2.x, A1.x, acc[9]);  acc[9]  = fma2(W2.y, A1.y, acc[9]);
        acc[10] = fma2(W2.x, A2.x, acc[10]); acc[10] = fma2(W2.y, A2.y, acc[10]);
        acc[11] = fma2(W2.x, A3.x, acc[11]); acc[11] = fma2(W2.y, A3.y, acc[11]);
        acc[12] = fma2(W3.x, A0.x, acc[12]); acc[12] = fma2(W3.y, A0.y, acc[12]);
        acc[13] = fma2(W3.x, A1.x, acc[13]); acc[13] = fma2(W3.y, A1.y, acc[13]);
        acc[14] = fma2(W3.x, A2.x, acc[14]); acc[14] = fma2(W3.y, A2.y, acc[14]);
        acc[15] = fma2(W3.x, A3.x, acc[15]); acc[15] = fma2(W3.y, A3.y, acc[15]);
    }
}

__global__ void __launch_bounds__(512, 1)
lstm2_kernel(const float* __restrict__ Wih, const float* __restrict__ Whh,
             const float* __restrict__ bih, const float* __restrict__ bhh,
             float* __restrict__ dout)
{
    extern __shared__ float sm[];
    float* sW    = sm;
    float* sA    = sm + 12352;
    ull*   sP    = (ull*)(sm + 37056);
    float* sBias = sm + 53696;
    float* sC    = sm + 53712;

    const int tid = threadIdx.x;
    const int bx  = blockIdx.x;
    const int hg = bx >> 1, rowgrp = bx & 1, rows0 = rowgrp * 32;

    for (int i = tid; i < 16 * 768; i += 512) {
        int lr = i / 768, k = i - lr * 768;
        int g = lr >> 2, hc = lr & 3;
        int grow = g * H2 + hg * 4 + hc;
        sW[lr * 772 + k] = (k < H1) ? Wih[grow * H1 + k] : Whh[grow * H2 + (k - H1)];
    }
    if (tid < 16) {
        int g = tid >> 2, hc = tid & 3;
        int grow = g * H2 + hg * 4 + hc;
        sBias[tid] = bih[grow] + bhh[grow];
    }
    if (tid < 128) sC[tid] = 0.f;
    __syncthreads();

    const int hcl = tid & 3;
    const int rq  = (tid >> 2) & 7;
    const int ks  = tid >> 5;
    const int lr_ = tid >> 4;
    const int lc  = tid & 15;
    const int lp  = (lr_ >> 2) + (lr_ & 3) * 8;
    const uint32_t aB = s2u(sA);
    unsigned* ctr = &g_bars[32 + rowgrp * 16];

    // prime: h1[0] loads j=0..7 (2 groups)
#pragma unroll
    for (int j = 0; j < 4; ++j) {
        int k4 = lc + 16 * j;
        cp16(aB + (uint32_t)((lp * 772 + k4 * 4) * 4),
             g_out1 + ((size_t)(rows0 + lr_) * TT + 0) * H1 + k4 * 4);
    }
    cpcommit();
#pragma unroll
    for (int j = 4; j < 8; ++j) {
        int k4 = lc + 16 * j;
        cp16(aB + (uint32_t)((lp * 772 + k4 * 4) * 4),
             g_out1 + ((size_t)(rows0 + lr_) * TT + 0) * H1 + k4 * 4);
    }
    cpcommit();

    for (int t = 0; t < TT; ++t) {
        ull acc[16];
#pragma unroll
        for (int i = 0; i < 16; ++i) acc[i] = 0;

        // ---- non-recurrent part: h1[t] (loads issued last iteration) ----
        cpwait<1>(); __syncthreads();
        compute2_q(sW, sA, hcl, rq, ks, 0, acc);
        compute2_q(sW, sA, hcl, rq, ks, 1, acc);
        cpwait<0>(); __syncthreads();
        compute2_q(sW, sA, hcl, rq, ks, 2, acc);
        compute2_q(sW, sA, hcl, rq, ks, 3, acc);

        // ---- recurrent part: h2[t-1] ----
        if (t > 0) {
            if (tid == 0) {
                unsigned tgt = 64u * (unsigned)t;
                while (ldvol(ctr) < tgt) { __nanosleep(32); }
            }
            __syncthreads();
#pragma unroll
            for (int j = 8; j < 12; ++j) {
                int k4 = lc + 16 * j;
                cp16(aB + (uint32_t)((lp * 772 + k4 * 4) * 4),
                     g_out2 + ((size_t)(rows0 + lr_) * TT + (t - 1)) * H2 + (k4 * 4 - 512));
            }
            cpcommit();
            cpwait<0>(); __syncthreads();
            compute2_q(sW, sA, hcl, rq, ks, 4, acc);
            compute2_q(sW, sA, hcl, rq, ks, 5, acc);
        }

        // ---- partial store ----
#pragma unroll
        for (int g = 0; g < 4; ++g) {
#pragma unroll
            for (int r = 0; r < 4; ++r) {
                int cell = (rq * 4 + r) * 4 + hcl;
                int col = g * 16 + ((ks + rq) & 15);
                sP[cell * 65 + col] = acc[g * 4 + r];
            }
        }
        __syncthreads();

        // ---- issue next step's h1 loads (overlaps reduce) ----
        if (t + 1 < TT) {
#pragma unroll
            for (int j = 0; j < 4; ++j) {
                int k4 = lc + 16 * j;
                cp16(aB + (uint32_t)((lp * 772 + k4 * 4) * 4),
                     g_out1 + ((size_t)(rows0 + lr_) * TT + (t + 1)) * H1 + k4 * 4);
            }
            cpcommit();
#pragma unroll
            for (int j = 4; j < 8; ++j) {
                int k4 = lc + 16 * j;
                cp16(aB + (uint32_t)((lp * 772 + k4 * 4) * 4),
                     g_out1 + ((size_t)(rows0 + lr_) * TT + (t + 1)) * H1 + k4 * 4);
            }
            cpcommit();
        } else {
            // keep group count consistent for final iteration (no-op groups)
            cpcommit(); cpcommit();
        }

        // ---- reduce + nonlinearity ----
        if (tid < 128) {
            int n = tid >> 2, hc = tid & 3;
            const ull* pp = sP + tid * 65;
            float gate[4];
#pragma unroll
            for (int g = 0; g < 4; ++g) {
                ull s = pp[g * 16];
#pragma unroll
                for (int j = 1; j < 16; ++j) s = add2(s, pp[g * 16 + j]);
                gate[g] = psum(s) + sBias[g * 4 + hc];
            }
            float cp = sC[tid];
            float cn = sigf(gate[1]) * cp + sigf(gate[0]) * tanhf(gate[2]);
            sC[tid] = cn;
            float h = sigf(gate[3]) * tanhf(cn);
            int ng = rows0 + n;
            int hcg = hg * 4 + hc;
            g_out2[((size_t)ng * TT + t) * H2 + hcg] = h;
            if (t == TT - 1) {
                dout[131072 + ng * H2 + hcg] = h;
                dout[147456 + ng * H2 + hcg] = cn;
            }
        }

        if (t < TT - 1) {
            __threadfence();
            __syncthreads();
            if (tid == 0) atomicAdd(ctr, 1u);
        }
    }
}

// ============================ causal attention (tiled) ============================
__global__ void __launch_bounds__(256)
attn_kernel()
{
    __shared__ float sK[32 * 256];
    const int tid = threadIdx.x;
    const int lane = tid & 31, warp = tid >> 5;
    const int qb = blockIdx.x, n = blockIdx.y;
    const int q0 = qb * 16 + warp * 2, q1 = q0 + 1;
    const float* bp = g_out2 + (size_t)n * TT * H2;

    const float4* qp0 = (const float4*)(bp + (size_t)q0 * H2) + lane * 2;
    const float4* qp1 = (const float4*)(bp + (size_t)q1 * H2) + lane * 2;
    float4 q0a = qp0[0], q0b = qp0[1];
    float4 q1a = qp1[0], q1b = qp1[1];

    float m0 = -1e30f, l0 = 0.f, m1 = -1e30f, l1 = 0.f;
    float4 a0a = {0,0,0,0}, a0b = {0,0,0,0}, a1a = {0,0,0,0}, a1b = {0,0,0,0};

    const int ntiles = (qb * 16 + 16 + 31) >> 5;
    const uint32_t kB = s2u(sK);

    for (int tile = 0; tile < ntiles; ++tile) {
        const int s0 = tile * 32;
        __syncthreads();
#pragma unroll
        for (int jj = 0; jj < 8; ++jj) {
            int flat = jj * 256 + tid;
            int key = flat >> 6, off = flat & 63;
            cp16(kB + (uint32_t)flat * 16, bp + (size_t)(s0 + key) * H2 + off * 4);
        }
        cpcommit();
        cpwait<0>();
        __syncthreads();

        int kmax = q1 - s0 + 1;
        if (kmax > 32) kmax = 32;
        for (int kk = 0; kk < kmax; ++kk) {
            const float4* kp = (const float4*)(sK + kk * 256) + lane * 2;
            float4 ka = kp[0], kb4 = kp[1];
            float p0 = q0a.x*ka.x + q0a.y*ka.y + q0a.z*ka.z + q0a.w*ka.w
                     + q0b.x*kb4.x + q0b.y*kb4.y + q0b.z*kb4.z + q0b.w*kb4.w;
            float p1 = q1a.x*ka.x + q1a.y*ka.y + q1a.z*ka.z + q1a.w*ka.w
                     + q1b.x*kb4.x + q1b.y*kb4.y + q1b.z*kb4.z + q1b.w*kb4.w;
            p0 += __shfl_xor_sync(0xffffffffu, p0, 16);
            p1 += __shfl_xor_sync(0xffffffffu, p1, 16);
            p0 += __shfl_xor_sync(0xffffffffu, p0, 8);
            p1 += __shfl_xor_sync(0xffffffffu, p1, 8);
            p0 += __shfl_xor_sync(0xffffffffu, p0, 4);
            p1 += __shfl_xor_sync(0xffffffffu, p1, 4);
            p0 += __shfl_xor_sync(0xffffffffu, p0, 2);
            p1 += __shfl_xor_sync(0xffffffffu, p1, 2);
            p0 += __shfl_xor_sync(0xffffffffu, p0, 1);
            p1 += __shfl_xor_sync(0xffffffffu, p1, 1);
            int keyg = s0 + kk;
            {
                float nm = fmaxf(m1, p1);
                float e  = __expf(p1 - nm);
                float sc = __expf(m1 - nm);
                l1 = l1 * sc + e; m1 = nm;
                a1a.x = a1a.x*sc + e*ka.x;  a1a.y = a1a.y*sc + e*ka.y;
                a1a.z = a1a.z*sc + e*ka.z;  a1a.w = a1a.w*sc + e*ka.w;
                a1b.x = a1b.x*sc + e*kb4.x; a1b.y = a1b.y*sc + e*kb4.y;
                a1b.z = a1b.z*sc + e*kb4.z; a1b.w = a1b.w*sc + e*kb4.w;
            }
            if (keyg <= q0) {
                float nm = fmaxf(m0, p0);
                float e  = __expf(p0 - nm);
                float sc = __expf(m0 - nm);
                l0 = l0 * sc + e; m0 = nm;
                a0a.x = a0a.x*sc + e*ka.x;  a0a.y = a0a.y*sc + e*ka.y;
                a0a.z = a0a.z*sc + e*ka.z;  a0a.w = a0a.w*sc + e*ka.w;
                a0b.x = a0b.x*sc + e*kb4.x; a0b.y = a0b.y*sc + e*kb4.y;
                a0b.z = a0b.z*sc + e*kb4.z; a0b.w = a0b.w*sc + e*kb4.w;
            }
        }
    }

    float i0 = 1.f / l0, i1 = 1.f / l1;
    float4* o0 = (float4*)(g_ctx + ((size_t)n * TT + q0) * H2) + lane * 2;
    float4* o1 = (float4*)(g_ctx + ((size_t)n * TT + q1) * H2) + lane * 2;
    o0[0] = make_float4(a0a.x*i0, a0a.y*i0, a0a.z*i0, a0a.w*i0);
    o0[1] = make_float4(a0b.x*i0, a0b.y*i0, a0b.z*i0, a0b.w*i0);
    o1[0] = make_float4(a1a.x*i1, a1a.y*i1, a1a.z*i1, a1a.w*i1);
    o1[1] = make_float4(a1b.x*i1, a1b.y*i1, a1b.z*i1, a1b.w*i1);
}

// ============================ MLP head ============================
__global__ void __launch_bounds__(128)
mlp_kernel(const float* __restrict__ fc1b,
           const float* __restrict__ fc2b,
           const float* __restrict__ fc3w, const float* __restrict__ fc3b,
           float* __restrict__ dout)
{
    __shared__ float sIn[16][512];
    __shared__ float sH1b[16][128];
    __shared__ float sH2b[16][52];
    const int tid = threadIdx.x;

    for (int tile = blockIdx.x; tile < (NB * TT) / 16; tile += gridDim.x) {
        const int row0 = tile * 16;
        for (int i = tid; i < 16 * 512; i += 128) {
            int r = i >> 9, c = i & 511;
            size_t row = (size_t)(row0 + r);
            sIn[r][c] = (c < 256) ? g_ctx[row * 256 + c] : g_out2[row * 256 + (c - 256)];
        }
        __syncthreads();

        {
            float acc[16];
            float b = fc1b[tid];
#pragma unroll
            for (int r = 0; r < 16; ++r) acc[r] = b;
            for (int k = 0; k < 512; ++k) {
                float w = g_fc1T[k * 128 + tid];
#pragma unroll
                for (int r = 0; r < 16; ++r) acc[r] = fmaf(w, sIn[r][k], acc[r]);
            }
#pragma unroll
            for (int r = 0; r < 16; ++r) sH1b[r][tid] = fmaxf(acc[r], 0.f);
        }
        __syncthreads();

        if (tid < 51) {
            float acc[16];
            float b = fc2b[tid];
#pragma unroll
            for (int r = 0; r < 16; ++r) acc[r] = b;
            for (int k = 0; k < 128; ++k) {
                float w = g_fc2T[k * 51 + tid];
#pragma unroll
                for (int r = 0; r < 16; ++r) acc[r] = fmaf(w, sH1b[r][k], acc[r]);
            }
#pragma unroll
            for (int r = 0; r < 16; ++r) sH2b[r][tid] = fmaxf(acc[r], 0.f);
        }
        __syncthreads();

        if (tid < 16) {
            float s = fc3b[0];
            for (int k = 0; k < 51; ++k) s = fmaf(fc3w[k], sH2b[tid][k], s);
            dout[row0 + tid] = s;
        }
        __syncthreads();
    }
}

// ============================ launch ============================
extern "C" void kernel_launch(void* const* d_in, const int* in_sizes, int n_in,
                              void* d_out, int out_size)
{
    const float* x     = (const float*)d_in[0];
    const float* Wih1  = (const float*)d_in[1];
    const float* Whh1  = (const float*)d_in[2];
    const float* bih1  = (const float*)d_in[3];
    const float* bhh1  = (const float*)d_in[4];
    const float* Wih2  = (const float*)d_in[5];
    const float* Whh2  = (const float*)d_in[6];
    const float* bih2  = (const float*)d_in[7];
    const float* bhh2  = (const float*)d_in[8];
    const float* fc1w  = (const float*)d_in[9];
    const float* fc1b  = (const float*)d_in[10];
    const float* fc2w  = (const float*)d_in[11];
    const float* fc2b  = (const float*)d_in[12];
    const float* fc3w  = (const float*)d_in[13];
    const float* fc3b  = (const float*)d_in[14];
    float* out = (float*)d_out;

    const int SM1 = 54304 * 4;
    const int SM2 = 53840 * 4;
    cudaFuncSetAttribute(lstm1_kernel, cudaFuncAttributeMaxDynamicSharedMemorySize, SM1);
    cudaFuncSetAttribute(lstm2_kernel, cudaFuncAttributeMaxDynamicSharedMemorySize, SM2);

    reset_kernel<<<1, 64>>>();
    prep_kernel<<<(128 * 512 + 255) / 256, 256>>>(fc1w, fc2w);
    lstm1_kernel<<<128, 512, SM1>>>(x, Wih1, Whh1, bih1, bhh1, out);
    lstm2_kernel<<<128, 512, SM2>>>(Wih2, Whh2, bih2, bhh2, out);
    {
        dim3 grid(64, 64);
        attn_kernel<<<grid, 256>>>();
    }
    mlp_kernel<<<1024, 128>>>(fc1b, fc2b, fc3w, fc3b, out);
}

// round 12
// speedup vs baseline: 1.7461x; 1.0006x over previous
#include <cuda_runtime.h>
#include <math.h>
#include <stdint.h>

typedef unsigned long long ull;

#define NB   64
#define TT   1024
#define INW  64
#define H1   512
#define H2   256

// ---------------- scratch (static device globals; no allocation) ----------------
__device__ float g_out1[(size_t)NB * TT * H1];
__device__ float g_out2[(size_t)NB * TT * H2];
__device__ float g_ctx [(size_t)NB * TT * H2];
__device__ float g_fc1T[512 * 128];
__device__ float g_fc2T[128 * 51];
__device__ unsigned g_bars[64];

__global__ void reset_kernel() {
    if (threadIdx.x < 64) g_bars[threadIdx.x] = 0u;
}

__global__ void prep_kernel(const float* __restrict__ fc1w, const float* __restrict__ fc2w) {
    int i = blockIdx.x * blockDim.x + threadIdx.x;
    if (i < 128 * 512) { int j = i / 512, k = i % 512; g_fc1T[k * 128 + j] = fc1w[i]; }
    if (i < 51 * 128)  { int j = i / 128, k = i % 128; g_fc2T[k * 51 + j] = fc2w[i]; }
}

// ---------------- helpers ----------------
__device__ __forceinline__ float sigf(float x) { return 1.f / (1.f + __expf(-x)); }
__device__ __forceinline__ float tanhfast(float x) {
    float e = __expf(-2.f * x);
    return (1.f - e) / (1.f + e);
}

__device__ __forceinline__ uint32_t s2u(const void* p) {
    uint32_t a;
    asm("{ .reg .u64 t; cvta.to.shared.u64 t, %1; cvt.u32.u64 %0, t; }" : "=r"(a) : "l"(p));
    return a;
}
__device__ __forceinline__ void cp16(uint32_t dst, const void* src) {
    asm volatile("cp.async.cg.shared.global [%0], [%1], 16;" :: "r"(dst), "l"(src));
}
__device__ __forceinline__ void cpcommit() {
    asm volatile("cp.async.commit_group;" ::: "memory");
}
template <int N>
__device__ __forceinline__ void cpwait() {
    asm volatile("cp.async.wait_group %0;" :: "n"(N) : "memory");
}
__device__ __forceinline__ ull fma2(ull a, ull b, ull c) {
    ull d;
    asm("fma.rn.f32x2 %0, %1, %2, %3;" : "=l"(d) : "l"(a), "l"(b), "l"(c));
    return d;
}
__device__ __forceinline__ ull add2(ull a, ull b) {
    ull d;
    asm("add.rn.f32x2 %0, %1, %2;" : "=l"(d) : "l"(a), "l"(b));
    return d;
}
__device__ __forceinline__ float psum(ull a) {
    return __int_as_float((int)(a & 0xffffffffULL)) + __int_as_float((int)(a >> 32));
}
__device__ __forceinline__ unsigned ldvol(const unsigned* p) {
    unsigned v;
    asm volatile("ld.volatile.global.u32 %0, [%1];" : "=r"(v) : "l"(p));
    return v;
}

// ---------------- pipelined tile compute ----------------
// 32 FFMA2 on a 4x4 tile of packed-f32x2 operands.
__device__ __forceinline__ void fma16(const ulonglong2* W, const ulonglong2* A, ull* acc) {
    acc[0]  = fma2(W[0].x, A[0].x, acc[0]);  acc[0]  = fma2(W[0].y, A[0].y, acc[0]);
    acc[1]  = fma2(W[0].x, A[1].x, acc[1]);  acc[1]  = fma2(W[0].y, A[1].y, acc[1]);
    acc[2]  = fma2(W[0].x, A[2].x, acc[2]);  acc[2]  = fma2(W[0].y, A[2].y, acc[2]);
    acc[3]  = fma2(W[0].x, A[3].x, acc[3]);  acc[3]  = fma2(W[0].y, A[3].y, acc[3]);
    acc[4]  = fma2(W[1].x, A[0].x, acc[4]);  acc[4]  = fma2(W[1].y, A[0].y, acc[4]);
    acc[5]  = fma2(W[1].x, A[1].x, acc[5]);  acc[5]  = fma2(W[1].y, A[1].y, acc[5]);
    acc[6]  = fma2(W[1].x, A[2].x, acc[6]);  acc[6]  = fma2(W[1].y, A[2].y, acc[6]);
    acc[7]  = fma2(W[1].x, A[3].x, acc[7]);  acc[7]  = fma2(W[1].y, A[3].y, acc[7]);
    acc[8]  = fma2(W[2].x, A[0].x, acc[8]);  acc[8]  = fma2(W[2].y, A[0].y, acc[8]);
    acc[9]  = fma2(W[2].x, A[1].x, acc[9]);  acc[9]  = fma2(W[2].y, A[1].y, acc[9]);
    acc[10] = fma2(W[2].x, A[2].x, acc[10]); acc[10] = fma2(W[2].y, A[2].y, acc[10]);
    acc[11] = fma2(W[2].x, A[3].x, acc[11]); acc[11] = fma2(W[2].y, A[3].y, acc[11]);
    acc[12] = fma2(W[3].x, A[0].x, acc[12]); acc[12] = fma2(W[3].y, A[0].y, acc[12]);
    acc[13] = fma2(W[3].x, A[1].x, acc[13]); acc[13] = fma2(W[3].y, A[1].y, acc[13]);
    acc[14] = fma2(W[3].x, A[2].x, acc[14]); acc[14] = fma2(W[3].y, A[2].y, acc[14]);
    acc[15] = fma2(W[3].x, A[3].x, acc[15]); acc[15] = fma2(W[3].y, A[3].y, acc[15]);
}

// lstm1 operand fetch: W rows stride 8*580, A rows stride 8*580.
__device__ __forceinline__ void ld8_1(const float* sWb, const float* sAb, int off,
                                      ulonglong2* W, ulonglong2* A) {
    W[0] = *(const ulonglong2*)(sWb + off);
    W[1] = *(const ulonglong2*)(sWb + 8 * 580 + off);
    W[2] = *(const ulonglong2*)(sWb + 16 * 580 + off);
    W[3] = *(const ulonglong2*)(sWb + 24 * 580 + off);
    A[0] = *(const ulonglong2*)(sAb + off);
    A[1] = *(const ulonglong2*)(sAb + 8 * 580 + off);
    A[2] = *(const ulonglong2*)(sAb + 16 * 580 + off);
    A[3] = *(const ulonglong2*)(sAb + 24 * 580 + off);
}

template<int NU>
__device__ __forceinline__ void pipe1(const float* sWb, const float* sAb,
                                      const int* offs, ull* acc) {
    ulonglong2 W[2][4], A[2][4];
    ld8_1(sWb, sAb, offs[0], W[0], A[0]);
#pragma unroll
    for (int i = 0; i < NU; ++i) {
        if (i + 1 < NU) ld8_1(sWb, sAb, offs[i + 1], W[(i + 1) & 1], A[(i + 1) & 1]);
        fma16(W[i & 1], A[i & 1], acc);
    }
}

// lstm2 operand fetch: W rows stride 4*772, A rows stride 8*772.
__device__ __forceinline__ void ld8_2(const float* sWb, const float* sAb, int off,
                                      ulonglong2* W, ulonglong2* A) {
    W[0] = *(const ulonglong2*)(sWb + off);
    W[1] = *(const ulonglong2*)(sWb + 4 * 772 + off);
    W[2] = *(const ulonglong2*)(sWb + 8 * 772 + off);
    W[3] = *(const ulonglong2*)(sWb + 12 * 772 + off);
    A[0] = *(const ulonglong2*)(sAb + off);
    A[1] = *(const ulonglong2*)(sAb + 8 * 772 + off);
    A[2] = *(const ulonglong2*)(sAb + 16 * 772 + off);
    A[3] = *(const ulonglong2*)(sAb + 24 * 772 + off);
}

template<int NU>
__device__ __forceinline__ void pipe2(const float* sWb, const float* sAb,
                                      const int* offs, ull* acc) {
    ulonglong2 W[2][4], A[2][4];
    ld8_2(sWb, sAb, offs[0], W[0], A[0]);
#pragma unroll
    for (int i = 0; i < NU; ++i) {
        if (i + 1 < NU) ld8_2(sWb, sAb, offs[i + 1], W[(i + 1) & 1], A[(i + 1) & 1]);
        fma16(W[i & 1], A[i & 1], acc);
    }
}

// ============================ LSTM layer 1 ============================
// 128 CTAs x 512 thr. CTA bx: hg=bx>>1 (8 hidden cols), rowgrp=bx&1 (32 rows). K=576.
// Thread tile: hcl=tid&7, rq=(tid>>3)&7, ks=tid>>6; 4 gates x 4 rows, K-sliced by ks.
__global__ void __launch_bounds__(512, 1)
lstm1_kernel(const float* __restrict__ x,
             const float* __restrict__ Wih, const float* __restrict__ Whh,
             const float* __restrict__ bih, const float* __restrict__ bhh,
             float* __restrict__ dout)
{
    extern __shared__ float sm[];
    float* sW    = sm;
    float* sA    = sm + 18560;
    ull*   sP    = (ull*)(sm + 37120);
    float* sBias = sm + 54016;
    float* sC    = sm + 54048;

    const int tid = threadIdx.x;
    const int bx  = blockIdx.x;
    const int hg = bx >> 1, rowgrp = bx & 1, rows0 = rowgrp * 32;

    for (int i = tid; i < 32 * 576; i += 512) {
        int lr = i / 576, k = i - lr * 576;
        int g = lr >> 3, hc = lr & 7;
        int grow = g * H1 + hg * 8 + hc;
        sW[lr * 580 + k] = (k < INW) ? Wih[grow * INW + k] : Whh[grow * H1 + (k - INW)];
    }
    if (tid < 32) {
        int g = tid >> 3, hc = tid & 7;
        int grow = g * H1 + hg * 8 + hc;
        sBias[tid] = bih[grow] + bhh[grow];
    }
    if (tid < 256) sC[tid] = 0.f;
    __syncthreads();

    const int hcl = tid & 7;
    const int rq  = (tid >> 3) & 7;
    const int ks  = tid >> 6;
    const int lr_ = tid >> 4;
    const int lc  = tid & 15;
    const int lp  = (lr_ >> 2) + (lr_ & 3) * 8;
    const uint32_t aB = s2u(sA);
    unsigned* ctr = &g_bars[rowgrp * 16];

    const float* sWb = sW + hcl * 580 + ks * 8;
    const float* sAb = sA + rq * 580 + ks * 8;
    const int offsA[2] = {0, 4};
    const int offsB[8] = {64, 68, 128, 132, 192, 196, 256, 260};
    const int offsC[8] = {320, 324, 384, 388, 448, 452, 512, 516};

    // prime: x loads for t=0
    cp16(aB + (uint32_t)((lp * 580 + lc * 4) * 4),
         x + ((size_t)(rows0 + lr_) * TT + 0) * INW + lc * 4);
    cpcommit();

    for (int t = 0; t < TT; ++t) {
        ull acc[16];
#pragma unroll
        for (int i = 0; i < 16; ++i) acc[i] = 0;

        // ---- non-recurrent: x chunk ----
        cpwait<0>(); __syncthreads();
        pipe1<2>(sWb, sAb, offsA, acc);

        // ---- recurrent part ----
        if (t > 0) {
            if (tid == 0) {
                unsigned tgt = 64u * (unsigned)t;
                while (ldvol(ctr) < tgt) { __nanosleep(32); }
            }
            __syncthreads();
#pragma unroll
            for (int j = 1; j <= 4; ++j) {
                int k4 = lc + 16 * j;
                cp16(aB + (uint32_t)((lp * 580 + k4 * 4) * 4),
                     g_out1 + ((size_t)(rows0 + lr_) * TT + (t - 1)) * H1 + (k4 * 4 - 64));
            }
            cpcommit();
#pragma unroll
            for (int j = 5; j <= 8; ++j) {
                int k4 = lc + 16 * j;
                cp16(aB + (uint32_t)((lp * 580 + k4 * 4) * 4),
                     g_out1 + ((size_t)(rows0 + lr_) * TT + (t - 1)) * H1 + (k4 * 4 - 64));
            }
            cpcommit();

            cpwait<1>(); __syncthreads();
            pipe1<8>(sWb, sAb, offsB, acc);
            cpwait<0>(); __syncthreads();
            pipe1<8>(sWb, sAb, offsC, acc);
        }

        // ---- partial store ----
#pragma unroll
        for (int g = 0; g < 4; ++g) {
#pragma unroll
            for (int r = 0; r < 4; ++r) {
                int cell = (rq * 4 + r) * 8 + hcl;
                int col = g * 8 + ((ks + rq) & 7);
                sP[cell * 33 + col] = acc[g * 4 + r];
            }
        }
        __syncthreads();

        // ---- next step's x loads (overlap reduce) ----
        if (t + 1 < TT) {
            cp16(aB + (uint32_t)((lp * 580 + lc * 4) * 4),
                 x + ((size_t)(rows0 + lr_) * TT + (t + 1)) * INW + lc * 4);
            cpcommit();
        }

        // ---- reduce + nonlinearity ----
        if (tid < 256) {
            int n = tid >> 3, hc = tid & 7;
            const ull* pp = sP + tid * 33;
            float gate[4];
#pragma unroll
            for (int g = 0; g < 4; ++g) {
                ull s0 = add2(pp[g * 8 + 0], pp[g * 8 + 1]);
                ull s1 = add2(pp[g * 8 + 2], pp[g * 8 + 3]);
                ull s2 = add2(pp[g * 8 + 4], pp[g * 8 + 5]);
                ull s3 = add2(pp[g * 8 + 6], pp[g * 8 + 7]);
                ull s = add2(add2(s0, s1), add2(s2, s3));
                gate[g] = psum(s) + sBias[g * 8 + hc];
            }
            float cp = sC[tid];
            float cn = sigf(gate[1]) * cp + sigf(gate[0]) * tanhfast(gate[2]);
            sC[tid] = cn;
            float h = sigf(gate[3]) * tanhfast(cn);
            int ng = rows0 + n;
            int hcg = hg * 8 + hc;
            g_out1[((size_t)ng * TT + t) * H1 + hcg] = h;
            if (t == TT - 1) {
                dout[65536 + ng * H1 + hcg] = h;
                dout[98304 + ng * H1 + hcg] = cn;
            }
        }

        if (t < TT - 1) {
            __threadfence();
            __syncthreads();
            if (tid == 0) atomicAdd(ctr, 1u);
        }
    }
}

// ============================ LSTM layer 2 ============================
// 128 CTAs x 512 thr. hg=bx>>1 (4 hidden cols), rowgrp (32 rows). K=768.
// Thread: hcl=tid&3, rq=(tid>>2)&7, ks=tid>>5 (0..15).
__global__ void __launch_bounds__(512, 1)
lstm2_kernel(const float* __restrict__ Wih, const float* __restrict__ Whh,
             const float* __restrict__ bih, const float* __restrict__ bhh,
             float* __restrict__ dout)
{
    extern __shared__ float sm[];
    float* sW    = sm;
    float* sA    = sm + 12352;
    ull*   sP    = (ull*)(sm + 37056);
    float* sBias = sm + 53696;
    float* sC    = sm + 53712;

    const int tid = threadIdx.x;
    const int bx  = blockIdx.x;
    const int hg = bx >> 1, rowgrp = bx & 1, rows0 = rowgrp * 32;

    for (int i = tid; i < 16 * 768; i += 512) {
        int lr = i / 768, k = i - lr * 768;
        int g = lr >> 2, hc = lr & 3;
        int grow = g * H2 + hg * 4 + hc;
        sW[lr * 772 + k] = (k < H1) ? Wih[grow * H1 + k] : Whh[grow * H2 + (k - H1)];
    }
    if (tid < 16) {
        int g = tid >> 2, hc = tid & 3;
        int grow = g * H2 + hg * 4 + hc;
        sBias[tid] = bih[grow] + bhh[grow];
    }
    if (tid < 128) sC[tid] = 0.f;
    __syncthreads();

    const int hcl = tid & 3;
    const int rq  = (tid >> 2) & 7;
    const int ks  = tid >> 5;
    const int lr_ = tid >> 4;
    const int lc  = tid & 15;
    const int lp  = (lr_ >> 2) + (lr_ & 3) * 8;
    const uint32_t aB = s2u(sA);
    unsigned* ctr = &g_bars[32 + rowgrp * 16];

    const float* sWb = sW + hcl * 772 + ks * 8;
    const float* sAb = sA + rq * 772 + ks * 8;
    const int offsA[4] = {0, 4, 128, 132};
    const int offsB[4] = {256, 260, 384, 388};
    const int offsC[4] = {512, 516, 640, 644};

    // prime: h1[0] loads (2 groups)
#pragma unroll
    for (int j = 0; j < 4; ++j) {
        int k4 = lc + 16 * j;
        cp16(aB + (uint32_t)((lp * 772 + k4 * 4) * 4),
             g_out1 + ((size_t)(rows0 + lr_) * TT + 0) * H1 + k4 * 4);
    }
    cpcommit();
#pragma unroll
    for (int j = 4; j < 8; ++j) {
        int k4 = lc + 16 * j;
        cp16(aB + (uint32_t)((lp * 772 + k4 * 4) * 4),
             g_out1 + ((size_t)(rows0 + lr_) * TT + 0) * H1 + k4 * 4);
    }
    cpcommit();

    for (int t = 0; t < TT; ++t) {
        ull acc[16];
#pragma unroll
        for (int i = 0; i < 16; ++i) acc[i] = 0;

        // ---- non-recurrent: h1[t] ----
        cpwait<1>(); __syncthreads();
        pipe2<4>(sWb, sAb, offsA, acc);
        cpwait<0>(); __syncthreads();
        pipe2<4>(sWb, sAb, offsB, acc);

        // ---- recurrent: h2[t-1] ----
        if (t > 0) {
            if (tid == 0) {
                unsigned tgt = 64u * (unsigned)t;
                while (ldvol(ctr) < tgt) { __nanosleep(32); }
            }
            __syncthreads();
#pragma unroll
            for (int j = 8; j < 12; ++j) {
                int k4 = lc + 16 * j;
                cp16(aB + (uint32_t)((lp * 772 + k4 * 4) * 4),
                     g_out2 + ((size_t)(rows0 + lr_) * TT + (t - 1)) * H2 + (k4 * 4 - 512));
            }
            cpcommit();
            cpwait<0>(); __syncthreads();
            pipe2<4>(sWb, sAb, offsC, acc);
        }

        // ---- partial store ----
#pragma unroll
        for (int g = 0; g < 4; ++g) {
#pragma unroll
            for (int r = 0; r < 4; ++r) {
                int cell = (rq * 4 + r) * 4 + hcl;
                int col = g * 16 + ((ks + rq) & 15);
                sP[cell * 65 + col] = acc[g * 4 + r];
            }
        }
        __syncthreads();

        // ---- next step's h1 loads (overlap reduce) ----
        if (t + 1 < TT) {
#pragma unroll
            for (int j = 0; j < 4; ++j) {
                int k4 = lc + 16 * j;
                cp16(aB + (uint32_t)((lp * 772 + k4 * 4) * 4),
                     g_out1 + ((size_t)(rows0 + lr_) * TT + (t + 1)) * H1 + k4 * 4);
            }
            cpcommit();
#pragma unroll
            for (int j = 4; j < 8; ++j) {
                int k4 = lc + 16 * j;
                cp16(aB + (uint32_t)((lp * 772 + k4 * 4) * 4),
                     g_out1 + ((size_t)(rows0 + lr_) * TT + (t + 1)) * H1 + k4 * 4);
            }
            cpcommit();
        } else {
            cpcommit(); cpcommit();
        }

        // ---- reduce + nonlinearity ----
        if (tid < 128) {
            int n = tid >> 2, hc = tid & 3;
            const ull* pp = sP + tid * 65;
            float gate[4];
#pragma unroll
            for (int g = 0; g < 4; ++g) {
                ull s = pp[g * 16];
#pragma unroll
                for (int j = 1; j < 16; ++j) s = add2(s, pp[g * 16 + j]);
                gate[g] = psum(s) + sBias[g * 4 + hc];
            }
            float cp = sC[tid];
            float cn = sigf(gate[1]) * cp + sigf(gate[0]) * tanhfast(gate[2]);
            sC[tid] = cn;
            float h = sigf(gate[3]) * tanhfast(cn);
            int ng = rows0 + n;
            int hcg = hg * 4 + hc;
            g_out2[((size_t)ng * TT + t) * H2 + hcg] = h;
            if (t == TT - 1) {
                dout[131072 + ng * H2 + hcg] = h;
                dout[147456 + ng * H2 + hcg] = cn;
            }
        }

        if (t < TT - 1) {
            __threadfence();
            __syncthreads();
            if (tid == 0) atomicAdd(ctr, 1u);
        }
    }
}

// ============================ causal attention (tiled) ============================
__global__ void __launch_bounds__(256)
attn_kernel()
{
    __shared__ float sK[32 * 256];
    const int tid = threadIdx.x;
    const int lane = tid & 31, warp = tid >> 5;
    const int qb = blockIdx.x, n = blockIdx.y;
    const int q0 = qb * 16 + warp * 2, q1 = q0 + 1;
    const float* bp = g_out2 + (size_t)n * TT * H2;

    const float4* qp0 = (const float4*)(bp + (size_t)q0 * H2) + lane * 2;
    const float4* qp1 = (const float4*)(bp + (size_t)q1 * H2) + lane * 2;
    float4 q0a = qp0[0], q0b = qp0[1];
    float4 q1a = qp1[0], q1b = qp1[1];

    float m0 = -1e30f, l0 = 0.f, m1 = -1e30f, l1 = 0.f;
    float4 a0a = {0,0,0,0}, a0b = {0,0,0,0}, a1a = {0,0,0,0}, a1b = {0,0,0,0};

    const int ntiles = (qb * 16 + 16 + 31) >> 5;
    const uint32_t kB = s2u(sK);

    for (int tile = 0; tile < ntiles; ++tile) {
        const int s0 = tile * 32;
        __syncthreads();
#pragma unroll
        for (int jj = 0; jj < 8; ++jj) {
            int flat = jj * 256 + tid;
            int key = flat >> 6, off = flat & 63;
            cp16(kB + (uint32_t)flat * 16, bp + (size_t)(s0 + key) * H2 + off * 4);
        }
        cpcommit();
        cpwait<0>();
        __syncthreads();

        int kmax = q1 - s0 + 1;
        if (kmax > 32) kmax = 32;
        for (int kk = 0; kk < kmax; ++kk) {
            const float4* kp = (const float4*)(sK + kk * 256) + lane * 2;
            float4 ka = kp[0], kb4 = kp[1];
            float p0 = q0a.x*ka.x + q0a.y*ka.y + q0a.z*ka.z + q0a.w*ka.w
                     + q0b.x*kb4.x + q0b.y*kb4.y + q0b.z*kb4.z + q0b.w*kb4.w;
            float p1 = q1a.x*ka.x + q1a.y*ka.y + q1a.z*ka.z + q1a.w*ka.w
                     + q1b.x*kb4.x + q1b.y*kb4.y + q1b.z*kb4.z + q1b.w*kb4.w;
            p0 += __shfl_xor_sync(0xffffffffu, p0, 16);
            p1 += __shfl_xor_sync(0xffffffffu, p1, 16);
            p0 += __shfl_xor_sync(0xffffffffu, p0, 8);
            p1 += __shfl_xor_sync(0xffffffffu, p1, 8);
            p0 += __shfl_xor_sync(0xffffffffu, p0, 4);
            p1 += __shfl_xor_sync(0xffffffffu, p1, 4);
            p0 += __shfl_xor_sync(0xffffffffu, p0, 2);
            p1 += __shfl_xor_sync(0xffffffffu, p1, 2);
            p0 += __shfl_xor_sync(0xffffffffu, p0, 1);
            p1 += __shfl_xor_sync(0xffffffffu, p1, 1);
            int keyg = s0 + kk;
            {
                float nm = fmaxf(m1, p1);
                float e  = __expf(p1 - nm);
                float sc = __expf(m1 - nm);
                l1 = l1 * sc + e; m1 = nm;
                a1a.x = a1a.x*sc + e*ka.x;  a1a.y = a1a.y*sc + e*ka.y;
                a1a.z = a1a.z*sc + e*ka.z;  a1a.w = a1a.w*sc + e*ka.w;
                a1b.x = a1b.x*sc + e*kb4.x; a1b.y = a1b.y*sc + e*kb4.y;
                a1b.z = a1b.z*sc + e*kb4.z; a1b.w = a1b.w*sc + e*kb4.w;
            }
            if (keyg <= q0) {
                float nm = fmaxf(m0, p0);
                float e  = __expf(p0 - nm);
                float sc = __expf(m0 - nm);
                l0 = l0 * sc + e; m0 = nm;
                a0a.x = a0a.x*sc + e*ka.x;  a0a.y = a0a.y*sc + e*ka.y;
                a0a.z = a0a.z*sc + e*ka.z;  a0a.w = a0a.w*sc + e*ka.w;
                a0b.x = a0b.x*sc + e*kb4.x; a0b.y = a0b.y*sc + e*kb4.y;
                a0b.z = a0b.z*sc + e*kb4.z; a0b.w = a0b.w*sc + e*kb4.w;
            }
        }
    }

    float i0 = 1.f / l0, i1 = 1.f / l1;
    float4* o0 = (float4*)(g_ctx + ((size_t)n * TT + q0) * H2) + lane * 2;
    float4* o1 = (float4*)(g_ctx + ((size_t)n * TT + q1) * H2) + lane * 2;
    o0[0] = make_float4(a0a.x*i0, a0a.y*i0, a0a.z*i0, a0a.w*i0);
    o0[1] = make_float4(a0b.x*i0, a0b.y*i0, a0b.z*i0, a0b.w*i0);
    o1[0] = make_float4(a1a.x*i1, a1a.y*i1, a1a.z*i1, a1a.w*i1);
    o1[1] = make_float4(a1b.x*i1, a1b.y*i1, a1b.z*i1, a1b.w*i1);
}

// ============================ MLP head ============================
__global__ void __launch_bounds__(128)
mlp_kernel(const float* __restrict__ fc1b,
           const float* __restrict__ fc2b,
           const float* __restrict__ fc3w, const float* __restrict__ fc3b,
           float* __restrict__ dout)
{
    __shared__ float sIn[16][512];
    __shared__ float sH1b[16][128];
    __shared__ float sH2b[16][52];
    const int tid = threadIdx.x;

    for (int tile = blockIdx.x; tile < (NB * TT) / 16; tile += gridDim.x) {
        const int row0 = tile * 16;
        for (int i = tid; i < 16 * 512; i += 128) {
            int r = i >> 9, c = i & 511;
            size_t row = (size_t)(row0 + r);
            sIn[r][c] = (c < 256) ? g_ctx[row * 256 + c] : g_out2[row * 256 + (c - 256)];
        }
        __syncthreads();

        {
            float acc[16];
            float b = fc1b[tid];
#pragma unroll
            for (int r = 0; r < 16; ++r) acc[r] = b;
            for (int k = 0; k < 512; ++k) {
                float w = g_fc1T[k * 128 + tid];
#pragma unroll
                for (int r = 0; r < 16; ++r) acc[r] = fmaf(w, sIn[r][k], acc[r]);
            }
#pragma unroll
            for (int r = 0; r < 16; ++r) sH1b[r][tid] = fmaxf(acc[r], 0.f);
        }
        __syncthreads();

        if (tid < 51) {
            float acc[16];
            float b = fc2b[tid];
#pragma unroll
            for (int r = 0; r < 16; ++r) acc[r] = b;
            for (int k = 0; k < 128; ++k) {
                float w = g_fc2T[k * 51 + tid];
#pragma unroll
                for (int r = 0; r < 16; ++r) acc[r] = fmaf(w, sH1b[r][k], acc[r]);
            }
#pragma unroll
            for (int r = 0; r < 16; ++r) sH2b[r][tid] = fmaxf(acc[r], 0.f);
        }
        __syncthreads();

        if (tid < 16) {
            float s = fc3b[0];
            for (int k = 0; k < 51; ++k) s = fmaf(fc3w[k], sH2b[tid][k], s);
            dout[row0 + tid] = s;
        }
        __syncthreads();
    }
}

// ============================ launch ============================
extern "C" void kernel_launch(void* const* d_in, const int* in_sizes, int n_in,
                              void* d_out, int out_size)
{
    const float* x     = (const float*)d_in[0];
    const float* Wih1  = (const float*)d_in[1];
    const float* Whh1  = (const float*)d_in[2];
    const float* bih1  = (const float*)d_in[3];
    const float* bhh1  = (const float*)d_in[4];
    const float* Wih2  = (const float*)d_in[5];
    const float* Whh2  = (const float*)d_in[6];
    const float* bih2  = (const float*)d_in[7];
    const float* bhh2  = (const float*)d_in[8];
    const float* fc1w  = (const float*)d_in[9];
    const float* fc1b  = (const float*)d_in[10];
    const float* fc2w  = (const float*)d_in[11];
    const float* fc2b  = (const float*)d_in[12];
    const float* fc3w  = (const float*)d_in[13];
    const float* fc3b  = (const float*)d_in[14];
    float* out = (float*)d_out;

    const int SM1 = 54304 * 4;
    const int SM2 = 53840 * 4;
    cudaFuncSetAttribute(lstm1_kernel, cudaFuncAttributeMaxDynamicSharedMemorySize, SM1);
    cudaFuncSetAttribute(lstm2_kernel, cudaFuncAttributeMaxDynamicSharedMemorySize, SM2);

    reset_kernel<<<1, 64>>>();
    prep_kernel<<<(128 * 512 + 255) / 256, 256>>>(fc1w, fc2w);
    lstm1_kernel<<<128, 512, SM1>>>(x, Wih1, Whh1, bih1, bhh1, out);
    lstm2_kernel<<<128, 512, SM2>>>(Wih2, Whh2, bih2, bhh2, out);
    {
        dim3 grid(64, 64);
        attn_kernel<<<grid, 256>>>();
    }
    mlp_kernel<<<1024, 128>>>(fc1b, fc2b, fc3w, fc3b, out);
}

// round 13
// speedup vs baseline: 1.7471x; 1.0006x over previous
#include <cuda_runtime.h>
#include <math.h>
#include <stdint.h>

typedef unsigned long long ull;

#define NB   64
#define TT   1024
#define INW  64
#define H1   512
#define H2   256

// ---------------- scratch (static device globals; no allocation) ----------------
__device__ float g_out1[(size_t)NB * TT * H1];
__device__ float g_out2[(size_t)NB * TT * H2];
__device__ float g_ctx [(size_t)NB * TT * H2];
__device__ float g_fc1T[512 * 128];
__device__ float g_fc2T[128 * 51];
__device__ unsigned g_bars[64];

__global__ void reset_kernel() {
    if (threadIdx.x < 64) g_bars[threadIdx.x] = 0u;
}

__global__ void prep_kernel(const float* __restrict__ fc1w, const float* __restrict__ fc2w) {
    int i = blockIdx.x * blockDim.x + threadIdx.x;
    if (i < 128 * 512) { int j = i / 512, k = i % 512; g_fc1T[k * 128 + j] = fc1w[i]; }
    if (i < 51 * 128)  { int j = i / 128, k = i % 128; g_fc2T[k * 51 + j] = fc2w[i]; }
}

// ---------------- helpers ----------------
__device__ __forceinline__ float sigf(float x) { return 1.f / (1.f + __expf(-x)); }
__device__ __forceinline__ float tanhfast(float x) {
    float e = __expf(-2.f * x);
    return (1.f - e) / (1.f + e);
}

__device__ __forceinline__ uint32_t s2u(const void* p) {
    uint32_t a;
    asm("{ .reg .u64 t; cvta.to.shared.u64 t, %1; cvt.u32.u64 %0, t; }" : "=r"(a) : "l"(p));
    return a;
}
__device__ __forceinline__ void cp16(uint32_t dst, const void* src) {
    asm volatile("cp.async.cg.shared.global [%0], [%1], 16;" :: "r"(dst), "l"(src));
}
__device__ __forceinline__ void cpcommit() {
    asm volatile("cp.async.commit_group;" ::: "memory");
}
template <int N>
__device__ __forceinline__ void cpwait() {
    asm volatile("cp.async.wait_group %0;" :: "n"(N) : "memory");
}
__device__ __forceinline__ ull fma2(ull a, ull b, ull c) {
    ull d;
    asm("fma.rn.f32x2 %0, %1, %2, %3;" : "=l"(d) : "l"(a), "l"(b), "l"(c));
    return d;
}
__device__ __forceinline__ ull add2(ull a, ull b) {
    ull d;
    asm("add.rn.f32x2 %0, %1, %2;" : "=l"(d) : "l"(a), "l"(b));
    return d;
}
__device__ __forceinline__ float psum(ull a) {
    return __int_as_float((int)(a & 0xffffffffULL)) + __int_as_float((int)(a >> 32));
}
__device__ __forceinline__ unsigned ldvol(const unsigned* p) {
    unsigned v;
    asm volatile("ld.volatile.global.u32 %0, [%1];" : "=r"(v) : "l"(p));
    return v;
}

// ---------------- pipelined tile compute ----------------
// 32 FFMA2 on a 4x4 tile of packed-f32x2 operands.
__device__ __forceinline__ void fma16(const ulonglong2* W, const ulonglong2* A, ull* acc) {
    acc[0]  = fma2(W[0].x, A[0].x, acc[0]);  acc[0]  = fma2(W[0].y, A[0].y, acc[0]);
    acc[1]  = fma2(W[0].x, A[1].x, acc[1]);  acc[1]  = fma2(W[0].y, A[1].y, acc[1]);
    acc[2]  = fma2(W[0].x, A[2].x, acc[2]);  acc[2]  = fma2(W[0].y, A[2].y, acc[2]);
    acc[3]  = fma2(W[0].x, A[3].x, acc[3]);  acc[3]  = fma2(W[0].y, A[3].y, acc[3]);
    acc[4]  = fma2(W[1].x, A[0].x, acc[4]);  acc[4]  = fma2(W[1].y, A[0].y, acc[4]);
    acc[5]  = fma2(W[1].x, A[1].x, acc[5]);  acc[5]  = fma2(W[1].y, A[1].y, acc[5]);
    acc[6]  = fma2(W[1].x, A[2].x, acc[6]);  acc[6]  = fma2(W[1].y, A[2].y, acc[6]);
    acc[7]  = fma2(W[1].x, A[3].x, acc[7]);  acc[7]  = fma2(W[1].y, A[3].y, acc[7]);
    acc[8]  = fma2(W[2].x, A[0].x, acc[8]);  acc[8]  = fma2(W[2].y, A[0].y, acc[8]);
    acc[9]  = fma2(W[2].x, A[1].x, acc[9]);  acc[9]  = fma2(W[2].y, A[1].y, acc[9]);
    acc[10] = fma2(W[2].x, A[2].x, acc[10]); acc[10] = fma2(W[2].y, A[2].y, acc[10]);
    acc[11] = fma2(W[2].x, A[3].x, acc[11]); acc[11] = fma2(W[2].y, A[3].y, acc[11]);
    acc[12] = fma2(W[3].x, A[0].x, acc[12]); acc[12] = fma2(W[3].y, A[0].y, acc[12]);
    acc[13] = fma2(W[3].x, A[1].x, acc[13]); acc[13] = fma2(W[3].y, A[1].y, acc[13]);
    acc[14] = fma2(W[3].x, A[2].x, acc[14]); acc[14] = fma2(W[3].y, A[2].y, acc[14]);
    acc[15] = fma2(W[3].x, A[3].x, acc[15]); acc[15] = fma2(W[3].y, A[3].y, acc[15]);
}

// lstm1 operand fetch: W rows stride 8*580, A rows stride 8*580.
__device__ __forceinline__ void ld8_1(const float* sWb, const float* sAb, int off,
                                      ulonglong2* W, ulonglong2* A) {
    W[0] = *(const ulonglong2*)(sWb + off);
    W[1] = *(const ulonglong2*)(sWb + 8 * 580 + off);
    W[2] = *(const ulonglong2*)(sWb + 16 * 580 + off);
    W[3] = *(const ulonglong2*)(sWb + 24 * 580 + off);
    A[0] = *(const ulonglong2*)(sAb + off);
    A[1] = *(const ulonglong2*)(sAb + 8 * 580 + off);
    A[2] = *(const ulonglong2*)(sAb + 16 * 580 + off);
    A[3] = *(const ulonglong2*)(sAb + 24 * 580 + off);
}

template<int NU>
__device__ __forceinline__ void pipe1(const float* sWb, const float* sAb,
                                      const int* offs, ull* acc) {
    ulonglong2 W[2][4], A[2][4];
    ld8_1(sWb, sAb, offs[0], W[0], A[0]);
#pragma unroll
    for (int i = 0; i < NU; ++i) {
        if (i + 1 < NU) ld8_1(sWb, sAb, offs[i + 1], W[(i + 1) & 1], A[(i + 1) & 1]);
        fma16(W[i & 1], A[i & 1], acc);
    }
}

// lstm2 operand fetch: W rows stride 4*772, A rows stride 8*772.
__device__ __forceinline__ void ld8_2(const float* sWb, const float* sAb, int off,
                                      ulonglong2* W, ulonglong2* A) {
    W[0] = *(const ulonglong2*)(sWb + off);
    W[1] = *(const ulonglong2*)(sWb + 4 * 772 + off);
    W[2] = *(const ulonglong2*)(sWb + 8 * 772 + off);
    W[3] = *(const ulonglong2*)(sWb + 12 * 772 + off);
    A[0] = *(const ulonglong2*)(sAb + off);
    A[1] = *(const ulonglong2*)(sAb + 8 * 772 + off);
    A[2] = *(const ulonglong2*)(sAb + 16 * 772 + off);
    A[3] = *(const ulonglong2*)(sAb + 24 * 772 + off);
}

template<int NU>
__device__ __forceinline__ void pipe2(const float* sWb, const float* sAb,
                                      const int* offs, ull* acc) {
    ulonglong2 W[2][4], A[2][4];
    ld8_2(sWb, sAb, offs[0], W[0], A[0]);
#pragma unroll
    for (int i = 0; i < NU; ++i) {
        if (i + 1 < NU) ld8_2(sWb, sAb, offs[i + 1], W[(i + 1) & 1], A[(i + 1) & 1]);
        fma16(W[i & 1], A[i & 1], acc);
    }
}

// ============================ LSTM layer 1 ============================
// 128 CTAs x 512 thr. CTA bx: hg=bx>>1 (8 hidden cols), rowgrp=bx&1 (32 rows). K=576.
// Thread tile: hcl=tid&7, rq=(tid>>3)&7, ks=tid>>6; 4 gates x 4 rows, K-sliced by ks.
__global__ void __launch_bounds__(512, 1)
lstm1_kernel(const float* __restrict__ x,
             const float* __restrict__ Wih, const float* __restrict__ Whh,
             const float* __restrict__ bih, const float* __restrict__ bhh,
             float* __restrict__ dout)
{
    extern __shared__ float sm[];
    float* sW    = sm;
    float* sA    = sm + 18560;
    ull*   sP    = (ull*)(sm + 37120);
    float* sBias = sm + 54016;
    float* sC    = sm + 54048;

    const int tid = threadIdx.x;
    const int bx  = blockIdx.x;
    const int hg = bx >> 1, rowgrp = bx & 1, rows0 = rowgrp * 32;

    for (int i = tid; i < 32 * 576; i += 512) {
        int lr = i / 576, k = i - lr * 576;
        int g = lr >> 3, hc = lr & 7;
        int grow = g * H1 + hg * 8 + hc;
        sW[lr * 580 + k] = (k < INW) ? Wih[grow * INW + k] : Whh[grow * H1 + (k - INW)];
    }
    if (tid < 32) {
        int g = tid >> 3, hc = tid & 7;
        int grow = g * H1 + hg * 8 + hc;
        sBias[tid] = bih[grow] + bhh[grow];
    }
    if (tid < 256) sC[tid] = 0.f;
    __syncthreads();

    const int hcl = tid & 7;
    const int rq  = (tid >> 3) & 7;
    const int ks  = tid >> 6;
    const int lr_ = tid >> 4;
    const int lc  = tid & 15;
    const int lp  = (lr_ >> 2) + (lr_ & 3) * 8;
    const uint32_t aB = s2u(sA);
    unsigned* ctr = &g_bars[rowgrp * 16];

    const float* sWb = sW + hcl * 580 + ks * 8;
    const float* sAb = sA + rq * 580 + ks * 8;
    const int offsA[2] = {0, 4};
    const int offsB[8] = {64, 68, 128, 132, 192, 196, 256, 260};
    const int offsC[8] = {320, 324, 384, 388, 448, 452, 512, 516};

    // prime: x loads for t=0
    cp16(aB + (uint32_t)((lp * 580 + lc * 4) * 4),
         x + ((size_t)(rows0 + lr_) * TT + 0) * INW + lc * 4);
    cpcommit();

    for (int t = 0; t < TT; ++t) {
        ull acc[16];
#pragma unroll
        for (int i = 0; i < 16; ++i) acc[i] = 0;

        // ---- non-recurrent: x chunk ----
        cpwait<0>(); __syncthreads();
        pipe1<2>(sWb, sAb, offsA, acc);

        // ---- recurrent part ----
        if (t > 0) {
            if (tid == 0) {
                unsigned tgt = 64u * (unsigned)t;
                while (ldvol(ctr) < tgt) { __nanosleep(32); }
            }
            __syncthreads();
#pragma unroll
            for (int j = 1; j <= 4; ++j) {
                int k4 = lc + 16 * j;
                cp16(aB + (uint32_t)((lp * 580 + k4 * 4) * 4),
                     g_out1 + ((size_t)(rows0 + lr_) * TT + (t - 1)) * H1 + (k4 * 4 - 64));
            }
            cpcommit();
#pragma unroll
            for (int j = 5; j <= 8; ++j) {
                int k4 = lc + 16 * j;
                cp16(aB + (uint32_t)((lp * 580 + k4 * 4) * 4),
                     g_out1 + ((size_t)(rows0 + lr_) * TT + (t - 1)) * H1 + (k4 * 4 - 64));
            }
            cpcommit();

            cpwait<1>(); __syncthreads();
            pipe1<8>(sWb, sAb, offsB, acc);
            cpwait<0>(); __syncthreads();
            pipe1<8>(sWb, sAb, offsC, acc);
        }

        // ---- partial store ----
#pragma unroll
        for (int g = 0; g < 4; ++g) {
#pragma unroll
            for (int r = 0; r < 4; ++r) {
                int cell = (rq * 4 + r) * 8 + hcl;
                int col = g * 8 + ((ks + rq) & 7);
                sP[cell * 33 + col] = acc[g * 4 + r];
            }
        }
        __syncthreads();

        // ---- next step's x loads (overlap reduce) ----
        if (t + 1 < TT) {
            cp16(aB + (uint32_t)((lp * 580 + lc * 4) * 4),
                 x + ((size_t)(rows0 + lr_) * TT + (t + 1)) * INW + lc * 4);
            cpcommit();
        }

        // ---- reduce + nonlinearity ----
        if (tid < 256) {
            int n = tid >> 3, hc = tid & 7;
            const ull* pp = sP + tid * 33;
            float gate[4];
#pragma unroll
            for (int g = 0; g < 4; ++g) {
                ull s0 = add2(pp[g * 8 + 0], pp[g * 8 + 1]);
                ull s1 = add2(pp[g * 8 + 2], pp[g * 8 + 3]);
                ull s2 = add2(pp[g * 8 + 4], pp[g * 8 + 5]);
                ull s3 = add2(pp[g * 8 + 6], pp[g * 8 + 7]);
                ull s = add2(add2(s0, s1), add2(s2, s3));
                gate[g] = psum(s) + sBias[g * 8 + hc];
            }
            float cp = sC[tid];
            float cn = sigf(gate[1]) * cp + sigf(gate[0]) * tanhfast(gate[2]);
            sC[tid] = cn;
            float h = sigf(gate[3]) * tanhfast(cn);
            int ng = rows0 + n;
            int hcg = hg * 8 + hc;
            g_out1[((size_t)ng * TT + t) * H1 + hcg] = h;
            if (t == TT - 1) {
                dout[65536 + ng * H1 + hcg] = h;
                dout[98304 + ng * H1 + hcg] = cn;
            }
        }

        if (t < TT - 1) {
            __threadfence();
            __syncthreads();
            if (tid == 0) atomicAdd(ctr, 1u);
        }
    }
}

// ============================ LSTM layer 2 ============================
// 128 CTAs x 512 thr. hg=bx>>1 (4 hidden cols), rowgrp (32 rows). K=768.
// Thread: hcl=tid&3, rq=(tid>>2)&7, ks=tid>>5 (0..15).
__global__ void __launch_bounds__(512, 1)
lstm2_kernel(const float* __restrict__ Wih, const float* __restrict__ Whh,
             const float* __restrict__ bih, const float* __restrict__ bhh,
             float* __restrict__ dout)
{
    extern __shared__ float sm[];
    float* sW    = sm;
    float* sA    = sm + 12352;
    ull*   sP    = (ull*)(sm + 37056);
    float* sBias = sm + 53696;
    float* sC    = sm + 53712;

    const int tid = threadIdx.x;
    const int bx  = blockIdx.x;
    const int hg = bx >> 1, rowgrp = bx & 1, rows0 = rowgrp * 32;

    for (int i = tid; i < 16 * 768; i += 512) {
        int lr = i / 768, k = i - lr * 768;
        int g = lr >> 2, hc = lr & 3;
        int grow = g * H2 + hg * 4 + hc;
        sW[lr * 772 + k] = (k < H1) ? Wih[grow * H1 + k] : Whh[grow * H2 + (k - H1)];
    }
    if (tid < 16) {
        int g = tid >> 2, hc = tid & 3;
        int grow = g * H2 + hg * 4 + hc;
        sBias[tid] = bih[grow] + bhh[grow];
    }
    if (tid < 128) sC[tid] = 0.f;
    __syncthreads();

    const int hcl = tid & 3;
    const int rq  = (tid >> 2) & 7;
    const int ks  = tid >> 5;
    const int lr_ = tid >> 4;
    const int lc  = tid & 15;
    const int lp  = (lr_ >> 2) + (lr_ & 3) * 8;
    const uint32_t aB = s2u(sA);
    unsigned* ctr = &g_bars[32 + rowgrp * 16];

    const float* sWb = sW + hcl * 772 + ks * 8;
    const float* sAb = sA + rq * 772 + ks * 8;
    const int offsA[4] = {0, 4, 128, 132};
    const int offsB[4] = {256, 260, 384, 388};
    const int offsC[4] = {512, 516, 640, 644};

    // prime: h1[0] loads (2 groups)
#pragma unroll
    for (int j = 0; j < 4; ++j) {
        int k4 = lc + 16 * j;
        cp16(aB + (uint32_t)((lp * 772 + k4 * 4) * 4),
             g_out1 + ((size_t)(rows0 + lr_) * TT + 0) * H1 + k4 * 4);
    }
    cpcommit();
#pragma unroll
    for (int j = 4; j < 8; ++j) {
        int k4 = lc + 16 * j;
        cp16(aB + (uint32_t)((lp * 772 + k4 * 4) * 4),
             g_out1 + ((size_t)(rows0 + lr_) * TT + 0) * H1 + k4 * 4);
    }
    cpcommit();

    for (int t = 0; t < TT; ++t) {
        ull acc[16];
#pragma unroll
        for (int i = 0; i < 16; ++i) acc[i] = 0;

        // ---- non-recurrent: h1[t] ----
        cpwait<1>(); __syncthreads();
        pipe2<4>(sWb, sAb, offsA, acc);
        cpwait<0>(); __syncthreads();
        pipe2<4>(sWb, sAb, offsB, acc);

        // ---- recurrent: h2[t-1] ----
        if (t > 0) {
            if (tid == 0) {
                unsigned tgt = 64u * (unsigned)t;
                while (ldvol(ctr) < tgt) { __nanosleep(32); }
            }
            __syncthreads();
#pragma unroll
            for (int j = 8; j < 12; ++j) {
                int k4 = lc + 16 * j;
                cp16(aB + (uint32_t)((lp * 772 + k4 * 4) * 4),
                     g_out2 + ((size_t)(rows0 + lr_) * TT + (t - 1)) * H2 + (k4 * 4 - 512));
            }
            cpcommit();
            cpwait<0>(); __syncthreads();
            pipe2<4>(sWb, sAb, offsC, acc);
        }

        // ---- partial store ----
#pragma unroll
        for (int g = 0; g < 4; ++g) {
#pragma unroll
            for (int r = 0; r < 4; ++r) {
                int cell = (rq * 4 + r) * 4 + hcl;
                int col = g * 16 + ((ks + rq) & 15);
                sP[cell * 65 + col] = acc[g * 4 + r];
            }
        }
        __syncthreads();

        // ---- next step's h1 loads (overlap reduce) ----
        if (t + 1 < TT) {
#pragma unroll
            for (int j = 0; j < 4; ++j) {
                int k4 = lc + 16 * j;
                cp16(aB + (uint32_t)((lp * 772 + k4 * 4) * 4),
                     g_out1 + ((size_t)(rows0 + lr_) * TT + (t + 1)) * H1 + k4 * 4);
            }
            cpcommit();
#pragma unroll
            for (int j = 4; j < 8; ++j) {
                int k4 = lc + 16 * j;
                cp16(aB + (uint32_t)((lp * 772 + k4 * 4) * 4),
                     g_out1 + ((size_t)(rows0 + lr_) * TT + (t + 1)) * H1 + k4 * 4);
            }
            cpcommit();
        } else {
            cpcommit(); cpcommit();
        }

        // ---- reduce + nonlinearity ----
        if (tid < 128) {
            int n = tid >> 2, hc = tid & 3;
            const ull* pp = sP + tid * 65;
            float gate[4];
#pragma unroll
            for (int g = 0; g < 4; ++g) {
                ull s = pp[g * 16];
#pragma unroll
                for (int j = 1; j < 16; ++j) s = add2(s, pp[g * 16 + j]);
                gate[g] = psum(s) + sBias[g * 4 + hc];
            }
            float cp = sC[tid];
            float cn = sigf(gate[1]) * cp + sigf(gate[0]) * tanhfast(gate[2]);
            sC[tid] = cn;
            float h = sigf(gate[3]) * tanhfast(cn);
            int ng = rows0 + n;
            int hcg = hg * 4 + hc;
            g_out2[((size_t)ng * TT + t) * H2 + hcg] = h;
            if (t == TT - 1) {
                dout[131072 + ng * H2 + hcg] = h;
                dout[147456 + ng * H2 + hcg] = cn;
            }
        }

        if (t < TT - 1) {
            __threadfence();
            __syncthreads();
            if (tid == 0) atomicAdd(ctr, 1u);
        }
    }
}

// ============================ causal attention (tiled) ============================
__global__ void __launch_bounds__(256)
attn_kernel()
{
    __shared__ float sK[32 * 256];
    const int tid = threadIdx.x;
    const int lane = tid & 31, warp = tid >> 5;
    const int qb = blockIdx.x, n = blockIdx.y;
    const int q0 = qb * 16 + warp * 2, q1 = q0 + 1;
    const float* bp = g_out2 + (size_t)n * TT * H2;

    const float4* qp0 = (const float4*)(bp + (size_t)q0 * H2) + lane * 2;
    const float4* qp1 = (const float4*)(bp + (size_t)q1 * H2) + lane * 2;
    float4 q0a = qp0[0], q0b = qp0[1];
    float4 q1a = qp1[0], q1b = qp1[1];

    float m0 = -1e30f, l0 = 0.f, m1 = -1e30f, l1 = 0.f;
    float4 a0a = {0,0,0,0}, a0b = {0,0,0,0}, a1a = {0,0,0,0}, a1b = {0,0,0,0};

    const int ntiles = (qb * 16 + 16 + 31) >> 5;
    const uint32_t kB = s2u(sK);

    for (int tile = 0; tile < ntiles; ++tile) {
        const int s0 = tile * 32;
        __syncthreads();
#pragma unroll
        for (int jj = 0; jj < 8; ++jj) {
            int flat = jj * 256 + tid;
            int key = flat >> 6, off = flat & 63;
            cp16(kB + (uint32_t)flat * 16, bp + (size_t)(s0 + key) * H2 + off * 4);
        }
        cpcommit();
        cpwait<0>();
        __syncthreads();

        int kmax = q1 - s0 + 1;
        if (kmax > 32) kmax = 32;
        for (int kk = 0; kk < kmax; ++kk) {
            const float4* kp = (const float4*)(sK + kk * 256) + lane * 2;
            float4 ka = kp[0], kb4 = kp[1];
            float p0 = q0a.x*ka.x + q0a.y*ka.y + q0a.z*ka.z + q0a.w*ka.w
                     + q0b.x*kb4.x + q0b.y*kb4.y + q0b.z*kb4.z + q0b.w*kb4.w;
            float p1 = q1a.x*ka.x + q1a.y*ka.y + q1a.z*ka.z + q1a.w*ka.w
                     + q1b.x*kb4.x + q1b.y*kb4.y + q1b.z*kb4.z + q1b.w*kb4.w;
            p0 += __shfl_xor_sync(0xffffffffu, p0, 16);
            p1 += __shfl_xor_sync(0xffffffffu, p1, 16);
            p0 += __shfl_xor_sync(0xffffffffu, p0, 8);
            p1 += __shfl_xor_sync(0xffffffffu, p1, 8);
            p0 += __shfl_xor_sync(0xffffffffu, p0, 4);
            p1 += __shfl_xor_sync(0xffffffffu, p1, 4);
            p0 += __shfl_xor_sync(0xffffffffu, p0, 2);
            p1 += __shfl_xor_sync(0xffffffffu, p1, 2);
            p0 += __shfl_xor_sync(0xffffffffu, p0, 1);
            p1 += __shfl_xor_sync(0xffffffffu, p1, 1);
            int keyg = s0 + kk;
            {
                float nm = fmaxf(m1, p1);
                float e  = __expf(p1 - nm);
                float sc = __expf(m1 - nm);
                l1 = l1 * sc + e; m1 = nm;
                a1a.x = a1a.x*sc + e*ka.x;  a1a.y = a1a.y*sc + e*ka.y;
                a1a.z = a1a.z*sc + e*ka.z;  a1a.w = a1a.w*sc + e*ka.w;
                a1b.x = a1b.x*sc + e*kb4.x; a1b.y = a1b.y*sc + e*kb4.y;
                a1b.z = a1b.z*sc + e*kb4.z; a1b.w = a1b.w*sc + e*kb4.w;
            }
            if (keyg <= q0) {
                float nm = fmaxf(m0, p0);
                float e  = __expf(p0 - nm);
                float sc = __expf(m0 - nm);
                l0 = l0 * sc + e; m0 = nm;
                a0a.x = a0a.x*sc + e*ka.x;  a0a.y = a0a.y*sc + e*ka.y;
                a0a.z = a0a.z*sc + e*ka.z;  a0a.w = a0a.w*sc + e*ka.w;
                a0b.x = a0b.x*sc + e*kb4.x; a0b.y = a0b.y*sc + e*kb4.y;
                a0b.z = a0b.z*sc + e*kb4.z; a0b.w = a0b.w*sc + e*kb4.w;
            }
        }
    }

    float i0 = 1.f / l0, i1 = 1.f / l1;
    float4* o0 = (float4*)(g_ctx + ((size_t)n * TT + q0) * H2) + lane * 2;
    float4* o1 = (float4*)(g_ctx + ((size_t)n * TT + q1) * H2) + lane * 2;
    o0[0] = make_float4(a0a.x*i0, a0a.y*i0, a0a.z*i0, a0a.w*i0);
    o0[1] = make_float4(a0b.x*i0, a0b.y*i0, a0b.z*i0, a0b.w*i0);
    o1[0] = make_float4(a1a.x*i1, a1a.y*i1, a1a.z*i1, a1a.w*i1);
    o1[1] = make_float4(a1b.x*i1, a1b.y*i1, a1b.z*i1, a1b.w*i1);
}

// ============================ MLP head ============================
__global__ void __launch_bounds__(128)
mlp_kernel(const float* __restrict__ fc1b,
           const float* __restrict__ fc2b,
           const float* __restrict__ fc3w, const float* __restrict__ fc3b,
           float* __restrict__ dout)
{
    __shared__ float sIn[16][512];
    __shared__ float sH1b[16][128];
    __shared__ float sH2b[16][52];
    const int tid = threadIdx.x;

    for (int tile = blockIdx.x; tile < (NB * TT) / 16; tile += gridDim.x) {
        const int row0 = tile * 16;
        for (int i = tid; i < 16 * 512; i += 128) {
            int r = i >> 9, c = i & 511;
            size_t row = (size_t)(row0 + r);
            sIn[r][c] = (c < 256) ? g_ctx[row * 256 + c] : g_out2[row * 256 + (c - 256)];
        }
        __syncthreads();

        {
            float acc[16];
            float b = fc1b[tid];
#pragma unroll
            for (int r = 0; r < 16; ++r) acc[r] = b;
            for (int k = 0; k < 512; ++k) {
                float w = g_fc1T[k * 128 + tid];
#pragma unroll
                for (int r = 0; r < 16; ++r) acc[r] = fmaf(w, sIn[r][k], acc[r]);
            }
#pragma unroll
            for (int r = 0; r < 16; ++r) sH1b[r][tid] = fmaxf(acc[r], 0.f);
        }
        __syncthreads();

        if (tid < 51) {
            float acc[16];
            float b = fc2b[tid];
#pragma unroll
            for (int r = 0; r < 16; ++r) acc[r] = b;
            for (int k = 0; k < 128; ++k) {
                float w = g_fc2T[k * 51 + tid];
#pragma unroll
                for (int r = 0; r < 16; ++r) acc[r] = fmaf(w, sH1b[r][k], acc[r]);
            }
#pragma unroll
            for (int r = 0; r < 16; ++r) sH2b[r][tid] = fmaxf(acc[r], 0.f);
        }
        __syncthreads();

        if (tid < 16) {
            float s = fc3b[0];
            for (int k = 0; k < 51; ++k) s = fmaf(fc3w[k], sH2b[tid][k], s);
            dout[row0 + tid] = s;
        }
        __syncthreads();
    }
}

// ============================ launch ============================
extern "C" void kernel_launch(void* const* d_in, const int* in_sizes, int n_in,
                              void* d_out, int out_size)
{
    const float* x     = (const float*)d_in[0];
    const float* Wih1  = (const float*)d_in[1];
    const float* Whh1  = (const float*)d_in[2];
    const float* bih1  = (const float*)d_in[3];
    const float* bhh1  = (const float*)d_in[4];
    const float* Wih2  = (const float*)d_in[5];
    const float* Whh2  = (const float*)d_in[6];
    const float* bih2  = (const float*)d_in[7];
    const float* bhh2  = (const float*)d_in[8];
    const float* fc1w  = (const float*)d_in[9];
    const float* fc1b  = (const float*)d_in[10];
    const float* fc2w  = (const float*)d_in[11];
    const float* fc2b  = (const float*)d_in[12];
    const float* fc3w  = (const float*)d_in[13];
    const float* fc3b  = (const float*)d_in[14];
    float* out = (float*)d_out;

    const int SM1 = 54304 * 4;
    const int SM2 = 53840 * 4;
    cudaFuncSetAttribute(lstm1_kernel, cudaFuncAttributeMaxDynamicSharedMemorySize, SM1);
    cudaFuncSetAttribute(lstm2_kernel, cudaFuncAttributeMaxDynamicSharedMemorySize, SM2);

    reset_kernel<<<1, 64>>>();
    prep_kernel<<<(128 * 512 + 255) / 256, 256>>>(fc1w, fc2w);
    lstm1_kernel<<<128, 512, SM1>>>(x, Wih1, Whh1, bih1, bhh1, out);
    lstm2_kernel<<<128, 512, SM2>>>(Wih2, Whh2, bih2, bhh2, out);
    {
        dim3 grid(64, 64);
        attn_kernel<<<grid, 256>>>();
    }
    mlp_kernel<<<1024, 128>>>(fc1b, fc2b, fc3w, fc3b, out);
}

// round 14
// speedup vs baseline: 1.8301x; 1.0475x over previous
#include <cuda_runtime.h>
#include <cuda_fp16.h>
#include <math.h>
#include <stdint.h>

typedef unsigned long long ull;

#define NB   64
#define TT   1024
#define INW  64
#define H1   512
#define H2   256

__device__ float g_out1[(size_t)NB * TT * H1];
__device__ float g_out2[(size_t)NB * TT * H2];
__device__ float g_ctx [(size_t)NB * TT * H2];
__device__ float g_fc1T[512 * 128];
__device__ float g_fc2T[128 * 51];
__device__ unsigned g_bars[64];
__device__ __half g_w2hi[1024 * 512];
__device__ __half g_w2lo[1024 * 512];
__device__ float  g_pre2[(size_t)NB * TT * 1024];

__global__ void reset_kernel() {
    if (threadIdx.x < 64) g_bars[threadIdx.x] = 0u;
}

__global__ void prep_kernel(const float* __restrict__ fc1w, const float* __restrict__ fc2w) {
    int i = blockIdx.x * blockDim.x + threadIdx.x;
    if (i < 128 * 512) { int j = i / 512, k = i % 512; g_fc1T[k * 128 + j] = fc1w[i]; }
    if (i < 51 * 128)  { int j = i / 128, k = i % 128; g_fc2T[k * 51 + j] = fc2w[i]; }
}

__global__ void prep_w2_kernel(const float* __restrict__ Wih2) {
    int i = blockIdx.x * blockDim.x + threadIdx.x;
    if (i < 1024 * 512) {
        float f = Wih2[i];
        __half hi = __float2half_rn(f);
        g_w2hi[i] = hi;
        g_w2lo[i] = __float2half_rn((f - __half2float(hi)) * 2048.0f);
    }
}

// ---------------- helpers ----------------
__device__ __forceinline__ float sigf(float x) { return 1.f / (1.f + __expf(-x)); }
__device__ __forceinline__ float tanhfast(float x) {
    float e = __expf(-2.f * x);
    return (1.f - e) / (1.f + e);
}
__device__ __forceinline__ uint32_t s2u(const void* p) {
    uint32_t a;
    asm("{ .reg .u64 t; cvta.to.shared.u64 t, %1; cvt.u32.u64 %0, t; }" : "=r"(a) : "l"(p));
    return a;
}
__device__ __forceinline__ void cp16(uint32_t dst, const void* src) {
    asm volatile("cp.async.cg.shared.global [%0], [%1], 16;" :: "r"(dst), "l"(src));
}
__device__ __forceinline__ void cpcommit() {
    asm volatile("cp.async.commit_group;" ::: "memory");
}
template <int N>
__device__ __forceinline__ void cpwait() {
    asm volatile("cp.async.wait_group %0;" :: "n"(N) : "memory");
}
__device__ __forceinline__ ull fma2(ull a, ull b, ull c) {
    ull d;
    asm("fma.rn.f32x2 %0, %1, %2, %3;" : "=l"(d) : "l"(a), "l"(b), "l"(c));
    return d;
}
__device__ __forceinline__ ull add2(ull a, ull b) {
    ull d;
    asm("add.rn.f32x2 %0, %1, %2;" : "=l"(d) : "l"(a), "l"(b));
    return d;
}
__device__ __forceinline__ float psum(ull a) {
    return __int_as_float((int)(a & 0xffffffffULL)) + __int_as_float((int)(a >> 32));
}
__device__ __forceinline__ unsigned ldvol(const unsigned* p) {
    unsigned v;
    asm volatile("ld.volatile.global.u32 %0, [%1];" : "=r"(v) : "l"(p));
    return v;
}
__device__ __forceinline__ void ldsm4(uint32_t addr, uint32_t* r) {
    asm volatile("ldmatrix.sync.aligned.m8n8.x4.shared.b16 {%0,%1,%2,%3},[%4];"
        : "=r"(r[0]), "=r"(r[1]), "=r"(r[2]), "=r"(r[3]) : "r"(addr));
}
__device__ __forceinline__ void ldsm2(uint32_t addr, uint32_t* r) {
    asm volatile("ldmatrix.sync.aligned.m8n8.x2.shared.b16 {%0,%1},[%2];"
        : "=r"(r[0]), "=r"(r[1]) : "r"(addr));
}
__device__ __forceinline__ void mma16816(float* c, const uint32_t* a, const uint32_t* b) {
    asm volatile("mma.sync.aligned.m16n8k16.row.col.f32.f16.f16.f32 "
        "{%0,%1,%2,%3},{%4,%5,%6,%7},{%8,%9},{%0,%1,%2,%3};"
        : "+f"(c[0]), "+f"(c[1]), "+f"(c[2]), "+f"(c[3])
        : "r"(a[0]), "r"(a[1]), "r"(a[2]), "r"(a[3]), "r"(b[0]), "r"(b[1]));
}
__device__ __forceinline__ uint32_t h2pk(float a, float b) {
    __half2 h = __floats2half2_rn(a, b);
    return *(uint32_t*)&h;
}

// ---------------- fp32 tile compute (from verified R11) ----------------
__device__ __forceinline__ void fma16(const ulonglong2* W, const ulonglong2* A, ull* acc) {
    acc[0]  = fma2(W[0].x, A[0].x, acc[0]);  acc[0]  = fma2(W[0].y, A[0].y, acc[0]);
    acc[1]  = fma2(W[0].x, A[1].x, acc[1]);  acc[1]  = fma2(W[0].y, A[1].y, acc[1]);
    acc[2]  = fma2(W[0].x, A[2].x, acc[2]);  acc[2]  = fma2(W[0].y, A[2].y, acc[2]);
    acc[3]  = fma2(W[0].x, A[3].x, acc[3]);  acc[3]  = fma2(W[0].y, A[3].y, acc[3]);
    acc[4]  = fma2(W[1].x, A[0].x, acc[4]);  acc[4]  = fma2(W[1].y, A[0].y, acc[4]);
    acc[5]  = fma2(W[1].x, A[1].x, acc[5]);  acc[5]  = fma2(W[1].y, A[1].y, acc[5]);
    acc[6]  = fma2(W[1].x, A[2].x, acc[6]);  acc[6]  = fma2(W[1].y, A[2].y, acc[6]);
    acc[7]  = fma2(W[1].x, A[3].x, acc[7]);  acc[7]  = fma2(W[1].y, A[3].y, acc[7]);
    acc[8]  = fma2(W[2].x, A[0].x, acc[8]);  acc[8]  = fma2(W[2].y, A[0].y, acc[8]);
    acc[9]  = fma2(W[2].x, A[1].x, acc[9]);  acc[9]  = fma2(W[2].y, A[1].y, acc[9]);
    acc[10] = fma2(W[2].x, A[2].x, acc[10]); acc[10] = fma2(W[2].y, A[2].y, acc[10]);
    acc[11] = fma2(W[2].x, A[3].x, acc[11]); acc[11] = fma2(W[2].y, A[3].y, acc[11]);
    acc[12] = fma2(W[3].x, A[0].x, acc[12]); acc[12] = fma2(W[3].y, A[0].y, acc[12]);
    acc[13] = fma2(W[3].x, A[1].x, acc[13]); acc[13] = fma2(W[3].y, A[1].y, acc[13]);
    acc[14] = fma2(W[3].x, A[2].x, acc[14]); acc[14] = fma2(W[3].y, A[2].y, acc[14]);
    acc[15] = fma2(W[3].x, A[3].x, acc[15]); acc[15] = fma2(W[3].y, A[3].y, acc[15]);
}
__device__ __forceinline__ void ld8_1(const float* sWb, const float* sAb, int off,
                                      ulonglong2* W, ulonglong2* A) {
    W[0] = *(const ulonglong2*)(sWb + off);
    W[1] = *(const ulonglong2*)(sWb + 8 * 580 + off);
    W[2] = *(const ulonglong2*)(sWb + 16 * 580 + off);
    W[3] = *(const ulonglong2*)(sWb + 24 * 580 + off);
    A[0] = *(const ulonglong2*)(sAb + off);
    A[1] = *(const ulonglong2*)(sAb + 8 * 580 + off);
    A[2] = *(const ulonglong2*)(sAb + 16 * 580 + off);
    A[3] = *(const ulonglong2*)(sAb + 24 * 580 + off);
}
template<int NU>
__device__ __forceinline__ void pipe1(const float* sWb, const float* sAb,
                                      const int* offs, ull* acc) {
    ulonglong2 W[2][4], A[2][4];
    ld8_1(sWb, sAb, offs[0], W[0], A[0]);
#pragma unroll
    for (int i = 0; i < NU; ++i) {
        if (i + 1 < NU) ld8_1(sWb, sAb, offs[i + 1], W[(i + 1) & 1], A[(i + 1) & 1]);
        fma16(W[i & 1], A[i & 1], acc);
    }
}
__device__ __forceinline__ void ld8_2(const float* sWb, const float* sAb, int off,
                                      ulonglong2* W, ulonglong2* A) {
    W[0] = *(const ulonglong2*)(sWb + off);
    W[1] = *(const ulonglong2*)(sWb + 4 * 772 + off);
    W[2] = *(const ulonglong2*)(sWb + 8 * 772 + off);
    W[3] = *(const ulonglong2*)(sWb + 12 * 772 + off);
    A[0] = *(const ulonglong2*)(sAb + off);
    A[1] = *(const ulonglong2*)(sAb + 8 * 772 + off);
    A[2] = *(const ulonglong2*)(sAb + 16 * 772 + off);
    A[3] = *(const ulonglong2*)(sAb + 24 * 772 + off);
}
template<int NU>
__device__ __forceinline__ void pipe2(const float* sWb, const float* sAb,
                                      const int* offs, ull* acc) {
    ulonglong2 W[2][4], A[2][4];
    ld8_2(sWb, sAb, offs[0], W[0], A[0]);
#pragma unroll
    for (int i = 0; i < NU; ++i) {
        if (i + 1 < NU) ld8_2(sWb, sAb, offs[i + 1], W[(i + 1) & 1], A[(i + 1) & 1]);
        fma16(W[i & 1], A[i & 1], acc);
    }
}

// ============================ GEMM: g_pre2 = out1 · Wih2^T (fp16 split, mma) ============
// C[65536x1024] tiles M128 x N64 x K32; 256 thr = 8 warps (4m x 2n).
__global__ void __launch_bounds__(256) gemm_pre2_kernel() {
    __shared__ __half sAh[128 * 40], sAl[128 * 40], sBh[64 * 40], sBl[64 * 40];
    const int tid = threadIdx.x, lane = tid & 31, warp = tid >> 5;
    const int wm = warp >> 1, wn = warp & 1;
    const int n0 = blockIdx.x * 64, m0 = blockIdx.y * 128;
    const uint32_t ah = s2u(sAh), al = s2u(sAl), bh = s2u(sBh), bl = s2u(sBl);

    float Ch[8][4], Cx[8][4];
#pragma unroll
    for (int i = 0; i < 8; ++i)
#pragma unroll
        for (int j = 0; j < 4; ++j) { Ch[i][j] = 0.f; Cx[i][j] = 0.f; }

    const int arow = tid >> 1, ahf = tid & 1;
    const int brow = tid >> 2, bseg = tid & 3;

    for (int kc = 0; kc < 16; ++kc) {
        cp16(bh + (uint32_t)((brow * 40 + bseg * 8) * 2),
             g_w2hi + (size_t)(n0 + brow) * 512 + kc * 32 + bseg * 8);
        cp16(bl + (uint32_t)((brow * 40 + bseg * 8) * 2),
             g_w2lo + (size_t)(n0 + brow) * 512 + kc * 32 + bseg * 8);
        cpcommit();
        {
            const float* src = g_out1 + (size_t)(m0 + arow) * 512 + kc * 32 + ahf * 16;
            uint4* dh = (uint4*)(sAh + arow * 40 + ahf * 16);
            uint4* dl = (uint4*)(sAl + arow * 40 + ahf * 16);
#pragma unroll
            for (int q = 0; q < 2; ++q) {
                float4 x0 = *(const float4*)(src + q * 8);
                float4 x1 = *(const float4*)(src + q * 8 + 4);
                float f[8] = {x0.x, x0.y, x0.z, x0.w, x1.x, x1.y, x1.z, x1.w};
                uint32_t h[4], l[4];
#pragma unroll
                for (int i = 0; i < 4; ++i) {
                    float a = f[2 * i], b = f[2 * i + 1];
                    __half2 hh = __floats2half2_rn(a, b);
                    float2 fb = __half22float2(hh);
                    h[i] = *(uint32_t*)&hh;
                    l[i] = h2pk((a - fb.x) * 2048.f, (b - fb.y) * 2048.f);
                }
                dh[q] = make_uint4(h[0], h[1], h[2], h[3]);
                dl[q] = make_uint4(l[0], l[1], l[2], l[3]);
            }
        }
        cpwait<0>();
        __syncthreads();

#pragma unroll
        for (int kt = 0; kt < 2; ++kt) {
            uint32_t Af[2][4], Al2[2][4], Bf[4][2], Bl2[4][2];
            int arw = lane & 15, akh = lane >> 4;
#pragma unroll
            for (int mi = 0; mi < 2; ++mi) {
                uint32_t off = (uint32_t)(((wm * 32 + mi * 16 + arw) * 40 + kt * 16 + akh * 8) * 2);
                ldsm4(ah + off, Af[mi]);
                ldsm4(al + off, Al2[mi]);
            }
            int brw = lane & 7, bkh = (lane >> 3) & 1;
#pragma unroll
            for (int ni = 0; ni < 4; ++ni) {
                uint32_t off = (uint32_t)(((wn * 32 + ni * 8 + brw) * 40 + kt * 16 + bkh * 8) * 2);
                ldsm2(bh + off, Bf[ni]);
                ldsm2(bl + off, Bl2[ni]);
            }
#pragma unroll
            for (int mi = 0; mi < 2; ++mi)
#pragma unroll
                for (int ni = 0; ni < 4; ++ni) {
                    mma16816(Ch[mi * 4 + ni], Af[mi], Bf[ni]);
                    mma16816(Cx[mi * 4 + ni], Af[mi], Bl2[ni]);
                    mma16816(Cx[mi * 4 + ni], Al2[mi], Bf[ni]);
                }
        }
        __syncthreads();
    }

    const float s = 1.f / 2048.f;
#pragma unroll
    for (int mi = 0; mi < 2; ++mi)
#pragma unroll
        for (int ni = 0; ni < 4; ++ni) {
            float* c = Ch[mi * 4 + ni];
            float* x = Cx[mi * 4 + ni];
            int row = m0 + wm * 32 + mi * 16 + (lane >> 2);
            int col = n0 + wn * 32 + ni * 8 + (lane & 3) * 2;
            *(float2*)(g_pre2 + (size_t)row * 1024 + col) =
                make_float2(c[0] + x[0] * s, c[1] + x[1] * s);
            *(float2*)(g_pre2 + (size_t)(row + 8) * 1024 + col) =
                make_float2(c[2] + x[2] * s, c[3] + x[3] * s);
        }
}

// ============================ LSTM layer 1 (unchanged, verified) ============================
__global__ void __launch_bounds__(512, 1)
lstm1_kernel(const float* __restrict__ x,
             const float* __restrict__ Wih, const float* __restrict__ Whh,
             const float* __restrict__ bih, const float* __restrict__ bhh,
             float* __restrict__ dout)
{
    extern __shared__ float sm[];
    float* sW    = sm;
    float* sA    = sm + 18560;
    ull*   sP    = (ull*)(sm + 37120);
    float* sBias = sm + 54016;
    float* sC    = sm + 54048;

    const int tid = threadIdx.x;
    const int bx  = blockIdx.x;
    const int hg = bx >> 1, rowgrp = bx & 1, rows0 = rowgrp * 32;

    for (int i = tid; i < 32 * 576; i += 512) {
        int lr = i / 576, k = i - lr * 576;
        int g = lr >> 3, hc = lr & 7;
        int grow = g * H1 + hg * 8 + hc;
        sW[lr * 580 + k] = (k < INW) ? Wih[grow * INW + k] : Whh[grow * H1 + (k - INW)];
    }
    if (tid < 32) {
        int g = tid >> 3, hc = tid & 7;
        int grow = g * H1 + hg * 8 + hc;
        sBias[tid] = bih[grow] + bhh[grow];
    }
    if (tid < 256) sC[tid] = 0.f;
    __syncthreads();

    const int hcl = tid & 7;
    const int rq  = (tid >> 3) & 7;
    const int ks  = tid >> 6;
    const int lr_ = tid >> 4;
    const int lc  = tid & 15;
    const int lp  = (lr_ >> 2) + (lr_ & 3) * 8;
    const uint32_t aB = s2u(sA);
    unsigned* ctr = &g_bars[rowgrp * 16];

    const float* sWb = sW + hcl * 580 + ks * 8;
    const float* sAb = sA + rq * 580 + ks * 8;
    const int offsA[2] = {0, 4};
    const int offsB[8] = {64, 68, 128, 132, 192, 196, 256, 260};
    const int offsC[8] = {320, 324, 384, 388, 448, 452, 512, 516};

    cp16(aB + (uint32_t)((lp * 580 + lc * 4) * 4),
         x + ((size_t)(rows0 + lr_) * TT + 0) * INW + lc * 4);
    cpcommit();

    for (int t = 0; t < TT; ++t) {
        ull acc[16];
#pragma unroll
        for (int i = 0; i < 16; ++i) acc[i] = 0;

        cpwait<0>(); __syncthreads();
        pipe1<2>(sWb, sAb, offsA, acc);

        if (t > 0) {
            if (tid == 0) {
                unsigned tgt = 64u * (unsigned)t;
                while (ldvol(ctr) < tgt) { __nanosleep(32); }
            }
            __syncthreads();
#pragma unroll
            for (int j = 1; j <= 4; ++j) {
                int k4 = lc + 16 * j;
                cp16(aB + (uint32_t)((lp * 580 + k4 * 4) * 4),
                     g_out1 + ((size_t)(rows0 + lr_) * TT + (t - 1)) * H1 + (k4 * 4 - 64));
            }
            cpcommit();
#pragma unroll
            for (int j = 5; j <= 8; ++j) {
                int k4 = lc + 16 * j;
                cp16(aB + (uint32_t)((lp * 580 + k4 * 4) * 4),
                     g_out1 + ((size_t)(rows0 + lr_) * TT + (t - 1)) * H1 + (k4 * 4 - 64));
            }
            cpcommit();

            cpwait<1>(); __syncthreads();
            pipe1<8>(sWb, sAb, offsB, acc);
            cpwait<0>(); __syncthreads();
            pipe1<8>(sWb, sAb, offsC, acc);
        }

#pragma unroll
        for (int g = 0; g < 4; ++g) {
#pragma unroll
            for (int r = 0; r < 4; ++r) {
                int cell = (rq * 4 + r) * 8 + hcl;
                int col = g * 8 + ((ks + rq) & 7);
                sP[cell * 33 + col] = acc[g * 4 + r];
            }
        }
        __syncthreads();

        if (t + 1 < TT) {
            cp16(aB + (uint32_t)((lp * 580 + lc * 4) * 4),
                 x + ((size_t)(rows0 + lr_) * TT + (t + 1)) * INW + lc * 4);
            cpcommit();
        }

        if (tid < 256) {
            int n = tid >> 3, hc = tid & 7;
            const ull* pp = sP + tid * 33;
            float gate[4];
#pragma unroll
            for (int g = 0; g < 4; ++g) {
                ull s0 = add2(pp[g * 8 + 0], pp[g * 8 + 1]);
                ull s1 = add2(pp[g * 8 + 2], pp[g * 8 + 3]);
                ull s2 = add2(pp[g * 8 + 4], pp[g * 8 + 5]);
                ull s3 = add2(pp[g * 8 + 6], pp[g * 8 + 7]);
                ull s = add2(add2(s0, s1), add2(s2, s3));
                gate[g] = psum(s) + sBias[g * 8 + hc];
            }
            float cp = sC[tid];
            float cn = sigf(gate[1]) * cp + sigf(gate[0]) * tanhfast(gate[2]);
            sC[tid] = cn;
            float h = sigf(gate[3]) * tanhfast(cn);
            int ng = rows0 + n;
            int hcg = hg * 8 + hc;
            g_out1[((size_t)ng * TT + t) * H1 + hcg] = h;
            if (t == TT - 1) {
                dout[65536 + ng * H1 + hcg] = h;
                dout[98304 + ng * H1 + hcg] = cn;
            }
        }

        if (t < TT - 1) {
            __threadfence();
            __syncthreads();
            if (tid == 0) atomicAdd(ctr, 1u);
        }
    }
}

// ============================ LSTM layer 2 (h1-part via g_pre2) ============================
__global__ void __launch_bounds__(512, 1)
lstm2_kernel(const float* __restrict__ Wih, const float* __restrict__ Whh,
             const float* __restrict__ bih, const float* __restrict__ bhh,
             float* __restrict__ dout)
{
    extern __shared__ float sm[];
    float* sW    = sm;
    float* sA    = sm + 12352;
    ull*   sP    = (ull*)(sm + 37056);
    float* sBias = sm + 53696;
    float* sC    = sm + 53712;
    float* sPre  = sm + 53840;   // 32*20

    const int tid = threadIdx.x;
    const int bx  = blockIdx.x;
    const int hg = bx >> 1, rowgrp = bx & 1, rows0 = rowgrp * 32;

    for (int i = tid; i < 16 * 768; i += 512) {
        int lr = i / 768, k = i - lr * 768;
        int g = lr >> 2, hc = lr & 3;
        int grow = g * H2 + hg * 4 + hc;
        sW[lr * 772 + k] = (k < H1) ? Wih[grow * H1 + k] : Whh[grow * H2 + (k - H1)];
    }
    if (tid < 16) {
        int g = tid >> 2, hc = tid & 3;
        int grow = g * H2 + hg * 4 + hc;
        sBias[tid] = bih[grow] + bhh[grow];
    }
    if (tid < 128) sC[tid] = 0.f;
    __syncthreads();

    const int hcl = tid & 3;
    const int rq  = (tid >> 2) & 7;
    const int ks  = tid >> 5;
    const int lr_ = tid >> 4;
    const int lc  = tid & 15;
    const int lp  = (lr_ >> 2) + (lr_ & 3) * 8;
    const uint32_t aB = s2u(sA);
    const uint32_t pB = s2u(sPre);
    unsigned* ctr = &g_bars[32 + rowgrp * 16];

    const float* sWb = sW + hcl * 772 + ks * 8;
    const float* sAb = sA + rq * 772 + ks * 8;
    const int offsC[4] = {512, 516, 640, 644};

    for (int t = 0; t < TT; ++t) {
        // pre-activation slice for this step (overlaps spin + h2 loads)
        if (tid < 128) {
            int n = tid >> 2, g = tid & 3;
            size_t r = (size_t)(rows0 + n) * TT + t;
            cp16(pB + (uint32_t)((n * 20 + g * 4) * 4),
                 g_pre2 + r * 1024 + g * 256 + hg * 4);
        }
        cpcommit();

        ull acc[16];
#pragma unroll
        for (int i = 0; i < 16; ++i) acc[i] = 0;

        if (t > 0) {
            if (tid == 0) {
                unsigned tgt = 64u * (unsigned)t;
                while (ldvol(ctr) < tgt) { __nanosleep(32); }
            }
            __syncthreads();
#pragma unroll
            for (int j = 8; j < 12; ++j) {
                int k4 = lc + 16 * j;
                cp16(aB + (uint32_t)((lp * 772 + k4 * 4) * 4),
                     g_out2 + ((size_t)(rows0 + lr_) * TT + (t - 1)) * H2 + (k4 * 4 - 512));
            }
            cpcommit();
            cpwait<0>(); __syncthreads();
            pipe2<4>(sWb, sAb, offsC, acc);
        } else {
            cpwait<0>(); __syncthreads();
        }

#pragma unroll
        for (int g = 0; g < 4; ++g) {
#pragma unroll
            for (int r = 0; r < 4; ++r) {
                int cell = (rq * 4 + r) * 4 + hcl;
                int col = g * 16 + ((ks + rq) & 15);
                sP[cell * 65 + col] = acc[g * 4 + r];
            }
        }
        __syncthreads();

        if (tid < 128) {
            int n = tid >> 2, hc = tid & 3;
            const ull* pp = sP + tid * 65;
            const float* pr = sPre + n * 20 + hc;
            float gate[4];
#pragma unroll
            for (int g = 0; g < 4; ++g) {
                ull s = pp[g * 16];
#pragma unroll
                for (int j = 1; j < 16; ++j) s = add2(s, pp[g * 16 + j]);
                gate[g] = psum(s) + sBias[g * 4 + hc] + pr[g * 4];
            }
            float cp = sC[tid];
            float cn = sigf(gate[1]) * cp + sigf(gate[0]) * tanhfast(gate[2]);
            sC[tid] = cn;
            float h = sigf(gate[3]) * tanhfast(cn);
            int ng = rows0 + n;
            int hcg = hg * 4 + hc;
            g_out2[((size_t)ng * TT + t) * H2 + hcg] = h;
            if (t == TT - 1) {
                dout[131072 + ng * H2 + hcg] = h;
                dout[147456 + ng * H2 + hcg] = cn;
            }
        }

        if (t < TT - 1) {
            __threadfence();
            __syncthreads();
            if (tid == 0) atomicAdd(ctr, 1u);
        }
    }
}

// ============================ causal attention (unchanged) ============================
__global__ void __launch_bounds__(256)
attn_kernel()
{
    __shared__ float sK[32 * 256];
    const int tid = threadIdx.x;
    const int lane = tid & 31, warp = tid >> 5;
    const int qb = blockIdx.x, n = blockIdx.y;
    const int q0 = qb * 16 + warp * 2, q1 = q0 + 1;
    const float* bp = g_out2 + (size_t)n * TT * H2;

    const float4* qp0 = (const float4*)(bp + (size_t)q0 * H2) + lane * 2;
    const float4* qp1 = (const float4*)(bp + (size_t)q1 * H2) + lane * 2;
    float4 q0a = qp0[0], q0b = qp0[1];
    float4 q1a = qp1[0], q1b = qp1[1];

    float m0 = -1e30f, l0 = 0.f, m1 = -1e30f, l1 = 0.f;
    float4 a0a = {0,0,0,0}, a0b = {0,0,0,0}, a1a = {0,0,0,0}, a1b = {0,0,0,0};

    const int ntiles = (qb * 16 + 16 + 31) >> 5;
    const uint32_t kB = s2u(sK);

    for (int tile = 0; tile < ntiles; ++tile) {
        const int s0 = tile * 32;
        __syncthreads();
#pragma unroll
        for (int jj = 0; jj < 8; ++jj) {
            int flat = jj * 256 + tid;
            int key = flat >> 6, off = flat & 63;
            cp16(kB + (uint32_t)flat * 16, bp + (size_t)(s0 + key) * H2 + off * 4);
        }
        cpcommit();
        cpwait<0>();
        __syncthreads();

        int kmax = q1 - s0 + 1;
        if (kmax > 32) kmax = 32;
        for (int kk = 0; kk < kmax; ++kk) {
            const float4* kp = (const float4*)(sK + kk * 256) + lane * 2;
            float4 ka = kp[0], kb4 = kp[1];
            float p0 = q0a.x*ka.x + q0a.y*ka.y + q0a.z*ka.z + q0a.w*ka.w
                     + q0b.x*kb4.x + q0b.y*kb4.y + q0b.z*kb4.z + q0b.w*kb4.w;
            float p1 = q1a.x*ka.x + q1a.y*ka.y + q1a.z*ka.z + q1a.w*ka.w
                     + q1b.x*kb4.x + q1b.y*kb4.y + q1b.z*kb4.z + q1b.w*kb4.w;
            p0 += __shfl_xor_sync(0xffffffffu, p0, 16);
            p1 += __shfl_xor_sync(0xffffffffu, p1, 16);
            p0 += __shfl_xor_sync(0xffffffffu, p0, 8);
            p1 += __shfl_xor_sync(0xffffffffu, p1, 8);
            p0 += __shfl_xor_sync(0xffffffffu, p0, 4);
            p1 += __shfl_xor_sync(0xffffffffu, p1, 4);
            p0 += __shfl_xor_sync(0xffffffffu, p0, 2);
            p1 += __shfl_xor_sync(0xffffffffu, p1, 2);
            p0 += __shfl_xor_sync(0xffffffffu, p0, 1);
            p1 += __shfl_xor_sync(0xffffffffu, p1, 1);
            int keyg = s0 + kk;
            {
                float nm = fmaxf(m1, p1);
                float e  = __expf(p1 - nm);
                float sc = __expf(m1 - nm);
                l1 = l1 * sc + e; m1 = nm;
                a1a.x = a1a.x*sc + e*ka.x;  a1a.y = a1a.y*sc + e*ka.y;
                a1a.z = a1a.z*sc + e*ka.z;  a1a.w = a1a.w*sc + e*ka.w;
                a1b.x = a1b.x*sc + e*kb4.x; a1b.y = a1b.y*sc + e*kb4.y;
                a1b.z = a1b.z*sc + e*kb4.z; a1b.w = a1b.w*sc + e*kb4.w;
            }
            if (keyg <= q0) {
                float nm = fmaxf(m0, p0);
                float e  = __expf(p0 - nm);
                float sc = __expf(m0 - nm);
                l0 = l0 * sc + e; m0 = nm;
                a0a.x = a0a.x*sc + e*ka.x;  a0a.y = a0a.y*sc + e*ka.y;
                a0a.z = a0a.z*sc + e*ka.z;  a0a.w = a0a.w*sc + e*ka.w;
                a0b.x = a0b.x*sc + e*kb4.x; a0b.y = a0b.y*sc + e*kb4.y;
                a0b.z = a0b.z*sc + e*kb4.z; a0b.w = a0b.w*sc + e*kb4.w;
            }
        }
    }

    float i0 = 1.f / l0, i1 = 1.f / l1;
    float4* o0 = (float4*)(g_ctx + ((size_t)n * TT + q0) * H2) + lane * 2;
    float4* o1 = (float4*)(g_ctx + ((size_t)n * TT + q1) * H2) + lane * 2;
    o0[0] = make_float4(a0a.x*i0, a0a.y*i0, a0a.z*i0, a0a.w*i0);
    o0[1] = make_float4(a0b.x*i0, a0b.y*i0, a0b.z*i0, a0b.w*i0);
    o1[0] = make_float4(a1a.x*i1, a1a.y*i1, a1a.z*i1, a1a.w*i1);
    o1[1] = make_float4(a1b.x*i1, a1b.y*i1, a1b.z*i1, a1b.w*i1);
}

// ============================ MLP head (unchanged) ============================
__global__ void __launch_bounds__(128)
mlp_kernel(const float* __restrict__ fc1b,
           const float* __restrict__ fc2b,
           const float* __restrict__ fc3w, const float* __restrict__ fc3b,
           float* __restrict__ dout)
{
    __shared__ float sIn[16][512];
    __shared__ float sH1b[16][128];
    __shared__ float sH2b[16][52];
    const int tid = threadIdx.x;

    for (int tile = blockIdx.x; tile < (NB * TT) / 16; tile += gridDim.x) {
        const int row0 = tile * 16;
        for (int i = tid; i < 16 * 512; i += 128) {
            int r = i >> 9, c = i & 511;
            size_t row = (size_t)(row0 + r);
            sIn[r][c] = (c < 256) ? g_ctx[row * 256 + c] : g_out2[row * 256 + (c - 256)];
        }
        __syncthreads();

        {
            float acc[16];
            float b = fc1b[tid];
#pragma unroll
            for (int r = 0; r < 16; ++r) acc[r] = b;
            for (int k = 0; k < 512; ++k) {
                float w = g_fc1T[k * 128 + tid];
#pragma unroll
                for (int r = 0; r < 16; ++r) acc[r] = fmaf(w, sIn[r][k], acc[r]);
            }
#pragma unroll
            for (int r = 0; r < 16; ++r) sH1b[r][tid] = fmaxf(acc[r], 0.f);
        }
        __syncthreads();

        if (tid < 51) {
            float acc[16];
            float b = fc2b[tid];
#pragma unroll
            for (int r = 0; r < 16; ++r) acc[r] = b;
            for (int k = 0; k < 128; ++k) {
                float w = g_fc2T[k * 51 + tid];
#pragma unroll
                for (int r = 0; r < 16; ++r) acc[r] = fmaf(w, sH1b[r][k], acc[r]);
            }
#pragma unroll
            for (int r = 0; r < 16; ++r) sH2b[r][tid] = fmaxf(acc[r], 0.f);
        }
        __syncthreads();

        if (tid < 16) {
            float s = fc3b[0];
            for (int k = 0; k < 51; ++k) s = fmaf(fc3w[k], sH2b[tid][k], s);
            dout[row0 + tid] = s;
        }
        __syncthreads();
    }
}

// ============================ launch ============================
extern "C" void kernel_launch(void* const* d_in, const int* in_sizes, int n_in,
                              void* d_out, int out_size)
{
    const float* x     = (const float*)d_in[0];
    const float* Wih1  = (const float*)d_in[1];
    const float* Whh1  = (const float*)d_in[2];
    const float* bih1  = (const float*)d_in[3];
    const float* bhh1  = (const float*)d_in[4];
    const float* Wih2  = (const float*)d_in[5];
    const float* Whh2  = (const float*)d_in[6];
    const float* bih2  = (const float*)d_in[7];
    const float* bhh2  = (const float*)d_in[8];
    const float* fc1w  = (const float*)d_in[9];
    const float* fc1b  = (const float*)d_in[10];
    const float* fc2w  = (const float*)d_in[11];
    const float* fc2b  = (const float*)d_in[12];
    const float* fc3w  = (const float*)d_in[13];
    const float* fc3b  = (const float*)d_in[14];
    float* out = (float*)d_out;

    const int SM1 = 54304 * 4;
    const int SM2 = 54480 * 4;
    cudaFuncSetAttribute(lstm1_kernel, cudaFuncAttributeMaxDynamicSharedMemorySize, SM1);
    cudaFuncSetAttribute(lstm2_kernel, cudaFuncAttributeMaxDynamicSharedMemorySize, SM2);

    reset_kernel<<<1, 64>>>();
    prep_kernel<<<(128 * 512 + 255) / 256, 256>>>(fc1w, fc2w);
    prep_w2_kernel<<<2048, 256>>>(Wih2);
    lstm1_kernel<<<128, 512, SM1>>>(x, Wih1, Whh1, bih1, bhh1, out);
    {
        dim3 gg(16, 512);
        gemm_pre2_kernel<<<gg, 256>>>();
    }
    lstm2_kernel<<<128, 512, SM2>>>(Wih2, Whh2, bih2, bhh2, out);
    {
        dim3 grid(64, 64);
        attn_kernel<<<grid, 256>>>();
    }
    mlp_kernel<<<1024, 128>>>(fc1b, fc2b, fc3w, fc3b, out);
}

// round 17
// speedup vs baseline: 1.9964x; 1.0909x over previous
#include <cuda_runtime.h>
#include <cuda_fp16.h>
#include <math.h>
#include <stdint.h>

typedef unsigned long long ull;

#define NB   64
#define TT   1024
#define INW  64
#define H1   512
#define H2   256

__device__ float g_out1[(size_t)NB * TT * H1];
__device__ float g_out2[(size_t)NB * TT * H2];
__device__ float g_ctx [(size_t)NB * TT * H2];
__device__ float g_fc1T[512 * 128];
__device__ float g_fc2T[128 * 51];
__device__ unsigned g_bars[64];
__device__ __align__(16) __half g_w1hi[2048 * 64];
__device__ __align__(16) __half g_w1lo[2048 * 64];
__device__ __align__(16) __half g_w2hi[1024 * 512];
__device__ __align__(16) __half g_w2lo[1024 * 512];
__device__ __align__(16) __half g_h1hi[(size_t)NB * TT * H1];
__device__ __align__(16) __half g_h1lo[(size_t)NB * TT * H1];
__device__ float  g_pre1[(size_t)NB * TT * 2048];
__device__ float  g_pre2[(size_t)NB * TT * 1024];

__global__ void reset_kernel() {
    if (threadIdx.x < 64) g_bars[threadIdx.x] = 0u;
}

__global__ void prep_kernel(const float* __restrict__ fc1w, const float* __restrict__ fc2w) {
    int i = blockIdx.x * blockDim.x + threadIdx.x;
    if (i < 128 * 512) { int j = i / 512, k = i % 512; g_fc1T[k * 128 + j] = fc1w[i]; }
    if (i < 51 * 128)  { int j = i / 128, k = i % 128; g_fc2T[k * 51 + j] = fc2w[i]; }
}

// device globals referenced INSIDE kernels only (host-passing of __device__ symbols is invalid)
__global__ void prep_w1_kernel(const float* __restrict__ W) {
    int i = blockIdx.x * blockDim.x + threadIdx.x;
    if (i < 2048 * 64) {
        float f = W[i];
        __half h = __float2half_rn(f);
        g_w1hi[i] = h;
        g_w1lo[i] = __float2half_rn((f - __half2float(h)) * 2048.0f);
    }
}
__global__ void prep_w2_kernel(const float* __restrict__ W) {
    int i = blockIdx.x * blockDim.x + threadIdx.x;
    if (i < 1024 * 512) {
        float f = W[i];
        __half h = __float2half_rn(f);
        g_w2hi[i] = h;
        g_w2lo[i] = __float2half_rn((f - __half2float(h)) * 2048.0f);
    }
}

// ---------------- helpers ----------------
__device__ __forceinline__ float sigf(float x) { return 1.f / (1.f + __expf(-x)); }
__device__ __forceinline__ float tanhfast(float x) {
    float e = __expf(-2.f * x);
    return (1.f - e) / (1.f + e);
}
__device__ __forceinline__ uint32_t s2u(const void* p) {
    uint32_t a;
    asm("{ .reg .u64 t; cvta.to.shared.u64 t, %1; cvt.u32.u64 %0, t; }" : "=r"(a) : "l"(p));
    return a;
}
__device__ __forceinline__ void cp16(uint32_t dst, const void* src) {
    asm volatile("cp.async.cg.shared.global [%0], [%1], 16;" :: "r"(dst), "l"(src));
}
__device__ __forceinline__ void cpcommit() {
    asm volatile("cp.async.commit_group;" ::: "memory");
}
template <int N>
__device__ __forceinline__ void cpwait() {
    asm volatile("cp.async.wait_group %0;" :: "n"(N) : "memory");
}
__device__ __forceinline__ ull fma2(ull a, ull b, ull c) {
    ull d;
    asm("fma.rn.f32x2 %0, %1, %2, %3;" : "=l"(d) : "l"(a), "l"(b), "l"(c));
    return d;
}
__device__ __forceinline__ ull add2(ull a, ull b) {
    ull d;
    asm("add.rn.f32x2 %0, %1, %2;" : "=l"(d) : "l"(a), "l"(b));
    return d;
}
__device__ __forceinline__ float psum(ull a) {
    return __int_as_float((int)(a & 0xffffffffULL)) + __int_as_float((int)(a >> 32));
}
__device__ __forceinline__ unsigned ldvol(const unsigned* p) {
    unsigned v;
    asm volatile("ld.volatile.global.u32 %0, [%1];" : "=r"(v) : "l"(p));
    return v;
}
__device__ __forceinline__ void ldsm4(uint32_t addr, uint32_t* r) {
    asm volatile("ldmatrix.sync.aligned.m8n8.x4.shared.b16 {%0,%1,%2,%3},[%4];"
        : "=r"(r[0]), "=r"(r[1]), "=r"(r[2]), "=r"(r[3]) : "r"(addr));
}
__device__ __forceinline__ void ldsm2(uint32_t addr, uint32_t* r) {
    asm volatile("ldmatrix.sync.aligned.m8n8.x2.shared.b16 {%0,%1},[%2];"
        : "=r"(r[0]), "=r"(r[1]) : "r"(addr));
}
__device__ __forceinline__ void mma16816(float* c, const uint32_t* a, const uint32_t* b) {
    asm volatile("mma.sync.aligned.m16n8k16.row.col.f32.f16.f16.f32 "
        "{%0,%1,%2,%3},{%4,%5,%6,%7},{%8,%9},{%0,%1,%2,%3};"
        : "+f"(c[0]), "+f"(c[1]), "+f"(c[2]), "+f"(c[3])
        : "r"(a[0]), "r"(a[1]), "r"(a[2]), "r"(a[3]), "r"(b[0]), "r"(b[1]));
}
__device__ __forceinline__ uint32_t h2pk(float a, float b) {
    __half2 h = __floats2half2_rn(a, b);
    return *(uint32_t*)&h;
}

// ---------------- fp32 tile compute (lstm2 recurrent part; verified R13) ----------------
__device__ __forceinline__ void fma16(const ulonglong2* W, const ulonglong2* A, ull* acc) {
    acc[0]  = fma2(W[0].x, A[0].x, acc[0]);  acc[0]  = fma2(W[0].y, A[0].y, acc[0]);
    acc[1]  = fma2(W[0].x, A[1].x, acc[1]);  acc[1]  = fma2(W[0].y, A[1].y, acc[1]);
    acc[2]  = fma2(W[0].x, A[2].x, acc[2]);  acc[2]  = fma2(W[0].y, A[2].y, acc[2]);
    acc[3]  = fma2(W[0].x, A[3].x, acc[3]);  acc[3]  = fma2(W[0].y, A[3].y, acc[3]);
    acc[4]  = fma2(W[1].x, A[0].x, acc[4]);  acc[4]  = fma2(W[1].y, A[0].y, acc[4]);
    acc[5]  = fma2(W[1].x, A[1].x, acc[5]);  acc[5]  = fma2(W[1].y, A[1].y, acc[5]);
    acc[6]  = fma2(W[1].x, A[2].x, acc[6]);  acc[6]  = fma2(W[1].y, A[2].y, acc[6]);
    acc[7]  = fma2(W[1].x, A[3].x, acc[7]);  acc[7]  = fma2(W[1].y, A[3].y, acc[7]);
    acc[8]  = fma2(W[2].x, A[0].x, acc[8]);  acc[8]  = fma2(W[2].y, A[0].y, acc[8]);
    acc[9]  = fma2(W[2].x, A[1].x, acc[9]);  acc[9]  = fma2(W[2].y, A[1].y, acc[9]);
    acc[10] = fma2(W[2].x, A[2].x, acc[10]); acc[10] = fma2(W[2].y, A[2].y, acc[10]);
    acc[11] = fma2(W[2].x, A[3].x, acc[11]); acc[11] = fma2(W[2].y, A[3].y, acc[11]);
    acc[12] = fma2(W[3].x, A[0].x, acc[12]); acc[12] = fma2(W[3].y, A[0].y, acc[12]);
    acc[13] = fma2(W[3].x, A[1].x, acc[13]); acc[13] = fma2(W[3].y, A[1].y, acc[13]);
    acc[14] = fma2(W[3].x, A[2].x, acc[14]); acc[14] = fma2(W[3].y, A[2].y, acc[14]);
    acc[15] = fma2(W[3].x, A[3].x, acc[15]); acc[15] = fma2(W[3].y, A[3].y, acc[15]);
}
__device__ __forceinline__ void ld8_2(const float* sWb, const float* sAb, int off,
                                      ulonglong2* W, ulonglong2* A) {
    W[0] = *(const ulonglong2*)(sWb + off);
    W[1] = *(const ulonglong2*)(sWb + 4 * 772 + off);
    W[2] = *(const ulonglong2*)(sWb + 8 * 772 + off);
    W[3] = *(const ulonglong2*)(sWb + 12 * 772 + off);
    A[0] = *(const ulonglong2*)(sAb + off);
    A[1] = *(const ulonglong2*)(sAb + 8 * 772 + off);
    A[2] = *(const ulonglong2*)(sAb + 16 * 772 + off);
    A[3] = *(const ulonglong2*)(sAb + 24 * 772 + off);
}
template<int NU>
__device__ __forceinline__ void pipe2(const float* sWb, const float* sAb,
                                      const int* offs, ull* acc) {
    ulonglong2 W[2][4], A[2][4];
    ld8_2(sWb, sAb, offs[0], W[0], A[0]);
#pragma unroll
    for (int i = 0; i < NU; ++i) {
        if (i + 1 < NU) ld8_2(sWb, sAb, offs[i + 1], W[(i + 1) & 1], A[(i + 1) & 1]);
        fma16(W[i & 1], A[i & 1], acc);
    }
}

// ============================ split-fp16 GEMM body (verified R13 code) ============================
__device__ __forceinline__ void gemm_body(const float* __restrict__ A, int ldA,
                                          const __half* __restrict__ Bh,
                                          const __half* __restrict__ Bl, int ldB,
                                          float* __restrict__ C, int ldC, int K)
{
    __shared__ __align__(16) __half sAh[128 * 40];
    __shared__ __align__(16) __half sAl[128 * 40];
    __shared__ __align__(16) __half sBh[64 * 40];
    __shared__ __align__(16) __half sBl[64 * 40];
    const int tid = threadIdx.x, lane = tid & 31, warp = tid >> 5;
    const int wm = warp >> 1, wn = warp & 1;
    const int n0 = blockIdx.x * 64, m0 = blockIdx.y * 128;
    const uint32_t ah = s2u(sAh), al = s2u(sAl), bh = s2u(sBh), bl = s2u(sBl);

    float Ch[8][4], Cx[8][4];
#pragma unroll
    for (int i = 0; i < 8; ++i)
#pragma unroll
        for (int j = 0; j < 4; ++j) { Ch[i][j] = 0.f; Cx[i][j] = 0.f; }

    const int arow = tid >> 1, ahf = tid & 1;
    const int brow = tid >> 2, bseg = tid & 3;
    const int nkc = K / 32;

    for (int kc = 0; kc < nkc; ++kc) {
        cp16(bh + (uint32_t)((brow * 40 + bseg * 8) * 2),
             Bh + (size_t)(n0 + brow) * ldB + kc * 32 + bseg * 8);
        cp16(bl + (uint32_t)((brow * 40 + bseg * 8) * 2),
             Bl + (size_t)(n0 + brow) * ldB + kc * 32 + bseg * 8);
        cpcommit();
        {
            const float* src = A + (size_t)(m0 + arow) * ldA + kc * 32 + ahf * 16;
            uint4* dh = (uint4*)(sAh + arow * 40 + ahf * 16);
            uint4* dl = (uint4*)(sAl + arow * 40 + ahf * 16);
#pragma unroll
            for (int q = 0; q < 2; ++q) {
                float4 x0 = *(const float4*)(src + q * 8);
                float4 x1 = *(const float4*)(src + q * 8 + 4);
                float f[8] = {x0.x, x0.y, x0.z, x0.w, x1.x, x1.y, x1.z, x1.w};
                uint32_t h[4], l[4];
#pragma unroll
                for (int i = 0; i < 4; ++i) {
                    float a = f[2 * i], b = f[2 * i + 1];
                    __half2 hh = __floats2half2_rn(a, b);
                    float2 fb = __half22float2(hh);
                    h[i] = *(uint32_t*)&hh;
                    l[i] = h2pk((a - fb.x) * 2048.f, (b - fb.y) * 2048.f);
                }
                dh[q] = make_uint4(h[0], h[1], h[2], h[3]);
                dl[q] = make_uint4(l[0], l[1], l[2], l[3]);
            }
        }
        cpwait<0>();
        __syncthreads();

#pragma unroll
        for (int kt = 0; kt < 2; ++kt) {
            uint32_t Af[2][4], Al2[2][4], Bf[4][2], Bl2[4][2];
            int arw = lane & 15, akh = lane >> 4;
#pragma unroll
            for (int mi = 0; mi < 2; ++mi) {
                uint32_t off = (uint32_t)(((wm * 32 + mi * 16 + arw) * 40 + kt * 16 + akh * 8) * 2);
                ldsm4(ah + off, Af[mi]);
                ldsm4(al + off, Al2[mi]);
            }
            int brw = lane & 7, bkh = (lane >> 3) & 1;
#pragma unroll
            for (int ni = 0; ni < 4; ++ni) {
                uint32_t off = (uint32_t)(((wn * 32 + ni * 8 + brw) * 40 + kt * 16 + bkh * 8) * 2);
                ldsm2(bh + off, Bf[ni]);
                ldsm2(bl + off, Bl2[ni]);
            }
#pragma unroll
            for (int mi = 0; mi < 2; ++mi)
#pragma unroll
                for (int ni = 0; ni < 4; ++ni) {
                    mma16816(Ch[mi * 4 + ni], Af[mi], Bf[ni]);
                    mma16816(Cx[mi * 4 + ni], Af[mi], Bl2[ni]);
                    mma16816(Cx[mi * 4 + ni], Al2[mi], Bf[ni]);
                }
        }
        __syncthreads();
    }

    const float s = 1.f / 2048.f;
#pragma unroll
    for (int mi = 0; mi < 2; ++mi)
#pragma unroll
        for (int ni = 0; ni < 4; ++ni) {
            float* c = Ch[mi * 4 + ni];
            float* x = Cx[mi * 4 + ni];
            int row = m0 + wm * 32 + mi * 16 + (lane >> 2);
            int col = n0 + wn * 32 + ni * 8 + (lane & 3) * 2;
            *(float2*)(C + (size_t)row * ldC + col) =
                make_float2(c[0] + x[0] * s, c[1] + x[1] * s);
            *(float2*)(C + (size_t)(row + 8) * ldC + col) =
                make_float2(c[2] + x[2] * s, c[3] + x[3] * s);
        }
}

// wrappers: bind device globals in DEVICE code
__global__ void __launch_bounds__(256) gemm_pre1_kernel(const float* __restrict__ x) {
    gemm_body(x, 64, g_w1hi, g_w1lo, 64, g_pre1, 2048, 64);
}
__global__ void __launch_bounds__(256) gemm_pre2_kernel() {
    gemm_body(g_out1, 512, g_w2hi, g_w2lo, 512, g_pre2, 1024, 512);
}

// ============================ LSTM layer 1 (recurrence via in-loop MMA) ============================
// 128 CTAs x 512 thr. hg=bx>>1 (8 hidden cols = 32 gate rows), rowgrp=bx&1 (32 batch rows).
// gates = pre1(LDG) + Whh1·h[t-1] (split-fp16 MMA) + bias.
// 16 warps: mi=w&1 (M16), ni=(w>>1)&3 (N8), kh=w>>3 (K-half of 512).
__global__ void __launch_bounds__(512, 1)
lstm1_kernel(const float* __restrict__ Whh,
             const float* __restrict__ bih, const float* __restrict__ bhh,
             float* __restrict__ dout)
{
    extern __shared__ char smem[];
    __half* sWh = (__half*)smem;                   // 32 x 520
    __half* sWl = (__half*)(smem + 33280);
    __half* sHh = (__half*)(smem + 66560);         // 32 x 520
    __half* sHl = (__half*)(smem + 99840);
    float*  sPf = (float*)(smem + 133120);         // 2 x 32 x 34
    float*  sBias = (float*)(smem + 141824);       // 32
    float*  sC  = (float*)(smem + 141952);         // 256

    const int tid = threadIdx.x, bx = blockIdx.x;
    const int hg = bx >> 1, rowgrp = bx & 1, rows0 = rowgrp * 32;

    for (int i = tid; i < 32 * 512; i += 512) {
        int lr = i >> 9, k = i & 511;
        int grow = (lr >> 3) * H1 + hg * 8 + (lr & 7);
        float f = Whh[(size_t)grow * H1 + k];
        __half h = __float2half_rn(f);
        sWh[lr * 520 + k] = h;
        sWl[lr * 520 + k] = __float2half_rn((f - __half2float(h)) * 2048.f);
    }
    if (tid < 32) {
        int grow = (tid >> 3) * H1 + hg * 8 + (tid & 7);
        sBias[tid] = bih[grow] + bhh[grow];
    }
    if (tid < 256) sC[tid] = 0.f;
    __syncthreads();

    const int w = tid >> 5, lane = tid & 31;
    const int mi = w & 1, ni = (w >> 1) & 3, kh = w >> 3;
    const int arw = lane & 15, akh = lane >> 4;
    const int brw = lane & 7, bkh = (lane >> 3) & 1;
    const uint32_t whB = s2u(sWh), wlB = s2u(sWl);
    const uint32_t hhB = s2u(sHh), hlB = s2u(sHl);
    unsigned* ctr = &g_bars[rowgrp * 16];

    for (int t = 0; t < TT; ++t) {
        // pre1 slice via plain LDG (independent of barrier; latency hidden by spin/stage/MMA)
        float pre[4] = {0.f, 0.f, 0.f, 0.f};
        if (tid < 256) {
            int n = tid >> 3, hc = tid & 7;
            const float* pp = g_pre1 + ((size_t)(rows0 + n) * TT + t) * 2048 + hg * 8 + hc;
            pre[0] = pp[0];
            pre[1] = pp[512];
            pre[2] = pp[1024];
            pre[3] = pp[1536];
        }

        if (t > 0) {
            if (tid == 0) {
                unsigned tgt = 64u * (unsigned)t;
                while (ldvol(ctr) < tgt) { __nanosleep(32); }
            }
            __syncthreads();
#pragma unroll
            for (int j = 0; j < 4; ++j) {
                int f = j * 512 + tid;
                int row = f >> 6, seg = f & 63;
                size_t src = ((size_t)(rows0 + row) * TT + (t - 1)) * 512 + seg * 8;
                uint32_t dst = (uint32_t)((row * 520 + seg * 8) * 2);
                cp16(hhB + dst, g_h1hi + src);
                cp16(hlB + dst, g_h1lo + src);
            }
            cpcommit();
        }
        cpwait<0>(); __syncthreads();

        float Ch[4] = {0.f, 0.f, 0.f, 0.f}, Cx[4] = {0.f, 0.f, 0.f, 0.f};
        if (t > 0) {
#pragma unroll
            for (int j = 0; j < 16; ++j) {
                int ks = kh * 16 + j;
                uint32_t offA = (uint32_t)(((mi * 16 + arw) * 520 + ks * 16 + akh * 8) * 2);
                uint32_t offB = (uint32_t)(((ni * 8 + brw) * 520 + ks * 16 + bkh * 8) * 2);
                uint32_t Af[4], Al2[4], Bf[2], Bl2[2];
                ldsm4(hhB + offA, Af);
                ldsm4(hlB + offA, Al2);
                ldsm2(whB + offB, Bf);
                ldsm2(wlB + offB, Bl2);
                mma16816(Ch, Af, Bf);
                mma16816(Cx, Af, Bl2);
                mma16816(Cx, Al2, Bf);
            }
        }
        {
            const float s = 1.f / 2048.f;
            int r = mi * 16 + (lane >> 2);
            int c = ni * 8 + (lane & 3) * 2;
            float* base = sPf + kh * (32 * 34);
            *(float2*)(base + r * 34 + c)       = make_float2(Ch[0] + Cx[0] * s, Ch[1] + Cx[1] * s);
            *(float2*)(base + (r + 8) * 34 + c) = make_float2(Ch[2] + Cx[2] * s, Ch[3] + Cx[3] * s);
        }
        __syncthreads();

        if (tid < 256) {
            int n = tid >> 3, hc = tid & 7;
            float gate[4];
#pragma unroll
            for (int g = 0; g < 4; ++g) {
                int c = g * 8 + hc;
                gate[g] = sPf[n * 34 + c] + sPf[32 * 34 + n * 34 + c] + pre[g] + sBias[c];
            }
            float cp = sC[tid];
            float cn = sigf(gate[1]) * cp + sigf(gate[0]) * tanhfast(gate[2]);
            sC[tid] = cn;
            float h = sigf(gate[3]) * tanhfast(cn);
            int ng = rows0 + n, hcg = hg * 8 + hc;
            size_t idx = ((size_t)ng * TT + t) * H1 + hcg;
            g_out1[idx] = h;
            __half hh = __float2half_rn(h);
            g_h1hi[idx] = hh;
            g_h1lo[idx] = __float2half_rn((h - __half2float(hh)) * 2048.f);
            if (t == TT - 1) {
                dout[65536 + ng * H1 + hcg] = h;
                dout[98304 + ng * H1 + hcg] = cn;
            }
        }

        if (t < TT - 1) {
            __threadfence();
            __syncthreads();
            if (tid == 0) atomicAdd(ctr, 1u);
        }
    }
}

// ============================ LSTM layer 2 (R13-verified, unchanged) ============================
__global__ void __launch_bounds__(512, 1)
lstm2_kernel(const float* __restrict__ Wih, const float* __restrict__ Whh,
             const float* __restrict__ bih, const float* __restrict__ bhh,
             float* __restrict__ dout)
{
    extern __shared__ float sm[];
    float* sW    = sm;
    float* sA    = sm + 12352;
    ull*   sP    = (ull*)(sm + 37056);
    float* sBias = sm + 53696;
    float* sC    = sm + 53712;
    float* sPre  = sm + 53840;

    const int tid = threadIdx.x;
    const int bx  = blockIdx.x;
    const int hg = bx >> 1, rowgrp = bx & 1, rows0 = rowgrp * 32;

    for (int i = tid; i < 16 * 768; i += 512) {
        int lr = i / 768, k = i - lr * 768;
        int g = lr >> 2, hc = lr & 3;
        int grow = g * H2 + hg * 4 + hc;
        sW[lr * 772 + k] = (k < H1) ? Wih[grow * H1 + k] : Whh[grow * H2 + (k - H1)];
    }
    if (tid < 16) {
        int g = tid >> 2, hc = tid & 3;
        int grow = g * H2 + hg * 4 + hc;
        sBias[tid] = bih[grow] + bhh[grow];
    }
    if (tid < 128) sC[tid] = 0.f;
    __syncthreads();

    const int hcl = tid & 3;
    const int rq  = (tid >> 2) & 7;
    const int ks  = tid >> 5;
    const int lr_ = tid >> 4;
    const int lc  = tid & 15;
    const int lp  = (lr_ >> 2) + (lr_ & 3) * 8;
    const uint32_t aB = s2u(sA);
    const uint32_t pB = s2u(sPre);
    unsigned* ctr = &g_bars[32 + rowgrp * 16];

    const float* sWb = sW + hcl * 772 + ks * 8;
    const float* sAb = sA + rq * 772 + ks * 8;
    const int offsC[4] = {512, 516, 640, 644};

    for (int t = 0; t < TT; ++t) {
        if (tid < 128) {
            int n = tid >> 2, g = tid & 3;
            size_t r = (size_t)(rows0 + n) * TT + t;
            cp16(pB + (uint32_t)((n * 20 + g * 4) * 4),
                 g_pre2 + r * 1024 + g * 256 + hg * 4);
        }
        cpcommit();

        ull acc[16];
#pragma unroll
        for (int i = 0; i < 16; ++i) acc[i] = 0;

        if (t > 0) {
            if (tid == 0) {
                unsigned tgt = 64u * (unsigned)t;
                while (ldvol(ctr) < tgt) { __nanosleep(32); }
            }
            __syncthreads();
#pragma unroll
            for (int j = 8; j < 12; ++j) {
                int k4 = lc + 16 * j;
                cp16(aB + (uint32_t)((lp * 772 + k4 * 4) * 4),
                     g_out2 + ((size_t)(rows0 + lr_) * TT + (t - 1)) * H2 + (k4 * 4 - 512));
            }
            cpcommit();
            cpwait<0>(); __syncthreads();
            pipe2<4>(sWb, sAb, offsC, acc);
        } else {
            cpwait<0>(); __syncthreads();
        }

#pragma unroll
        for (int g = 0; g < 4; ++g) {
#pragma unroll
            for (int r = 0; r < 4; ++r) {
                int cell = (rq * 4 + r) * 4 + hcl;
                int col = g * 16 + ((ks + rq) & 15);
                sP[cell * 65 + col] = acc[g * 4 + r];
            }
        }
        __syncthreads();

        if (tid < 128) {
            int n = tid >> 2, hc = tid & 3;
            const ull* pp = sP + tid * 65;
            const float* pr = sPre + n * 20 + hc;
            float gate[4];
#pragma unroll
            for (int g = 0; g < 4; ++g) {
                ull s = pp[g * 16];
#pragma unroll
                for (int j = 1; j < 16; ++j) s = add2(s, pp[g * 16 + j]);
                gate[g] = psum(s) + sBias[g * 4 + hc] + pr[g * 4];
            }
            float cp = sC[tid];
            float cn = sigf(gate[1]) * cp + sigf(gate[0]) * tanhfast(gate[2]);
            sC[tid] = cn;
            float h = sigf(gate[3]) * tanhfast(cn);
            int ng = rows0 + n;
            int hcg = hg * 4 + hc;
            g_out2[((size_t)ng * TT + t) * H2 + hcg] = h;
            if (t == TT - 1) {
                dout[131072 + ng * H2 + hcg] = h;
                dout[147456 + ng * H2 + hcg] = cn;
            }
        }

        if (t < TT - 1) {
            __threadfence();
            __syncthreads();
            if (tid == 0) atomicAdd(ctr, 1u);
        }
    }
}

// ============================ causal attention (verified) ============================
__global__ void __launch_bounds__(256)
attn_kernel()
{
    __shared__ float sK[32 * 256];
    const int tid = threadIdx.x;
    const int lane = tid & 31, warp = tid >> 5;
    const int qb = blockIdx.x, n = blockIdx.y;
    const int q0 = qb * 16 + warp * 2, q1 = q0 + 1;
    const float* bp = g_out2 + (size_t)n * TT * H2;

    const float4* qp0 = (const float4*)(bp + (size_t)q0 * H2) + lane * 2;
    const float4* qp1 = (const float4*)(bp + (size_t)q1 * H2) + lane * 2;
    float4 q0a = qp0[0], q0b = qp0[1];
    float4 q1a = qp1[0], q1b = qp1[1];

    float m0 = -1e30f, l0 = 0.f, m1 = -1e30f, l1 = 0.f;
    float4 a0a = {0,0,0,0}, a0b = {0,0,0,0}, a1a = {0,0,0,0}, a1b = {0,0,0,0};

    const int ntiles = (qb * 16 + 16 + 31) >> 5;
    const uint32_t kB = s2u(sK);

    for (int tile = 0; tile < ntiles; ++tile) {
        const int s0 = tile * 32;
        __syncthreads();
#pragma unroll
        for (int jj = 0; jj < 8; ++jj) {
            int flat = jj * 256 + tid;
            int key = flat >> 6, off = flat & 63;
            cp16(kB + (uint32_t)flat * 16, bp + (size_t)(s0 + key) * H2 + off * 4);
        }
        cpcommit();
        cpwait<0>();
        __syncthreads();

        int kmax = q1 - s0 + 1;
        if (kmax > 32) kmax = 32;
        for (int kk = 0; kk < kmax; ++kk) {
            const float4* kp = (const float4*)(sK + kk * 256) + lane * 2;
            float4 ka = kp[0], kb4 = kp[1];
            float p0 = q0a.x*ka.x + q0a.y*ka.y + q0a.z*ka.z + q0a.w*ka.w
                     + q0b.x*kb4.x + q0b.y*kb4.y + q0b.z*kb4.z + q0b.w*kb4.w;
            float p1 = q1a.x*ka.x + q1a.y*ka.y + q1a.z*ka.z + q1a.w*ka.w
                     + q1b.x*kb4.x + q1b.y*kb4.y + q1b.z*kb4.z + q1b.w*kb4.w;
            p0 += __shfl_xor_sync(0xffffffffu, p0, 16);
            p1 += __shfl_xor_sync(0xffffffffu, p1, 16);
            p0 += __shfl_xor_sync(0xffffffffu, p0, 8);
            p1 += __shfl_xor_sync(0xffffffffu, p1, 8);
            p0 += __shfl_xor_sync(0xffffffffu, p0, 4);
            p1 += __shfl_xor_sync(0xffffffffu, p1, 4);
            p0 += __shfl_xor_sync(0xffffffffu, p0, 2);
            p1 += __shfl_xor_sync(0xffffffffu, p1, 2);
            p0 += __shfl_xor_sync(0xffffffffu, p0, 1);
            p1 += __shfl_xor_sync(0xffffffffu, p1, 1);
            int keyg = s0 + kk;
            {
                float nm = fmaxf(m1, p1);
                float e  = __expf(p1 - nm);
                float sc = __expf(m1 - nm);
                l1 = l1 * sc + e; m1 = nm;
                a1a.x = a1a.x*sc + e*ka.x;  a1a.y = a1a.y*sc + e*ka.y;
                a1a.z = a1a.z*sc + e*ka.z;  a1a.w = a1a.w*sc + e*ka.w;
                a1b.x = a1b.x*sc + e*kb4.x; a1b.y = a1b.y*sc + e*kb4.y;
                a1b.z = a1b.z*sc + e*kb4.z; a1b.w = a1b.w*sc + e*kb4.w;
            }
            if (keyg <= q0) {
                float nm = fmaxf(m0, p0);
                float e  = __expf(p0 - nm);
                float sc = __expf(m0 - nm);
                l0 = l0 * sc + e; m0 = nm;
                a0a.x = a0a.x*sc + e*ka.x;  a0a.y = a0a.y*sc + e*ka.y;
                a0a.z = a0a.z*sc + e*ka.z;  a0a.w = a0a.w*sc + e*ka.w;
                a0b.x = a0b.x*sc + e*kb4.x; a0b.y = a0b.y*sc + e*kb4.y;
                a0b.z = a0b.z*sc + e*kb4.z; a0b.w = a0b.w*sc + e*kb4.w;
            }
        }
    }

    float i0 = 1.f / l0, i1 = 1.f / l1;
    float4* o0 = (float4*)(g_ctx + ((size_t)n * TT + q0) * H2) + lane * 2;
    float4* o1 = (float4*)(g_ctx + ((size_t)n * TT + q1) * H2) + lane * 2;
    o0[0] = make_float4(a0a.x*i0, a0a.y*i0, a0a.z*i0, a0a.w*i0);
    o0[1] = make_float4(a0b.x*i0, a0b.y*i0, a0b.z*i0, a0b.w*i0);
    o1[0] = make_float4(a1a.x*i1, a1a.y*i1, a1a.z*i1, a1a.w*i1);
    o1[1] = make_float4(a1b.x*i1, a1b.y*i1, a1b.z*i1, a1b.w*i1);
}

// ============================ MLP head (verified) ============================
__global__ void __launch_bounds__(128)
mlp_kernel(const float* __restrict__ fc1b,
           const float* __restrict__ fc2b,
           const float* __restrict__ fc3w, const float* __restrict__ fc3b,
           float* __restrict__ dout)
{
    __shared__ float sIn[16][512];
    __shared__ float sH1b[16][128];
    __shared__ float sH2b[16][52];
    const int tid = threadIdx.x;

    for (int tile = blockIdx.x; tile < (NB * TT) / 16; tile += gridDim.x) {
        const int row0 = tile * 16;
        for (int i = tid; i < 16 * 512; i += 128) {
            int r = i >> 9, c = i & 511;
            size_t row = (size_t)(row0 + r);
            sIn[r][c] = (c < 256) ? g_ctx[row * 256 + c] : g_out2[row * 256 + (c - 256)];
        }
        __syncthreads();

        {
            float acc[16];
            float b = fc1b[tid];
#pragma unroll
            for (int r = 0; r < 16; ++r) acc[r] = b;
            for (int k = 0; k < 512; ++k) {
                float w = g_fc1T[k * 128 + tid];
#pragma unroll
                for (int r = 0; r < 16; ++r) acc[r] = fmaf(w, sIn[r][k], acc[r]);
            }
#pragma unroll
            for (int r = 0; r < 16; ++r) sH1b[r][tid] = fmaxf(acc[r], 0.f);
        }
        __syncthreads();

        if (tid < 51) {
            float acc[16];
            float b = fc2b[tid];
#pragma unroll
            for (int r = 0; r < 16; ++r) acc[r] = b;
            for (int k = 0; k < 128; ++k) {
                float w = g_fc2T[k * 51 + tid];
#pragma unroll
                for (int r = 0; r < 16; ++r) acc[r] = fmaf(w, sH1b[r][k], acc[r]);
            }
#pragma unroll
            for (int r = 0; r < 16; ++r) sH2b[r][tid] = fmaxf(acc[r], 0.f);
        }
        __syncthreads();

        if (tid < 16) {
            float s = fc3b[0];
            for (int k = 0; k < 51; ++k) s = fmaf(fc3w[k], sH2b[tid][k], s);
            dout[row0 + tid] = s;
        }
        __syncthreads();
    }
}

// ============================ launch ============================
extern "C" void kernel_launch(void* const* d_in, const int* in_sizes, int n_in,
                              void* d_out, int out_size)
{
    const float* x     = (const float*)d_in[0];
    const float* Wih1  = (const float*)d_in[1];
    const float* Whh1  = (const float*)d_in[2];
    const float* bih1  = (const float*)d_in[3];
    const float* bhh1  = (const float*)d_in[4];
    const float* Wih2  = (const float*)d_in[5];
    const float* Whh2  = (const float*)d_in[6];
    const float* bih2  = (const float*)d_in[7];
    const float* bhh2  = (const float*)d_in[8];
    const float* fc1w  = (const float*)d_in[9];
    const float* fc1b  = (const float*)d_in[10];
    const float* fc2w  = (const float*)d_in[11];
    const float* fc2b  = (const float*)d_in[12];
    const float* fc3w  = (const float*)d_in[13];
    const float* fc3b  = (const float*)d_in[14];
    float* out = (float*)d_out;

    const int SM1 = 142976;
    const int SM2 = 54480 * 4;
    cudaFuncSetAttribute(lstm1_kernel, cudaFuncAttributeMaxDynamicSharedMemorySize, SM1);
    cudaFuncSetAttribute(lstm2_kernel, cudaFuncAttributeMaxDynamicSharedMemorySize, SM2);

    reset_kernel<<<1, 64>>>();
    prep_kernel<<<256, 256>>>(fc1w, fc2w);
    prep_w1_kernel<<<512, 256>>>(Wih1);
    prep_w2_kernel<<<2048, 256>>>(Wih2);
    {
        dim3 gg(32, 512);
        gemm_pre1_kernel<<<gg, 256>>>(x);
    }
    lstm1_kernel<<<128, 512, SM1>>>(Whh1, bih1, bhh1, out);
    {
        dim3 gg(16, 512);
        gemm_pre2_kernel<<<gg, 256>>>();
    }
    lstm2_kernel<<<128, 512, SM2>>>(Wih2, Whh2, bih2, bhh2, out);
    {
        dim3 grid(64, 64);
        attn_kernel<<<grid, 256>>>();
    }
    mlp_kernel<<<1024, 128>>>(fc1b, fc2b, fc3w, fc3b, out);
}